// round 5
// baseline (speedup 1.0000x reference)
#include <cuda_runtime.h>

#define NN   100000
#define DIM1 128
#define H1   4
#define F2   40

// ---------------- scratch (device globals: allocation-free) ----------------
__device__ float g_xw1[(size_t)NN * DIM1];   // layer1 x@W1           [N,128]
__device__ float g_h  [(size_t)NN * DIM1];   // layer1 numerator acc  [N,128]
__device__ float g_asrc1[NN * H1];
__device__ float g_adst1[NN * H1];
__device__ float g_den1 [NN * H1];
__device__ float g_xw2[(size_t)NN * F2];     // layer2 h@W2           [N,40]
__device__ float g_asrc2[NN];
__device__ float g_adst2[NN];
__device__ float g_den2 [NN];
__device__ float g_W1t[128 * 128];           // W1 transposed [c][k]
__device__ float g_W2t[40 * 128];            // W2 transposed [c][k]

__device__ __forceinline__ float leaky(float v) { return v > 0.f ? v : 0.2f * v; }

__device__ __forceinline__ void red_add_v4(float* addr, float4 v) {
    asm volatile("red.global.add.v4.f32 [%0], {%1, %2, %3, %4};"
                 :: "l"(addr), "f"(v.x), "f"(v.y), "f"(v.z), "f"(v.w) : "memory");
}
__device__ __forceinline__ void red_add_f32(float* addr, float v) {
    asm volatile("red.global.add.f32 [%0], %1;" :: "l"(addr), "f"(v) : "memory");
}
// Packed fp32x2 FMA (Blackwell FFMA2): d = a*b + d
__device__ __forceinline__ void fma2(unsigned long long& d,
                                     unsigned long long a, unsigned long long b) {
    asm("fma.rn.f32x2 %0, %1, %2, %0;" : "+l"(d) : "l"(a), "l"(b));
}
__device__ __forceinline__ void unpack2(unsigned long long d, float& lo, float& hi) {
    asm("mov.b64 {%0, %1}, %2;" : "=f"(lo), "=f"(hi) : "l"(d));
}

// ---------------- prep: zero accumulators + transpose weights ---------------
__global__ void prep_kernel(const float* __restrict__ W1, const float* __restrict__ W2,
                            float* __restrict__ out, int N) {
    size_t nh = (size_t)N * DIM1, nd1 = (size_t)N * H1, no = (size_t)N * F2;
    size_t tW = 128 * 128 + 40 * 128;              // 21504 transpose elems
    size_t total = tW + nh + nd1 + no + N;
    for (size_t i = (size_t)blockIdx.x * blockDim.x + threadIdx.x; i < total;
         i += (size_t)gridDim.x * blockDim.x) {
        if (i < 16384) {
            int k = (int)i >> 7, c = (int)i & 127;
            g_W1t[c * 128 + k] = W1[i];
        } else if (i < tW) {
            int t = (int)(i - 16384);
            int k = t / 40, c = t - k * 40;
            g_W2t[c * 128 + k] = W2[t];
        } else {
            size_t j = i - tW;
            if (j < nh) g_h[j] = 0.f;
            else if (j < nh + nd1) g_den1[j - nh] = 0.f;
            else if (j < nh + nd1 + no) out[j - nh - nd1] = 0.f;
            else g_den2[j - nh - nd1 - no] = 0.f;
        }
    }
}

// ---------------- GEMM1 + fused attention dots ------------------------------
// block = 256 thr = 8 warps. warp -> (row group = warp>>1 : 8 rows) x
// (col half = warp&1 : 64 cols as 2 sub-groups of 32). k-pair f32x2 dot trick.
__global__ __launch_bounds__(256) void gemm1_kernel(
    const float* __restrict__ x,
    const float* __restrict__ att_s, const float* __restrict__ att_d, int N) {
    __shared__ float sWt[128][68];   // transposed W tile [c][k], pad 68 (34KB)
    __shared__ float sx[32][64];     // x tile (8KB)
    int rowBase = blockIdx.x * 32;
    int tid = threadIdx.x, warp = tid >> 5, lane = tid & 31;
    int j2 = warp & 1;        // column half (0: cols 0..63, 1: 64..127)
    int rg = warp >> 1;       // row group: rows rg*8 .. rg*8+7

    unsigned long long acc[8][2];
#pragma unroll
    for (int r = 0; r < 8; ++r) { acc[r][0] = 0ull; acc[r][1] = 0ull; }

    for (int kt = 0; kt < 2; ++kt) {
        __syncthreads();
        // sWt[c][k] = W1t[c][kt*64+k]  (128 x 64 floats = 2048 float4)
        for (int i = tid; i < 2048; i += 256) {
            int c = i >> 4, k4 = i & 15;
            ((float4*)&sWt[c][0])[k4] =
                ((const float4*)(g_W1t + c * 128 + kt * 64))[k4];
        }
        // sx: 32 x 64 floats = 512 float4
        for (int i = tid; i < 512; i += 256) {
            int r = i >> 4, c4 = i & 15;
            int row = rowBase + r;
            ((float4*)&sx[r][0])[c4] = (row < N)
                ? ((const float4*)(x + (size_t)row * 128 + kt * 64))[c4]
                : make_float4(0.f, 0.f, 0.f, 0.f);
        }
        __syncthreads();
#pragma unroll 4
        for (int k4 = 0; k4 < 16; ++k4) {
            double2 xp[8];
#pragma unroll
            for (int r = 0; r < 8; ++r)
                xp[r] = ((const double2*)&sx[rg * 8 + r][0])[k4];
#pragma unroll
            for (int jj = 0; jj < 2; ++jj) {
                int c = j2 * 64 + jj * 32 + lane;
                double2 w = ((const double2*)&sWt[c][0])[k4];
                unsigned long long w0 = __double_as_longlong(w.x);
                unsigned long long w1 = __double_as_longlong(w.y);
#pragma unroll
                for (int r = 0; r < 8; ++r) {
                    fma2(acc[r][jj], __double_as_longlong(xp[r].x), w0);
                    fma2(acc[r][jj], __double_as_longlong(xp[r].y), w1);
                }
            }
        }
    }
    // epilogue: horizontal add, store, per-head attention dots
#pragma unroll
    for (int jj = 0; jj < 2; ++jj) {
        int c = j2 * 64 + jj * 32 + lane;
        int head = c >> 5;                         // = j2*2 + jj
        float as = att_s[c], ad = att_d[c];
#pragma unroll
        for (int r = 0; r < 8; ++r) {
            float lo, hi;
            unpack2(acc[r][jj], lo, hi);
            float v = lo + hi;
            float ps = v * as, pd = v * ad;
#pragma unroll
            for (int o = 16; o; o >>= 1) {
                ps += __shfl_xor_sync(0xffffffffu, ps, o);
                pd += __shfl_xor_sync(0xffffffffu, pd, o);
            }
            int row = rowBase + rg * 8 + r;
            if (row < N) {
                g_xw1[(size_t)row * 128 + c] = v;
                if (lane == 0) {
                    g_asrc1[row * 4 + head] = ps;
                    g_adst1[row * 4 + head] = pd;
                }
            }
        }
    }
}

// ---------------- layer1 fused aggregate: numerator + denominator -----------
__global__ void agg1_kernel(const int* __restrict__ ei, int E, int N) {
    int warp = threadIdx.x >> 5, lane = threadIdx.x & 31;
    long e = (long)blockIdx.x * 8 + warp;
    if (e >= (long)E + N) return;
    int src, dst;
    if (e < E) { src = __ldg(ei + e); dst = __ldg(ei + E + e); }
    else       { src = (int)(e - E); dst = src; }
    int head = lane >> 3;
    float s = g_asrc1[src * 4 + head] + g_adst1[dst * 4 + head];
    float ex = __expf(leaky(s));
    float4 v = ((const float4*)(g_xw1 + (size_t)src * 128))[lane];
    v.x *= ex; v.y *= ex; v.z *= ex; v.w *= ex;
    red_add_v4(g_h + (size_t)dst * 128 + lane * 4, v);
    float e0 = __shfl_sync(0xffffffffu, ex, 0);
    float e1 = __shfl_sync(0xffffffffu, ex, 8);
    float e2 = __shfl_sync(0xffffffffu, ex, 16);
    float e3 = __shfl_sync(0xffffffffu, ex, 24);
    if (lane == 0) red_add_v4(&g_den1[dst * 4], make_float4(e0, e1, e2, e3));
}

// ---------------- GEMM2 (h=relu(num/den+b1) on load; att2 in epilogue) ------
// 256 thr = 8 warps x 4 rows = 32 rows/block. lanes 0..19 own cols (lane, lane+20).
__global__ __launch_bounds__(256) void gemm2_kernel(
    const float* __restrict__ b1,
    const float* __restrict__ att_s, const float* __restrict__ att_d, int N) {
    __shared__ float sx[32][128];    // 16KB post-activation rows
    __shared__ float sW2t[40][132];  // transposed W2 [c][k], pad 132 (21KB)
    int rowBase = blockIdx.x * 32;
    int tid = threadIdx.x, warp = tid >> 5, lane = tid & 31;

    for (int i = tid; i < 1280; i += 256) {
        int c = i >> 5, k4 = i & 31;
        ((float4*)&sW2t[c][0])[k4] = ((const float4*)(g_W2t + c * 128))[k4];
    }
    for (int i = tid; i < 1024; i += 256) {
        int r = i >> 5, c4 = i & 31;
        int row = rowBase + r;
        if (row < N) {
            float4 v = ((const float4*)(g_h + (size_t)row * 128))[c4];
            float inv = 1.f / g_den1[row * 4 + (c4 >> 3)];
            float4 b = ((const float4*)b1)[c4];
            v.x = fmaxf(v.x * inv + b.x, 0.f);
            v.y = fmaxf(v.y * inv + b.y, 0.f);
            v.z = fmaxf(v.z * inv + b.z, 0.f);
            v.w = fmaxf(v.w * inv + b.w, 0.f);
            ((float4*)&sx[r][0])[c4] = v;
        } else {
            ((float4*)&sx[r][0])[c4] = make_float4(0.f, 0.f, 0.f, 0.f);
        }
    }
    __syncthreads();

    bool act = lane < 20;
    int cA = act ? lane : 0, cB = cA + 20;
    unsigned long long accA[4] = {0ull, 0ull, 0ull, 0ull};
    unsigned long long accB[4] = {0ull, 0ull, 0ull, 0ull};

#pragma unroll 4
    for (int k4 = 0; k4 < 32; ++k4) {
        double2 xp[4];
#pragma unroll
        for (int r = 0; r < 4; ++r)
            xp[r] = ((const double2*)&sx[warp * 4 + r][0])[k4];
        double2 wA = ((const double2*)&sW2t[cA][0])[k4];
        double2 wB = ((const double2*)&sW2t[cB][0])[k4];
        unsigned long long wA0 = __double_as_longlong(wA.x);
        unsigned long long wA1 = __double_as_longlong(wA.y);
        unsigned long long wB0 = __double_as_longlong(wB.x);
        unsigned long long wB1 = __double_as_longlong(wB.y);
#pragma unroll
        for (int r = 0; r < 4; ++r) {
            unsigned long long x0 = __double_as_longlong(xp[r].x);
            unsigned long long x1 = __double_as_longlong(xp[r].y);
            fma2(accA[r], x0, wA0); fma2(accA[r], x1, wA1);
            fma2(accB[r], x0, wB0); fma2(accB[r], x1, wB1);
        }
    }
    float asA = att_s[cA], adA = att_d[cA];
    float asB = att_s[cB], adB = att_d[cB];
#pragma unroll
    for (int r = 0; r < 4; ++r) {
        float lA0, lA1, lB0, lB1;
        unpack2(accA[r], lA0, lA1);
        unpack2(accB[r], lB0, lB1);
        float vA = lA0 + lA1, vB = lB0 + lB1;
        float ps = act ? (vA * asA + vB * asB) : 0.f;
        float pd = act ? (vA * adA + vB * adB) : 0.f;
#pragma unroll
        for (int o = 16; o; o >>= 1) {
            ps += __shfl_xor_sync(0xffffffffu, ps, o);
            pd += __shfl_xor_sync(0xffffffffu, pd, o);
        }
        int row = rowBase + warp * 4 + r;
        if (row < N) {
            if (act) {
                g_xw2[(size_t)row * F2 + cA] = vA;
                g_xw2[(size_t)row * F2 + cB] = vB;
            }
            if (lane == 0) { g_asrc2[row] = ps; g_adst2[row] = pd; }
        }
    }
}

// ---------------- layer2 fused aggregate: 3 edges per warp -------------------
__global__ void agg2_kernel(const int* __restrict__ ei,
                            float* __restrict__ out, int E, int N) {
    int warp = threadIdx.x >> 5, lane = threadIdx.x & 31;
    int grp = lane / 10, gl = lane - grp * 10;
    long e = (long)blockIdx.x * 24 + warp * 3 + grp;
    long EP = (long)E + N;
    if (grp >= 3 || e >= EP) return;
    int src, dst;
    if (e < E) { src = __ldg(ei + e); dst = __ldg(ei + E + e); }
    else       { src = (int)(e - E); dst = src; }
    float s = g_asrc2[src] + g_adst2[dst];
    float ex = __expf(leaky(s));
    float4 v = ((const float4*)(g_xw2 + (size_t)src * F2))[gl];
    v.x *= ex; v.y *= ex; v.z *= ex; v.w *= ex;
    red_add_v4(out + (size_t)dst * F2 + gl * 4, v);
    if (gl == 0) red_add_f32(&g_den2[dst], ex);
}

// ---------------- final: out = out/den2 + b2 (32-bit index math) -------------
__global__ void final_kernel(float* __restrict__ out, const float* __restrict__ b2,
                             int N) {
    unsigned total = (unsigned)N * F2;
    for (unsigned i = blockIdx.x * blockDim.x + threadIdx.x; i < total;
         i += gridDim.x * blockDim.x) {
        unsigned n = i / F2;          // magic-mul div
        unsigned c = i - n * F2;
        out[i] = out[i] / g_den2[n] + b2[c];
    }
}

// ============================================================================
extern "C" void kernel_launch(void* const* d_in, const int* in_sizes, int n_in,
                              void* d_out, int out_size) {
    const float* x   = (const float*)d_in[0];
    const int*   ei  = (const int*)d_in[1];   // int32 (JAX default-config downcast)
    const float* W1  = (const float*)d_in[2];
    const float* as1 = (const float*)d_in[3];
    const float* ad1 = (const float*)d_in[4];
    const float* b1  = (const float*)d_in[5];
    const float* W2  = (const float*)d_in[6];
    const float* as2 = (const float*)d_in[7];
    const float* ad2 = (const float*)d_in[8];
    const float* b2  = (const float*)d_in[9];
    float*       out = (float*)d_out;

    int N  = in_sizes[0] / DIM1;   // 100000
    int E  = in_sizes[1] / 2;      // 1600000
    int EP = E + N;

    prep_kernel <<<4096, 256>>>(W1, W2, out, N);
    gemm1_kernel<<<(N + 31) / 32, 256>>>(x, as1, ad1, N);
    agg1_kernel <<<(EP + 7) / 8, 256>>>(ei, E, N);
    gemm2_kernel<<<(N + 31) / 32, 256>>>(b1, as2, ad2, N);
    agg2_kernel <<<(EP + 23) / 24, 256>>>(ei, out, E, N);
    final_kernel<<<2048, 256>>>(out, b2, N);
}

// round 7
// speedup vs baseline: 1.4804x; 1.4804x over previous
#include <cuda_runtime.h>

#define NN   100000
#define DIM1 128
#define H1   4
#define F2   40

// ---------------- scratch (device globals: allocation-free) ----------------
__device__ float g_xw1[(size_t)NN * DIM1];   // layer1 x@W1           [N,128]
__device__ float g_h  [(size_t)NN * DIM1];   // layer1 numerator acc  [N,128]
__device__ float g_asrc1[NN * H1];
__device__ float g_adst1[NN * H1];
__device__ float g_den1 [NN * H1];
__device__ float g_xw2[(size_t)NN * F2];     // layer2 h@W2           [N,40]
__device__ float g_asrc2[NN];
__device__ float g_adst2[NN];
__device__ float g_den2 [NN];
__device__ float g_W1t[128 * 128];           // W1 transposed [c][k]
__device__ float g_W2t[40 * 128];            // W2 transposed [c][k]

__device__ __forceinline__ float leaky(float v) { return v > 0.f ? v : 0.2f * v; }

__device__ __forceinline__ void red_add_v4(float* addr, float4 v) {
    asm volatile("red.global.add.v4.f32 [%0], {%1, %2, %3, %4};"
                 :: "l"(addr), "f"(v.x), "f"(v.y), "f"(v.z), "f"(v.w) : "memory");
}
__device__ __forceinline__ void red_add_f32(float* addr, float v) {
    asm volatile("red.global.add.f32 [%0], %1;" :: "l"(addr), "f"(v) : "memory");
}
// Packed fp32x2 FMA (Blackwell FFMA2): d = a*b + d
__device__ __forceinline__ void fma2(unsigned long long& d,
                                     unsigned long long a, unsigned long long b) {
    asm("fma.rn.f32x2 %0, %1, %2, %0;" : "+l"(d) : "l"(a), "l"(b));
}
__device__ __forceinline__ void unpack2(unsigned long long d, float& lo, float& hi) {
    asm("mov.b64 {%0, %1}, %2;" : "=f"(lo), "=f"(hi) : "l"(d));
}

// ---------------- prep: zero accumulators + transpose weights ---------------
__global__ void prep_kernel(const float* __restrict__ W1, const float* __restrict__ W2,
                            float* __restrict__ out, int N) {
    size_t nh = (size_t)N * DIM1, nd1 = (size_t)N * H1, no = (size_t)N * F2;
    size_t tW = 128 * 128 + 40 * 128;
    size_t total = tW + nh + nd1 + no + N;
    for (size_t i = (size_t)blockIdx.x * blockDim.x + threadIdx.x; i < total;
         i += (size_t)gridDim.x * blockDim.x) {
        if (i < 16384) {
            int k = (int)i >> 7, c = (int)i & 127;
            g_W1t[c * 128 + k] = W1[i];
        } else if (i < tW) {
            int t = (int)(i - 16384);
            int k = t / 40, c = t - k * 40;
            g_W2t[c * 128 + k] = W2[t];
        } else {
            size_t j = i - tW;
            if (j < nh) g_h[j] = 0.f;
            else if (j < nh + nd1) g_den1[j - nh] = 0.f;
            else if (j < nh + nd1 + no) out[j - nh - nd1] = 0.f;
            else g_den2[j - nh - nd1 - no] = 0.f;
        }
    }
}

// ---------------- GEMM1 + fused attention dots ------------------------------
// 256 thr = 8 warps. warp -> (rg = warp>>1 : 8 rows) x (j2 = warp&1 : 64 cols).
// sWt stride 68 words = 272B: 16B-aligned rows; phase offsets 16*l mod 128 -> no conflicts.
__global__ __launch_bounds__(256) void gemm1_kernel(
    const float* __restrict__ x,
    const float* __restrict__ att_s, const float* __restrict__ att_d, int N) {
    __shared__ float sWt[128][68];   // 34KB
    __shared__ float sx[32][64];     // 8KB
    int rowBase = blockIdx.x * 32;
    int tid = threadIdx.x, warp = tid >> 5, lane = tid & 31;
    int j2 = warp & 1;
    int rg = warp >> 1;

    unsigned long long acc[8][2];
#pragma unroll
    for (int r = 0; r < 8; ++r) { acc[r][0] = 0ull; acc[r][1] = 0ull; }

    for (int kt = 0; kt < 2; ++kt) {
        __syncthreads();
        // sWt[c][k] = W1t[c][kt*64+k]  (128 rows x 16 float4)
        for (int i = tid; i < 2048; i += 256) {
            int c = i >> 4, k4 = i & 15;
            ((float4*)&sWt[c][0])[k4] =
                ((const float4*)(g_W1t + c * 128 + kt * 64))[k4];
        }
        // sx: 32 x 64 floats = 512 float4
        for (int i = tid; i < 512; i += 256) {
            int r = i >> 4, c4 = i & 15;
            int row = rowBase + r;
            ((float4*)&sx[r][0])[c4] = (row < N)
                ? ((const float4*)(x + (size_t)row * 128 + kt * 64))[c4]
                : make_float4(0.f, 0.f, 0.f, 0.f);
        }
        __syncthreads();
#pragma unroll 4
        for (int k4 = 0; k4 < 16; ++k4) {
            double2 xp[8];
#pragma unroll
            for (int r = 0; r < 8; ++r)
                xp[r] = ((const double2*)&sx[rg * 8 + r][0])[k4];
#pragma unroll
            for (int jj = 0; jj < 2; ++jj) {
                int c = j2 * 64 + jj * 32 + lane;
                double2 w = ((const double2*)&sWt[c][0])[k4];
                unsigned long long w0 = __double_as_longlong(w.x);
                unsigned long long w1 = __double_as_longlong(w.y);
#pragma unroll
                for (int r = 0; r < 8; ++r) {
                    fma2(acc[r][jj], __double_as_longlong(xp[r].x), w0);
                    fma2(acc[r][jj], __double_as_longlong(xp[r].y), w1);
                }
            }
        }
    }
    // epilogue: horizontal add, store, per-head attention dots
#pragma unroll
    for (int jj = 0; jj < 2; ++jj) {
        int c = j2 * 64 + jj * 32 + lane;
        int head = c >> 5;
        float as = att_s[c], ad = att_d[c];
#pragma unroll
        for (int r = 0; r < 8; ++r) {
            float lo, hi;
            unpack2(acc[r][jj], lo, hi);
            float v = lo + hi;
            float ps = v * as, pd = v * ad;
#pragma unroll
            for (int o = 16; o; o >>= 1) {
                ps += __shfl_xor_sync(0xffffffffu, ps, o);
                pd += __shfl_xor_sync(0xffffffffu, pd, o);
            }
            int row = rowBase + rg * 8 + r;
            if (row < N) {
                g_xw1[(size_t)row * 128 + c] = v;
                if (lane == 0) {
                    g_asrc1[row * 4 + head] = ps;
                    g_adst1[row * 4 + head] = pd;
                }
            }
        }
    }
}

// ---------------- layer1 fused aggregate: numerator + denominator -----------
__global__ void agg1_kernel(const int* __restrict__ ei, int E, int N) {
    int warp = threadIdx.x >> 5, lane = threadIdx.x & 31;
    long e = (long)blockIdx.x * 8 + warp;
    if (e >= (long)E + N) return;
    int src, dst;
    if (e < E) { src = __ldg(ei + e); dst = __ldg(ei + E + e); }
    else       { src = (int)(e - E); dst = src; }
    int head = lane >> 3;
    float s = g_asrc1[src * 4 + head] + g_adst1[dst * 4 + head];
    float ex = __expf(leaky(s));
    float4 v = ((const float4*)(g_xw1 + (size_t)src * 128))[lane];
    v.x *= ex; v.y *= ex; v.z *= ex; v.w *= ex;
    red_add_v4(g_h + (size_t)dst * 128 + lane * 4, v);
    float e0 = __shfl_sync(0xffffffffu, ex, 0);
    float e1 = __shfl_sync(0xffffffffu, ex, 8);
    float e2 = __shfl_sync(0xffffffffu, ex, 16);
    float e3 = __shfl_sync(0xffffffffu, ex, 24);
    if (lane == 0) red_add_v4(&g_den1[dst * 4], make_float4(e0, e1, e2, e3));
}

// ---------------- GEMM2 (h=relu(num/den+b1) on load; att2 in epilogue) ------
// 256 thr = 8 warps x 8 rows = 64 rows/block. lanes 0..19 own cols (lane, lane+20).
// sW2t stride 132 words = 528B: 16B-aligned; phase offsets 16*l mod 128 -> no conflicts.
__global__ __launch_bounds__(256) void gemm2_kernel(
    const float* __restrict__ b1,
    const float* __restrict__ att_s, const float* __restrict__ att_d, int N) {
    __shared__ float sx[64][128];    // 32KB post-activation rows
    __shared__ float sW2t[40][132];  // ~20.6KB
    int rowBase = blockIdx.x * 64;
    int tid = threadIdx.x, warp = tid >> 5, lane = tid & 31;

    for (int i = tid; i < 1280; i += 256) {
        int c = i >> 5, k4 = i & 31;
        ((float4*)&sW2t[c][0])[k4] = ((const float4*)(g_W2t + c * 128))[k4];
    }
    for (int i = tid; i < 2048; i += 256) {
        int r = i >> 5, c4 = i & 31;
        int row = rowBase + r;
        if (row < N) {
            float4 v = ((const float4*)(g_h + (size_t)row * 128))[c4];
            float inv = 1.f / g_den1[row * 4 + (c4 >> 3)];
            float4 b = ((const float4*)b1)[c4];
            v.x = fmaxf(v.x * inv + b.x, 0.f);
            v.y = fmaxf(v.y * inv + b.y, 0.f);
            v.z = fmaxf(v.z * inv + b.z, 0.f);
            v.w = fmaxf(v.w * inv + b.w, 0.f);
            ((float4*)&sx[r][0])[c4] = v;
        } else {
            ((float4*)&sx[r][0])[c4] = make_float4(0.f, 0.f, 0.f, 0.f);
        }
    }
    __syncthreads();

    bool act = lane < 20;
    int cA = act ? lane : 0, cB = cA + 20;
    unsigned long long accA[8], accB[8];
#pragma unroll
    for (int r = 0; r < 8; ++r) { accA[r] = 0ull; accB[r] = 0ull; }

#pragma unroll 4
    for (int k4 = 0; k4 < 32; ++k4) {
        double2 wA = ((const double2*)&sW2t[cA][0])[k4];
        double2 wB = ((const double2*)&sW2t[cB][0])[k4];
        unsigned long long wA0 = __double_as_longlong(wA.x);
        unsigned long long wA1 = __double_as_longlong(wA.y);
        unsigned long long wB0 = __double_as_longlong(wB.x);
        unsigned long long wB1 = __double_as_longlong(wB.y);
#pragma unroll
        for (int r = 0; r < 8; ++r) {
            double2 xp = ((const double2*)&sx[warp * 8 + r][0])[k4];
            unsigned long long x0 = __double_as_longlong(xp.x);
            unsigned long long x1 = __double_as_longlong(xp.y);
            fma2(accA[r], x0, wA0); fma2(accA[r], x1, wA1);
            fma2(accB[r], x0, wB0); fma2(accB[r], x1, wB1);
        }
    }
    float asA = att_s[cA], adA = att_d[cA];
    float asB = att_s[cB], adB = att_d[cB];
#pragma unroll
    for (int r = 0; r < 8; ++r) {
        float lA0, lA1, lB0, lB1;
        unpack2(accA[r], lA0, lA1);
        unpack2(accB[r], lB0, lB1);
        float vA = lA0 + lA1, vB = lB0 + lB1;
        float ps = act ? (vA * asA + vB * asB) : 0.f;
        float pd = act ? (vA * adA + vB * adB) : 0.f;
#pragma unroll
        for (int o = 16; o; o >>= 1) {
            ps += __shfl_xor_sync(0xffffffffu, ps, o);
            pd += __shfl_xor_sync(0xffffffffu, pd, o);
        }
        int row = rowBase + warp * 8 + r;
        if (row < N) {
            if (act) {
                g_xw2[(size_t)row * F2 + cA] = vA;
                g_xw2[(size_t)row * F2 + cB] = vB;
            }
            if (lane == 0) { g_asrc2[row] = ps; g_adst2[row] = pd; }
        }
    }
}

// ---------------- layer2 fused aggregate: 3 edges per warp -------------------
__global__ void agg2_kernel(const int* __restrict__ ei,
                            float* __restrict__ out, int E, int N) {
    int warp = threadIdx.x >> 5, lane = threadIdx.x & 31;
    int grp = lane / 10, gl = lane - grp * 10;
    long e = (long)blockIdx.x * 24 + warp * 3 + grp;
    long EP = (long)E + N;
    if (grp >= 3 || e >= EP) return;
    int src, dst;
    if (e < E) { src = __ldg(ei + e); dst = __ldg(ei + E + e); }
    else       { src = (int)(e - E); dst = src; }
    float s = g_asrc2[src] + g_adst2[dst];
    float ex = __expf(leaky(s));
    float4 v = ((const float4*)(g_xw2 + (size_t)src * F2))[gl];
    v.x *= ex; v.y *= ex; v.z *= ex; v.w *= ex;
    red_add_v4(out + (size_t)dst * F2 + gl * 4, v);
    if (gl == 0) red_add_f32(&g_den2[dst], ex);
}

// ---------------- final: out = out/den2 + b2 (32-bit index math) -------------
__global__ void final_kernel(float* __restrict__ out, const float* __restrict__ b2,
                             int N) {
    unsigned total = (unsigned)N * F2;
    for (unsigned i = blockIdx.x * blockDim.x + threadIdx.x; i < total;
         i += gridDim.x * blockDim.x) {
        unsigned n = i / F2;
        unsigned c = i - n * F2;
        out[i] = out[i] / g_den2[n] + b2[c];
    }
}

// ============================================================================
extern "C" void kernel_launch(void* const* d_in, const int* in_sizes, int n_in,
                              void* d_out, int out_size) {
    const float* x   = (const float*)d_in[0];
    const int*   ei  = (const int*)d_in[1];   // int32 (JAX default-config downcast)
    const float* W1  = (const float*)d_in[2];
    const float* as1 = (const float*)d_in[3];
    const float* ad1 = (const float*)d_in[4];
    const float* b1  = (const float*)d_in[5];
    const float* W2  = (const float*)d_in[6];
    const float* as2 = (const float*)d_in[7];
    const float* ad2 = (const float*)d_in[8];
    const float* b2  = (const float*)d_in[9];
    float*       out = (float*)d_out;

    int N  = in_sizes[0] / DIM1;   // 100000
    int E  = in_sizes[1] / 2;      // 1600000
    int EP = E + N;

    prep_kernel <<<4096, 256>>>(W1, W2, out, N);
    gemm1_kernel<<<(N + 31) / 32, 256>>>(x, as1, ad1, N);
    agg1_kernel <<<(EP + 7) / 8, 256>>>(ei, E, N);
    gemm2_kernel<<<(N + 63) / 64, 256>>>(b1, as2, ad2, N);
    agg2_kernel <<<(EP + 23) / 24, 256>>>(ei, out, E, N);
    final_kernel<<<2048, 256>>>(out, b2, N);
}

// round 9
// speedup vs baseline: 1.4962x; 1.0107x over previous
#include <cuda_runtime.h>
#include <cstdint>

#define NN   100000
#define DIM1 128
#define H1   4
#define F2   40

// ---------------- scratch (device globals: allocation-free) ----------------
__device__ float g_xw1[(size_t)NN * DIM1];   // layer1 x@W1           [N,128]
__device__ float g_h  [(size_t)NN * DIM1];   // layer1 numerator acc  [N,128]
__device__ float g_asrc1[NN * H1];
__device__ float g_adst1[NN * H1];
__device__ float g_den1 [NN * H1];
__device__ float g_xw2[(size_t)NN * F2];     // layer2 h@W2           [N,40]
__device__ float g_asrc2[NN];
__device__ float g_adst2[NN];
__device__ float g_den2 [NN];

__device__ __forceinline__ float leaky(float v) { return v > 0.f ? v : 0.2f * v; }

__device__ __forceinline__ void red_add_v4(float* addr, float4 v) {
    asm volatile("red.global.add.v4.f32 [%0], {%1, %2, %3, %4};"
                 :: "l"(addr), "f"(v.x), "f"(v.y), "f"(v.z), "f"(v.w) : "memory");
}
__device__ __forceinline__ void red_add_f32(float* addr, float v) {
    asm volatile("red.global.add.f32 [%0], %1;" :: "l"(addr), "f"(v) : "memory");
}
__device__ __forceinline__ uint32_t f2tf32(float f) {
    uint32_t r;
    asm("cvt.rna.tf32.f32 %0, %1;" : "=r"(r) : "f"(f));
    return r;
}
__device__ __forceinline__ void mma_tf32(float* d, uint32_t a0, uint32_t a1,
                                         uint32_t a2, uint32_t a3,
                                         uint32_t b0, uint32_t b1) {
    asm volatile(
        "mma.sync.aligned.m16n8k8.row.col.f32.tf32.tf32.f32 "
        "{%0,%1,%2,%3}, {%4,%5,%6,%7}, {%8,%9}, {%0,%1,%2,%3};"
        : "+f"(d[0]), "+f"(d[1]), "+f"(d[2]), "+f"(d[3])
        : "r"(a0), "r"(a1), "r"(a2), "r"(a3), "r"(b0), "r"(b1));
}

// ---------------- zero all accumulators ------------------------------------
__global__ void zero_kernel(float* __restrict__ out, int N) {
    size_t nh = (size_t)N * DIM1, nd1 = (size_t)N * H1, no = (size_t)N * F2;
    size_t total = nh + nd1 + no + N;
    for (size_t i = (size_t)blockIdx.x * blockDim.x + threadIdx.x; i < total;
         i += (size_t)gridDim.x * blockDim.x) {
        if (i < nh) g_h[i] = 0.f;
        else if (i < nh + nd1) g_den1[i - nh] = 0.f;
        else if (i < nh + nd1 + no) out[i - nh - nd1] = 0.f;
        else g_den2[i - nh - nd1 - no] = 0.f;
    }
}

// ---------------- GEMM1 via tensor cores (3xTF32) + fused attention dots ----
// block 256 thr = 8 warps x 16 rows = 128 rows. Each warp: 16 rows x 128 cols
// = 16 m16n8 tiles; K=128 in 8 chunks of 16 (2 k-steps of 8).
__global__ __launch_bounds__(256) void gemm1_kernel(
    const float* __restrict__ x, const float* __restrict__ W,
    const float* __restrict__ att_s, const float* __restrict__ att_d, int N) {
    __shared__ uint32_t sAh[128][20], sAl[128][20];   // x hi/lo, stride 20 (conflict-free)
    __shared__ uint32_t sBh[16][132], sBl[16][132];   // W hi/lo, stride 132
    int rowBase = blockIdx.x * 128;
    int tid = threadIdx.x, warp = tid >> 5, lane = tid & 31;
    int g = lane >> 2, tig = lane & 3;
    int wrow = warp * 16;

    float acc[16][4];
#pragma unroll
    for (int j = 0; j < 16; ++j)
#pragma unroll
        for (int q = 0; q < 4; ++q) acc[j][q] = 0.f;

    for (int kc = 0; kc < 8; ++kc) {
        __syncthreads();
        // A tile: 128 rows x 16 k = 512 float4
        for (int i = tid; i < 512; i += 256) {
            int r = i >> 2, q = i & 3;
            int row = rowBase + r;
            float4 v = (row < N)
                ? *((const float4*)(x + (size_t)row * 128 + kc * 16 + q * 4))
                : make_float4(0.f, 0.f, 0.f, 0.f);
            const float* vf = (const float*)&v;
#pragma unroll
            for (int t = 0; t < 4; ++t) {
                uint32_t h = f2tf32(vf[t]);
                sAh[r][q * 4 + t] = h;
                sAl[r][q * 4 + t] = f2tf32(vf[t] - __uint_as_float(h));
            }
        }
        // B tile: 16 k x 128 cols = 512 float4
        for (int i = tid; i < 512; i += 256) {
            int k = i >> 5, q = i & 31;
            float4 v = *((const float4*)(W + (size_t)(kc * 16 + k) * 128 + q * 4));
            const float* vf = (const float*)&v;
#pragma unroll
            for (int t = 0; t < 4; ++t) {
                uint32_t h = f2tf32(vf[t]);
                sBh[k][q * 4 + t] = h;
                sBl[k][q * 4 + t] = f2tf32(vf[t] - __uint_as_float(h));
            }
        }
        __syncthreads();
#pragma unroll
        for (int ks = 0; ks < 2; ++ks) {
            int k0 = ks * 8;
            uint32_t ah0 = sAh[wrow + g][k0 + tig];
            uint32_t ah1 = sAh[wrow + g + 8][k0 + tig];
            uint32_t ah2 = sAh[wrow + g][k0 + tig + 4];
            uint32_t ah3 = sAh[wrow + g + 8][k0 + tig + 4];
            uint32_t al0 = sAl[wrow + g][k0 + tig];
            uint32_t al1 = sAl[wrow + g + 8][k0 + tig];
            uint32_t al2 = sAl[wrow + g][k0 + tig + 4];
            uint32_t al3 = sAl[wrow + g + 8][k0 + tig + 4];
#pragma unroll
            for (int j = 0; j < 16; ++j) {
                int n0 = j * 8;
                uint32_t bh0 = sBh[k0 + tig][n0 + g];
                uint32_t bh1 = sBh[k0 + tig + 4][n0 + g];
                uint32_t bl0 = sBl[k0 + tig][n0 + g];
                uint32_t bl1 = sBl[k0 + tig + 4][n0 + g];
                mma_tf32(acc[j], ah0, ah1, ah2, ah3, bh0, bh1);
                mma_tf32(acc[j], ah0, ah1, ah2, ah3, bl0, bl1);
                mma_tf32(acc[j], al0, al1, al2, al3, bh0, bh1);
            }
        }
    }
    // epilogue: rows row0 = rowBase+wrow+g (c0,c1), row1 = row0+8 (c2,c3)
    int row0 = rowBase + wrow + g, row1 = row0 + 8;
    float ps0[4] = {0,0,0,0}, pd0[4] = {0,0,0,0};
    float ps1[4] = {0,0,0,0}, pd1[4] = {0,0,0,0};
#pragma unroll
    for (int j = 0; j < 16; ++j) {
        int col = j * 8 + tig * 2;
        int head = j >> 2;
        float a0 = att_s[col], a1 = att_s[col + 1];
        float d0 = att_d[col], d1 = att_d[col + 1];
        ps0[head] += acc[j][0] * a0 + acc[j][1] * a1;
        pd0[head] += acc[j][0] * d0 + acc[j][1] * d1;
        ps1[head] += acc[j][2] * a0 + acc[j][3] * a1;
        pd1[head] += acc[j][2] * d0 + acc[j][3] * d1;
        if (row0 < N)
            *(float2*)(g_xw1 + (size_t)row0 * 128 + col) = make_float2(acc[j][0], acc[j][1]);
        if (row1 < N)
            *(float2*)(g_xw1 + (size_t)row1 * 128 + col) = make_float2(acc[j][2], acc[j][3]);
    }
#pragma unroll
    for (int h = 0; h < 4; ++h) {
#pragma unroll
        for (int o = 1; o < 4; o <<= 1) {
            ps0[h] += __shfl_xor_sync(0xffffffffu, ps0[h], o);
            pd0[h] += __shfl_xor_sync(0xffffffffu, pd0[h], o);
            ps1[h] += __shfl_xor_sync(0xffffffffu, ps1[h], o);
            pd1[h] += __shfl_xor_sync(0xffffffffu, pd1[h], o);
        }
    }
    if (tig == 0) {
        if (row0 < N) {
            *(float4*)(g_asrc1 + row0 * 4) = make_float4(ps0[0], ps0[1], ps0[2], ps0[3]);
            *(float4*)(g_adst1 + row0 * 4) = make_float4(pd0[0], pd0[1], pd0[2], pd0[3]);
        }
        if (row1 < N) {
            *(float4*)(g_asrc1 + row1 * 4) = make_float4(ps1[0], ps1[1], ps1[2], ps1[3]);
            *(float4*)(g_adst1 + row1 * 4) = make_float4(pd1[0], pd1[1], pd1[2], pd1[3]);
        }
    }
}

// ---------------- layer1 fused aggregate: numerator + denominator -----------
__global__ void agg1_kernel(const int* __restrict__ ei, int E, int N) {
    int warp = threadIdx.x >> 5, lane = threadIdx.x & 31;
    long e = (long)blockIdx.x * 8 + warp;
    if (e >= (long)E + N) return;
    int src, dst;
    if (e < E) { src = __ldg(ei + e); dst = __ldg(ei + E + e); }
    else       { src = (int)(e - E); dst = src; }
    int head = lane >> 3;
    float s = g_asrc1[src * 4 + head] + g_adst1[dst * 4 + head];
    float ex = __expf(leaky(s));
    float4 v = ((const float4*)(g_xw1 + (size_t)src * 128))[lane];
    v.x *= ex; v.y *= ex; v.z *= ex; v.w *= ex;
    red_add_v4(g_h + (size_t)dst * 128 + lane * 4, v);
    float e0 = __shfl_sync(0xffffffffu, ex, 0);
    float e1 = __shfl_sync(0xffffffffu, ex, 8);
    float e2 = __shfl_sync(0xffffffffu, ex, 16);
    float e3 = __shfl_sync(0xffffffffu, ex, 24);
    if (lane == 0) red_add_v4(&g_den1[dst * 4], make_float4(e0, e1, e2, e3));
}

// ---------------- GEMM2 (R4 version: 58us measured) --------------------------
// h = relu(num/den + b1) on load; att2 in epilogue. 8 warps x 4 rows = 32 rows.
__global__ __launch_bounds__(256) void gemm2_kernel(
    const float* __restrict__ W2, const float* __restrict__ b1,
    const float* __restrict__ att_s, const float* __restrict__ att_d, int N) {
    __shared__ float sx[32][128];   // 16KB
    __shared__ float sW[128 * 40];  // 20KB
    int rowBase = blockIdx.x * 32;
    int tid = threadIdx.x, warp = tid >> 5, lane = tid & 31;
    for (int i = tid; i < 1280; i += 256)
        ((float4*)sW)[i] = ((const float4*)W2)[i];
    for (int i = tid; i < 1024; i += 256) {
        int r = i >> 5, c4 = i & 31;
        int row = rowBase + r;
        if (row < N) {
            float4 v = ((const float4*)(g_h + (size_t)row * 128))[c4];
            float inv = 1.f / g_den1[row * 4 + (c4 >> 3)];
            float4 b = ((const float4*)b1)[c4];
            v.x = fmaxf(v.x * inv + b.x, 0.f);
            v.y = fmaxf(v.y * inv + b.y, 0.f);
            v.z = fmaxf(v.z * inv + b.z, 0.f);
            v.w = fmaxf(v.w * inv + b.w, 0.f);
            ((float4*)&sx[r][0])[c4] = v;
        } else {
            ((float4*)&sx[r][0])[c4] = make_float4(0.f, 0.f, 0.f, 0.f);
        }
    }
    __syncthreads();

    float acc0[4] = {0.f, 0.f, 0.f, 0.f};
    float acc1[4] = {0.f, 0.f, 0.f, 0.f};
    bool hi = lane < 8;
#pragma unroll 4
    for (int k = 0; k < 128; ++k) {
        float w0 = sW[k * 40 + lane];
        float w1 = hi ? sW[k * 40 + 32 + lane] : 0.f;
#pragma unroll
        for (int r = 0; r < 4; ++r) {
            float xv = sx[warp * 4 + r][k];
            acc0[r] += xv * w0;
            acc1[r] += xv * w1;
        }
    }
    // attention dots: lane owns col lane (and lane+32 if hi)
    float asA = att_s[lane < 40 ? lane : 0], adA = att_d[lane < 40 ? lane : 0];
    float asB = hi ? att_s[lane + 32] : 0.f, adB = hi ? att_d[lane + 32] : 0.f;
    bool actA = lane < 40;
#pragma unroll
    for (int r = 0; r < 4; ++r) {
        float ps = (actA ? acc0[r] * asA : 0.f) + acc1[r] * asB;
        float pd = (actA ? acc0[r] * adA : 0.f) + acc1[r] * adB;
#pragma unroll
        for (int o = 16; o; o >>= 1) {
            ps += __shfl_xor_sync(0xffffffffu, ps, o);
            pd += __shfl_xor_sync(0xffffffffu, pd, o);
        }
        int row = rowBase + warp * 4 + r;
        if (row < N) {
            g_xw2[(size_t)row * F2 + lane] = acc0[r];   // lanes 32..39: see hi-store
            if (hi) g_xw2[(size_t)row * F2 + 32 + lane] = acc1[r];
            if (lane == 0) { g_asrc2[row] = ps; g_adst2[row] = pd; }
        }
    }
}

// ---------------- layer2 fused aggregate: 3 edges per warp -------------------
__global__ void agg2_kernel(const int* __restrict__ ei,
                            float* __restrict__ out, int E, int N) {
    int warp = threadIdx.x >> 5, lane = threadIdx.x & 31;
    int grp = lane / 10, gl = lane - grp * 10;
    long e = (long)blockIdx.x * 24 + warp * 3 + grp;
    long EP = (long)E + N;
    if (grp >= 3 || e >= EP) return;
    int src, dst;
    if (e < E) { src = __ldg(ei + e); dst = __ldg(ei + E + e); }
    else       { src = (int)(e - E); dst = src; }
    float s = g_asrc2[src] + g_adst2[dst];
    float ex = __expf(leaky(s));
    float4 v = ((const float4*)(g_xw2 + (size_t)src * F2))[gl];
    v.x *= ex; v.y *= ex; v.z *= ex; v.w *= ex;
    red_add_v4(out + (size_t)dst * F2 + gl * 4, v);
    if (gl == 0) red_add_f32(&g_den2[dst], ex);
}

// ---------------- final: out = out/den2 + b2 ---------------------------------
__global__ void final_kernel(float* __restrict__ out, const float* __restrict__ b2,
                             int N) {
    unsigned total = (unsigned)N * F2;
    for (unsigned i = blockIdx.x * blockDim.x + threadIdx.x; i < total;
         i += gridDim.x * blockDim.x) {
        unsigned n = i / F2;
        unsigned c = i - n * F2;
        out[i] = out[i] / g_den2[n] + b2[c];
    }
}

// ============================================================================
extern "C" void kernel_launch(void* const* d_in, const int* in_sizes, int n_in,
                              void* d_out, int out_size) {
    const float* x   = (const float*)d_in[0];
    const int*   ei  = (const int*)d_in[1];   // int32 (JAX default-config downcast)
    const float* W1  = (const float*)d_in[2];
    const float* as1 = (const float*)d_in[3];
    const float* ad1 = (const float*)d_in[4];
    const float* b1  = (const float*)d_in[5];
    const float* W2  = (const float*)d_in[6];
    const float* as2 = (const float*)d_in[7];
    const float* ad2 = (const float*)d_in[8];
    const float* b2  = (const float*)d_in[9];
    float*       out = (float*)d_out;

    int N  = in_sizes[0] / DIM1;   // 100000
    int E  = in_sizes[1] / 2;      // 1600000
    int EP = E + N;

    zero_kernel <<<4096, 256>>>(out, N);
    gemm1_kernel<<<(N + 127) / 128, 256>>>(x, W1, as1, ad1, N);
    agg1_kernel <<<(EP + 7) / 8, 256>>>(ei, E, N);
    gemm2_kernel<<<(N + 31) / 32, 256>>>(W2, b1, as2, ad2, N);
    agg2_kernel <<<(EP + 23) / 24, 256>>>(ei, out, E, N);
    final_kernel<<<2048, 256>>>(out, b2, N);
}

// round 10
// speedup vs baseline: 1.9801x; 1.3234x over previous
#include <cuda_runtime.h>
#include <cstdint>

#define NN    100000
#define EMAX  1700000
#define DIM1  128
#define H1    4
#define F2    40

// ---------------- scratch (device globals: allocation-free) ----------------
__device__ float g_xw1[(size_t)NN * DIM1];   // layer1 x@W1        [N,128]
__device__ float g_h  [(size_t)NN * DIM1];   // layer1 activated   [N,128]
__device__ float g_asrc1[NN * H1];
__device__ float g_adst1[NN * H1];
__device__ float g_xw2[(size_t)NN * F2];     // layer2 h@W2        [N,40]
__device__ float g_asrc2[NN];
__device__ float g_adst2[NN];
__device__ int   g_cnt [NN];                 // per-dst degree
__device__ int   g_fill[NN];                 // scatter cursors
__device__ int   g_off [NN + 1];             // CSR offsets
__device__ int   g_srt [EMAX];               // src indices sorted by dst

__device__ __forceinline__ float leaky(float v) { return v > 0.f ? v : 0.2f * v; }

__device__ __forceinline__ uint32_t f2tf32(float f) {
    uint32_t r;
    asm("cvt.rna.tf32.f32 %0, %1;" : "=r"(r) : "f"(f));
    return r;
}
__device__ __forceinline__ void mma_tf32(float* d, uint32_t a0, uint32_t a1,
                                         uint32_t a2, uint32_t a3,
                                         uint32_t b0, uint32_t b1) {
    asm volatile(
        "mma.sync.aligned.m16n8k8.row.col.f32.tf32.tf32.f32 "
        "{%0,%1,%2,%3}, {%4,%5,%6,%7}, {%8,%9}, {%0,%1,%2,%3};"
        : "+f"(d[0]), "+f"(d[1]), "+f"(d[2]), "+f"(d[3])
        : "r"(a0), "r"(a1), "r"(a2), "r"(a3), "r"(b0), "r"(b1));
}

// ---------------- CSR build ---------------------------------------------------
__global__ void zero_cnt_kernel(int N) {
    int i = blockIdx.x * blockDim.x + threadIdx.x;
    if (i < N) { g_cnt[i] = 0; g_fill[i] = 0; }
}

__global__ void hist_kernel(const int* __restrict__ ei, int E) {
    int e = blockIdx.x * blockDim.x + threadIdx.x;
    if (e < E) atomicAdd(&g_cnt[__ldg(ei + E + e)], 1);
}

// single-block exclusive scan over g_cnt[0..NC) -> g_off
__global__ void scan_kernel(int NC) {
    __shared__ int wsum[32];
    int tid = threadIdx.x, lane = tid & 31, wid = tid >> 5;
    int carry = 0;
    for (int base = 0; base < NC; base += 1024) {
        int i = base + tid;
        int v = (i < NC) ? g_cnt[i] : 0;
        int s = v;
#pragma unroll
        for (int o = 1; o < 32; o <<= 1) {
            int t = __shfl_up_sync(0xffffffffu, s, o);
            if (lane >= o) s += t;
        }
        if (lane == 31) wsum[wid] = s;
        __syncthreads();
        if (wid == 0) {
            int ws = wsum[lane];
#pragma unroll
            for (int o = 1; o < 32; o <<= 1) {
                int t = __shfl_up_sync(0xffffffffu, ws, o);
                if (lane >= o) ws += t;
            }
            wsum[lane] = ws;
        }
        __syncthreads();
        int wexcl = (wid > 0) ? wsum[wid - 1] : 0;
        if (i < NC) g_off[i] = carry + wexcl + s - v;
        int total = wsum[31];
        __syncthreads();
        carry += total;
    }
    if (tid == 0) g_off[NC] = carry;
}

__global__ void scatter_kernel(const int* __restrict__ ei, int E) {
    int e = blockIdx.x * blockDim.x + threadIdx.x;
    if (e < E) {
        int src = __ldg(ei + e), dst = __ldg(ei + E + e);
        int pos = g_off[dst] + atomicAdd(&g_fill[dst], 1);
        g_srt[pos] = src;
    }
}

// ---------------- GEMM1 via tensor cores (3xTF32) + fused attention dots ----
__global__ __launch_bounds__(256) void gemm1_kernel(
    const float* __restrict__ x, const float* __restrict__ W,
    const float* __restrict__ att_s, const float* __restrict__ att_d, int N) {
    __shared__ uint32_t sAh[128][20], sAl[128][20];
    __shared__ uint32_t sBh[16][132], sBl[16][132];
    int rowBase = blockIdx.x * 128;
    int tid = threadIdx.x, warp = tid >> 5, lane = tid & 31;
    int g = lane >> 2, tig = lane & 3;
    int wrow = warp * 16;

    float acc[16][4];
#pragma unroll
    for (int j = 0; j < 16; ++j)
#pragma unroll
        for (int q = 0; q < 4; ++q) acc[j][q] = 0.f;

    for (int kc = 0; kc < 8; ++kc) {
        __syncthreads();
        for (int i = tid; i < 512; i += 256) {
            int r = i >> 2, q = i & 3;
            int row = rowBase + r;
            float4 v = (row < N)
                ? *((const float4*)(x + (size_t)row * 128 + kc * 16 + q * 4))
                : make_float4(0.f, 0.f, 0.f, 0.f);
            const float* vf = (const float*)&v;
#pragma unroll
            for (int t = 0; t < 4; ++t) {
                uint32_t h = f2tf32(vf[t]);
                sAh[r][q * 4 + t] = h;
                sAl[r][q * 4 + t] = f2tf32(vf[t] - __uint_as_float(h));
            }
        }
        for (int i = tid; i < 512; i += 256) {
            int k = i >> 5, q = i & 31;
            float4 v = *((const float4*)(W + (size_t)(kc * 16 + k) * 128 + q * 4));
            const float* vf = (const float*)&v;
#pragma unroll
            for (int t = 0; t < 4; ++t) {
                uint32_t h = f2tf32(vf[t]);
                sBh[k][q * 4 + t] = h;
                sBl[k][q * 4 + t] = f2tf32(vf[t] - __uint_as_float(h));
            }
        }
        __syncthreads();
#pragma unroll
        for (int ks = 0; ks < 2; ++ks) {
            int k0 = ks * 8;
            uint32_t ah0 = sAh[wrow + g][k0 + tig];
            uint32_t ah1 = sAh[wrow + g + 8][k0 + tig];
            uint32_t ah2 = sAh[wrow + g][k0 + tig + 4];
            uint32_t ah3 = sAh[wrow + g + 8][k0 + tig + 4];
            uint32_t al0 = sAl[wrow + g][k0 + tig];
            uint32_t al1 = sAl[wrow + g + 8][k0 + tig];
            uint32_t al2 = sAl[wrow + g][k0 + tig + 4];
            uint32_t al3 = sAl[wrow + g + 8][k0 + tig + 4];
#pragma unroll
            for (int j = 0; j < 16; ++j) {
                int n0 = j * 8;
                uint32_t bh0 = sBh[k0 + tig][n0 + g];
                uint32_t bh1 = sBh[k0 + tig + 4][n0 + g];
                uint32_t bl0 = sBl[k0 + tig][n0 + g];
                uint32_t bl1 = sBl[k0 + tig + 4][n0 + g];
                mma_tf32(acc[j], ah0, ah1, ah2, ah3, bh0, bh1);
                mma_tf32(acc[j], ah0, ah1, ah2, ah3, bl0, bl1);
                mma_tf32(acc[j], al0, al1, al2, al3, bh0, bh1);
            }
        }
    }
    int row0 = rowBase + wrow + g, row1 = row0 + 8;
    float ps0[4] = {0,0,0,0}, pd0[4] = {0,0,0,0};
    float ps1[4] = {0,0,0,0}, pd1[4] = {0,0,0,0};
#pragma unroll
    for (int j = 0; j < 16; ++j) {
        int col = j * 8 + tig * 2;
        int head = j >> 2;
        float a0 = att_s[col], a1 = att_s[col + 1];
        float d0 = att_d[col], d1 = att_d[col + 1];
        ps0[head] += acc[j][0] * a0 + acc[j][1] * a1;
        pd0[head] += acc[j][0] * d0 + acc[j][1] * d1;
        ps1[head] += acc[j][2] * a0 + acc[j][3] * a1;
        pd1[head] += acc[j][2] * d0 + acc[j][3] * d1;
        if (row0 < N)
            *(float2*)(g_xw1 + (size_t)row0 * 128 + col) = make_float2(acc[j][0], acc[j][1]);
        if (row1 < N)
            *(float2*)(g_xw1 + (size_t)row1 * 128 + col) = make_float2(acc[j][2], acc[j][3]);
    }
#pragma unroll
    for (int h = 0; h < 4; ++h) {
#pragma unroll
        for (int o = 1; o < 4; o <<= 1) {
            ps0[h] += __shfl_xor_sync(0xffffffffu, ps0[h], o);
            pd0[h] += __shfl_xor_sync(0xffffffffu, pd0[h], o);
            ps1[h] += __shfl_xor_sync(0xffffffffu, ps1[h], o);
            pd1[h] += __shfl_xor_sync(0xffffffffu, pd1[h], o);
        }
    }
    if (tig == 0) {
        if (row0 < N) {
            *(float4*)(g_asrc1 + row0 * 4) = make_float4(ps0[0], ps0[1], ps0[2], ps0[3]);
            *(float4*)(g_adst1 + row0 * 4) = make_float4(pd0[0], pd0[1], pd0[2], pd0[3]);
        }
        if (row1 < N) {
            *(float4*)(g_asrc1 + row1 * 4) = make_float4(ps1[0], ps1[1], ps1[2], ps1[3]);
            *(float4*)(g_adst1 + row1 * 4) = make_float4(pd1[0], pd1[1], pd1[2], pd1[3]);
        }
    }
}

// ---------------- layer1 CSR aggregate: warp per dst, no atomics -------------
// Fuses softmax normalize + bias + relu: writes final h.
__global__ void agg1_kernel(const float* __restrict__ b1, int N) {
    int dst = blockIdx.x * 8 + (threadIdx.x >> 5);
    int lane = threadIdx.x & 31;
    if (dst >= N) return;
    int head = lane >> 3;
    float adst = g_adst1[dst * 4 + head];
    // self-loop contribution
    float ex = __expf(leaky(g_asrc1[dst * 4 + head] + adst));
    float4 acc = ((const float4*)(g_xw1 + (size_t)dst * 128))[lane];
    acc.x *= ex; acc.y *= ex; acc.z *= ex; acc.w *= ex;
    float den = ex;
    int start = g_off[dst], end = g_off[dst + 1];
    for (int i = start; i < end; ++i) {
        int src = g_srt[i];                       // warp-uniform broadcast
        float e2 = __expf(leaky(g_asrc1[src * 4 + head] + adst));
        float4 v = ((const float4*)(g_xw1 + (size_t)src * 128))[lane];
        acc.x += v.x * e2; acc.y += v.y * e2;
        acc.z += v.z * e2; acc.w += v.w * e2;
        den += e2;
    }
    float inv = 1.f / den;
    float4 b = ((const float4*)b1)[lane];
    float4 o;
    o.x = fmaxf(acc.x * inv + b.x, 0.f);
    o.y = fmaxf(acc.y * inv + b.y, 0.f);
    o.z = fmaxf(acc.z * inv + b.z, 0.f);
    o.w = fmaxf(acc.w * inv + b.w, 0.f);
    ((float4*)(g_h + (size_t)dst * 128))[lane] = o;
}

// ---------------- GEMM2 (g_h already activated) + att2 dots ------------------
__global__ __launch_bounds__(256) void gemm2_kernel(
    const float* __restrict__ W2,
    const float* __restrict__ att_s, const float* __restrict__ att_d, int N) {
    __shared__ float sx[32][128];   // 16KB
    __shared__ float sW[128 * 40];  // 20KB
    int rowBase = blockIdx.x * 32;
    int tid = threadIdx.x, warp = tid >> 5, lane = tid & 31;
    for (int i = tid; i < 1280; i += 256)
        ((float4*)sW)[i] = ((const float4*)W2)[i];
    for (int i = tid; i < 1024; i += 256) {
        int r = i >> 5, c4 = i & 31;
        int row = rowBase + r;
        ((float4*)&sx[r][0])[c4] = (row < N)
            ? ((const float4*)(g_h + (size_t)row * 128))[c4]
            : make_float4(0.f, 0.f, 0.f, 0.f);
    }
    __syncthreads();

    float acc0[4] = {0.f, 0.f, 0.f, 0.f};
    float acc1[4] = {0.f, 0.f, 0.f, 0.f};
    bool hi = lane < 8;
#pragma unroll 4
    for (int k = 0; k < 128; ++k) {
        float w0 = sW[k * 40 + lane];
        float w1 = hi ? sW[k * 40 + 32 + lane] : 0.f;
#pragma unroll
        for (int r = 0; r < 4; ++r) {
            float xv = sx[warp * 4 + r][k];
            acc0[r] += xv * w0;
            acc1[r] += xv * w1;
        }
    }
    float asA = att_s[lane < 40 ? lane : 0], adA = att_d[lane < 40 ? lane : 0];
    float asB = hi ? att_s[lane + 32] : 0.f, adB = hi ? att_d[lane + 32] : 0.f;
    bool actA = lane < 40;
#pragma unroll
    for (int r = 0; r < 4; ++r) {
        float ps = (actA ? acc0[r] * asA : 0.f) + acc1[r] * asB;
        float pd = (actA ? acc0[r] * adA : 0.f) + acc1[r] * adB;
#pragma unroll
        for (int o = 16; o; o >>= 1) {
            ps += __shfl_xor_sync(0xffffffffu, ps, o);
            pd += __shfl_xor_sync(0xffffffffu, pd, o);
        }
        int row = rowBase + warp * 4 + r;
        if (row < N) {
            g_xw2[(size_t)row * F2 + lane] = acc0[r];
            if (hi) g_xw2[(size_t)row * F2 + 32 + lane] = acc1[r];
            if (lane == 0) { g_asrc2[row] = ps; g_adst2[row] = pd; }
        }
    }
}

// ---------------- layer2 CSR aggregate: warp per dst, 3 edge-groups ----------
// Writes out = num/den + b2 directly (no atomics, no final kernel).
__global__ void agg2_kernel(const float* __restrict__ b2,
                            float* __restrict__ out, int N) {
    int dst = blockIdx.x * 8 + (threadIdx.x >> 5);
    int lane = threadIdx.x & 31;
    if (dst >= N) return;
    int grp = lane / 10, gl = lane - grp * 10;   // grp 3 = lanes 30,31 idle
    float adst = g_adst2[dst];
    float4 acc = make_float4(0.f, 0.f, 0.f, 0.f);
    float den = 0.f;
    if (grp == 0) {      // self-loop in group 0
        float ex = __expf(leaky(g_asrc2[dst] + adst));
        float4 v = ((const float4*)(g_xw2 + (size_t)dst * F2))[gl];
        acc.x = v.x * ex; acc.y = v.y * ex; acc.z = v.z * ex; acc.w = v.w * ex;
        den = ex;
    }
    int start = g_off[dst], end = g_off[dst + 1];
    if (grp < 3) {
        for (int i = start + grp; i < end; i += 3) {
            int src = g_srt[i];
            float ex = __expf(leaky(g_asrc2[src] + adst));
            float4 v = ((const float4*)(g_xw2 + (size_t)src * F2))[gl];
            acc.x += v.x * ex; acc.y += v.y * ex;
            acc.z += v.z * ex; acc.w += v.w * ex;
            den += ex;
        }
    }
    // combine groups 1,2 into group 0 (lanes 0..9)
    float4 a1, a2;
    a1.x = __shfl_sync(0xffffffffu, acc.x, lane + 10);
    a1.y = __shfl_sync(0xffffffffu, acc.y, lane + 10);
    a1.z = __shfl_sync(0xffffffffu, acc.z, lane + 10);
    a1.w = __shfl_sync(0xffffffffu, acc.w, lane + 10);
    a2.x = __shfl_sync(0xffffffffu, acc.x, lane + 20);
    a2.y = __shfl_sync(0xffffffffu, acc.y, lane + 20);
    a2.z = __shfl_sync(0xffffffffu, acc.z, lane + 20);
    a2.w = __shfl_sync(0xffffffffu, acc.w, lane + 20);
    float d1 = __shfl_sync(0xffffffffu, den, lane + 10);
    float d2 = __shfl_sync(0xffffffffu, den, lane + 20);
    if (grp == 0) {
        acc.x += a1.x + a2.x; acc.y += a1.y + a2.y;
        acc.z += a1.z + a2.z; acc.w += a1.w + a2.w;
        float inv = 1.f / (den + d1 + d2);
        float4 b = ((const float4*)b2)[gl];
        float4 o;
        o.x = acc.x * inv + b.x;
        o.y = acc.y * inv + b.y;
        o.z = acc.z * inv + b.z;
        o.w = acc.w * inv + b.w;
        ((float4*)(out + (size_t)dst * F2))[gl] = o;
    }
}

// ============================================================================
extern "C" void kernel_launch(void* const* d_in, const int* in_sizes, int n_in,
                              void* d_out, int out_size) {
    const float* x   = (const float*)d_in[0];
    const int*   ei  = (const int*)d_in[1];   // int32 (JAX default-config downcast)
    const float* W1  = (const float*)d_in[2];
    const float* as1 = (const float*)d_in[3];
    const float* ad1 = (const float*)d_in[4];
    const float* b1  = (const float*)d_in[5];
    const float* W2  = (const float*)d_in[6];
    const float* as2 = (const float*)d_in[7];
    const float* ad2 = (const float*)d_in[8];
    const float* b2  = (const float*)d_in[9];
    float*       out = (float*)d_out;

    int N  = in_sizes[0] / DIM1;   // 100000
    int E  = in_sizes[1] / 2;      // 1600000

    // CSR build (shared by both layers)
    zero_cnt_kernel<<<(N + 255) / 256, 256>>>(N);
    hist_kernel    <<<(E + 255) / 256, 256>>>(ei, E);
    scan_kernel    <<<1, 1024>>>(N);
    scatter_kernel <<<(E + 255) / 256, 256>>>(ei, E);

    // layer 1
    gemm1_kernel<<<(N + 127) / 128, 256>>>(x, W1, as1, ad1, N);
    agg1_kernel <<<(N + 7) / 8, 256>>>(b1, N);

    // layer 2
    gemm2_kernel<<<(N + 31) / 32, 256>>>(W2, as2, ad2, N);
    agg2_kernel <<<(N + 7) / 8, 256>>>(b2, out, N);
}

// round 11
// speedup vs baseline: 2.2084x; 1.1153x over previous
#include <cuda_runtime.h>
#include <cstdint>

#define NN    100000
#define EMAX  1700000
#define DIM1  128
#define H1    4
#define F2    40

// ---------------- scratch (device globals: allocation-free) ----------------
__device__ float g_xw1[(size_t)NN * DIM1];   // layer1 x@W1        [N,128]
__device__ float g_h  [(size_t)NN * DIM1];   // layer1 activated   [N,128]
__device__ float g_asrc1[NN * H1];
__device__ float g_adst1[NN * H1];
__device__ float g_xw2[(size_t)NN * F2];     // layer2 h@W2        [N,40]
__device__ float g_asrc2[NN];
__device__ float g_adst2[NN];
__device__ int   g_cnt [NN];                 // per-dst degree
__device__ int   g_fill[NN];                 // scatter cursors
__device__ int   g_off [NN + 1];             // CSR offsets
__device__ int   g_srt [EMAX];               // src indices sorted by dst

__device__ __forceinline__ float leaky(float v) { return v > 0.f ? v : 0.2f * v; }

__device__ __forceinline__ uint32_t f2tf32(float f) {
    uint32_t r;
    asm("cvt.rna.tf32.f32 %0, %1;" : "=r"(r) : "f"(f));
    return r;
}
__device__ __forceinline__ void mma_tf32(float* d, uint32_t a0, uint32_t a1,
                                         uint32_t a2, uint32_t a3,
                                         uint32_t b0, uint32_t b1) {
    asm volatile(
        "mma.sync.aligned.m16n8k8.row.col.f32.tf32.tf32.f32 "
        "{%0,%1,%2,%3}, {%4,%5,%6,%7}, {%8,%9}, {%0,%1,%2,%3};"
        : "+f"(d[0]), "+f"(d[1]), "+f"(d[2]), "+f"(d[3])
        : "r"(a0), "r"(a1), "r"(a2), "r"(a3), "r"(b0), "r"(b1));
}

// ---------------- CSR build ---------------------------------------------------
__global__ void zero_cnt_kernel(int N) {
    int i = blockIdx.x * blockDim.x + threadIdx.x;
    if (i < N) { g_cnt[i] = 0; g_fill[i] = 0; }
}

__global__ void hist_kernel(const int* __restrict__ ei, int E) {
    int e = blockIdx.x * blockDim.x + threadIdx.x;
    if (e < E) atomicAdd(&g_cnt[__ldg(ei + E + e)], 1);
}

// single-block exclusive scan over g_cnt[0..NC) -> g_off
__global__ void scan_kernel(int NC) {
    __shared__ int wsum[32];
    int tid = threadIdx.x, lane = tid & 31, wid = tid >> 5;
    int carry = 0;
    for (int base = 0; base < NC; base += 1024) {
        int i = base + tid;
        int v = (i < NC) ? g_cnt[i] : 0;
        int s = v;
#pragma unroll
        for (int o = 1; o < 32; o <<= 1) {
            int t = __shfl_up_sync(0xffffffffu, s, o);
            if (lane >= o) s += t;
        }
        if (lane == 31) wsum[wid] = s;
        __syncthreads();
        if (wid == 0) {
            int ws = wsum[lane];
#pragma unroll
            for (int o = 1; o < 32; o <<= 1) {
                int t = __shfl_up_sync(0xffffffffu, ws, o);
                if (lane >= o) ws += t;
            }
            wsum[lane] = ws;
        }
        __syncthreads();
        int wexcl = (wid > 0) ? wsum[wid - 1] : 0;
        if (i < NC) g_off[i] = carry + wexcl + s - v;
        int total = wsum[31];
        __syncthreads();
        carry += total;
    }
    if (tid == 0) g_off[NC] = carry;
}

__global__ void scatter_kernel(const int* __restrict__ ei, int E) {
    int e = blockIdx.x * blockDim.x + threadIdx.x;
    if (e < E) {
        int src = __ldg(ei + e), dst = __ldg(ei + E + e);
        int pos = g_off[dst] + atomicAdd(&g_fill[dst], 1);
        g_srt[pos] = src;
    }
}

// ---------------- GEMM1 via tensor cores (3xTF32) + fused attention dots ----
__global__ __launch_bounds__(256) void gemm1_kernel(
    const float* __restrict__ x, const float* __restrict__ W,
    const float* __restrict__ att_s, const float* __restrict__ att_d, int N) {
    __shared__ uint32_t sAh[128][20], sAl[128][20];
    __shared__ uint32_t sBh[16][136], sBl[16][136];   // stride 136: banks 8*tig+g
    int rowBase = blockIdx.x * 128;
    int tid = threadIdx.x, warp = tid >> 5, lane = tid & 31;
    int g = lane >> 2, tig = lane & 3;
    int wrow = warp * 16;

    float acc[16][4];
#pragma unroll
    for (int j = 0; j < 16; ++j)
#pragma unroll
        for (int q = 0; q < 4; ++q) acc[j][q] = 0.f;

    for (int kc = 0; kc < 8; ++kc) {
        __syncthreads();
        for (int i = tid; i < 512; i += 256) {
            int r = i >> 2, q = i & 3;
            int row = rowBase + r;
            float4 v = (row < N)
                ? *((const float4*)(x + (size_t)row * 128 + kc * 16 + q * 4))
                : make_float4(0.f, 0.f, 0.f, 0.f);
            const float* vf = (const float*)&v;
#pragma unroll
            for (int t = 0; t < 4; ++t) {
                uint32_t h = f2tf32(vf[t]);
                sAh[r][q * 4 + t] = h;
                sAl[r][q * 4 + t] = f2tf32(vf[t] - __uint_as_float(h));
            }
        }
        for (int i = tid; i < 512; i += 256) {
            int k = i >> 5, q = i & 31;
            float4 v = *((const float4*)(W + (size_t)(kc * 16 + k) * 128 + q * 4));
            const float* vf = (const float*)&v;
#pragma unroll
            for (int t = 0; t < 4; ++t) {
                uint32_t h = f2tf32(vf[t]);
                sBh[k][q * 4 + t] = h;
                sBl[k][q * 4 + t] = f2tf32(vf[t] - __uint_as_float(h));
            }
        }
        __syncthreads();
#pragma unroll
        for (int ks = 0; ks < 2; ++ks) {
            int k0 = ks * 8;
            uint32_t ah0 = sAh[wrow + g][k0 + tig];
            uint32_t ah1 = sAh[wrow + g + 8][k0 + tig];
            uint32_t ah2 = sAh[wrow + g][k0 + tig + 4];
            uint32_t ah3 = sAh[wrow + g + 8][k0 + tig + 4];
            uint32_t al0 = sAl[wrow + g][k0 + tig];
            uint32_t al1 = sAl[wrow + g + 8][k0 + tig];
            uint32_t al2 = sAl[wrow + g][k0 + tig + 4];
            uint32_t al3 = sAl[wrow + g + 8][k0 + tig + 4];
#pragma unroll
            for (int j = 0; j < 16; ++j) {
                int n0 = j * 8;
                uint32_t bh0 = sBh[k0 + tig][n0 + g];
                uint32_t bh1 = sBh[k0 + tig + 4][n0 + g];
                uint32_t bl0 = sBl[k0 + tig][n0 + g];
                uint32_t bl1 = sBl[k0 + tig + 4][n0 + g];
                mma_tf32(acc[j], ah0, ah1, ah2, ah3, bh0, bh1);
                mma_tf32(acc[j], ah0, ah1, ah2, ah3, bl0, bl1);
                mma_tf32(acc[j], al0, al1, al2, al3, bh0, bh1);
            }
        }
    }
    int row0 = rowBase + wrow + g, row1 = row0 + 8;
    float ps0[4] = {0,0,0,0}, pd0[4] = {0,0,0,0};
    float ps1[4] = {0,0,0,0}, pd1[4] = {0,0,0,0};
#pragma unroll
    for (int j = 0; j < 16; ++j) {
        int col = j * 8 + tig * 2;
        int head = j >> 2;
        float a0 = att_s[col], a1 = att_s[col + 1];
        float d0 = att_d[col], d1 = att_d[col + 1];
        ps0[head] += acc[j][0] * a0 + acc[j][1] * a1;
        pd0[head] += acc[j][0] * d0 + acc[j][1] * d1;
        ps1[head] += acc[j][2] * a0 + acc[j][3] * a1;
        pd1[head] += acc[j][2] * d0 + acc[j][3] * d1;
        if (row0 < N)
            *(float2*)(g_xw1 + (size_t)row0 * 128 + col) = make_float2(acc[j][0], acc[j][1]);
        if (row1 < N)
            *(float2*)(g_xw1 + (size_t)row1 * 128 + col) = make_float2(acc[j][2], acc[j][3]);
    }
#pragma unroll
    for (int h = 0; h < 4; ++h) {
#pragma unroll
        for (int o = 1; o < 4; o <<= 1) {
            ps0[h] += __shfl_xor_sync(0xffffffffu, ps0[h], o);
            pd0[h] += __shfl_xor_sync(0xffffffffu, pd0[h], o);
            ps1[h] += __shfl_xor_sync(0xffffffffu, ps1[h], o);
            pd1[h] += __shfl_xor_sync(0xffffffffu, pd1[h], o);
        }
    }
    if (tig == 0) {
        if (row0 < N) {
            *(float4*)(g_asrc1 + row0 * 4) = make_float4(ps0[0], ps0[1], ps0[2], ps0[3]);
            *(float4*)(g_adst1 + row0 * 4) = make_float4(pd0[0], pd0[1], pd0[2], pd0[3]);
        }
        if (row1 < N) {
            *(float4*)(g_asrc1 + row1 * 4) = make_float4(ps1[0], ps1[1], ps1[2], ps1[3]);
            *(float4*)(g_adst1 + row1 * 4) = make_float4(pd1[0], pd1[1], pd1[2], pd1[3]);
        }
    }
}

// ---------------- layer1 CSR aggregate: warp per dst, unroll-2 ---------------
__global__ void agg1_kernel(const float* __restrict__ b1, int N) {
    int dst = blockIdx.x * 8 + (threadIdx.x >> 5);
    int lane = threadIdx.x & 31;
    if (dst >= N) return;
    int head = lane >> 3;
    float adst = g_adst1[dst * 4 + head];
    float ex = __expf(leaky(g_asrc1[dst * 4 + head] + adst));   // self-loop
    float4 acc = ((const float4*)(g_xw1 + (size_t)dst * 128))[lane];
    acc.x *= ex; acc.y *= ex; acc.z *= ex; acc.w *= ex;
    float den = ex;
    float4 acc2 = make_float4(0.f, 0.f, 0.f, 0.f);
    float den2 = 0.f;
    int start = g_off[dst], end = g_off[dst + 1];
    int i = start;
    for (; i + 1 < end; i += 2) {
        int s0 = g_srt[i], s1 = g_srt[i + 1];
        float e0 = __expf(leaky(g_asrc1[s0 * 4 + head] + adst));
        float e1 = __expf(leaky(g_asrc1[s1 * 4 + head] + adst));
        float4 v0 = ((const float4*)(g_xw1 + (size_t)s0 * 128))[lane];
        float4 v1 = ((const float4*)(g_xw1 + (size_t)s1 * 128))[lane];
        acc.x  += v0.x * e0; acc.y  += v0.y * e0; acc.z  += v0.z * e0; acc.w  += v0.w * e0;
        acc2.x += v1.x * e1; acc2.y += v1.y * e1; acc2.z += v1.z * e1; acc2.w += v1.w * e1;
        den += e0; den2 += e1;
    }
    if (i < end) {
        int s0 = g_srt[i];
        float e0 = __expf(leaky(g_asrc1[s0 * 4 + head] + adst));
        float4 v0 = ((const float4*)(g_xw1 + (size_t)s0 * 128))[lane];
        acc.x += v0.x * e0; acc.y += v0.y * e0; acc.z += v0.z * e0; acc.w += v0.w * e0;
        den += e0;
    }
    acc.x += acc2.x; acc.y += acc2.y; acc.z += acc2.z; acc.w += acc2.w;
    den += den2;
    float inv = 1.f / den;
    float4 b = ((const float4*)b1)[lane];
    float4 o;
    o.x = fmaxf(acc.x * inv + b.x, 0.f);
    o.y = fmaxf(acc.y * inv + b.y, 0.f);
    o.z = fmaxf(acc.z * inv + b.z, 0.f);
    o.w = fmaxf(acc.w * inv + b.w, 0.f);
    ((float4*)(g_h + (size_t)dst * 128))[lane] = o;
}

// ---------------- GEMM2 via tensor cores (3xTF32) + att2 dots ----------------
// 128 rows/block, 8 warps x 16 rows; N=40 = 5 n-tiles; K=128 in 8 chunks.
__global__ __launch_bounds__(256) void gemm2_kernel(
    const float* __restrict__ W2,
    const float* __restrict__ att_s, const float* __restrict__ att_d, int N) {
    __shared__ uint32_t sAh[128][20], sAl[128][20];
    __shared__ uint32_t sBh[16][40], sBl[16][40];   // stride 40: banks 8*tig+g
    int rowBase = blockIdx.x * 128;
    int tid = threadIdx.x, warp = tid >> 5, lane = tid & 31;
    int g = lane >> 2, tig = lane & 3;
    int wrow = warp * 16;

    float acc[5][4];
#pragma unroll
    for (int j = 0; j < 5; ++j)
#pragma unroll
        for (int q = 0; q < 4; ++q) acc[j][q] = 0.f;

    for (int kc = 0; kc < 8; ++kc) {
        __syncthreads();
        // A tile from activated g_h
        for (int i = tid; i < 512; i += 256) {
            int r = i >> 2, q = i & 3;
            int row = rowBase + r;
            float4 v = (row < N)
                ? *((const float4*)(g_h + (size_t)row * 128 + kc * 16 + q * 4))
                : make_float4(0.f, 0.f, 0.f, 0.f);
            const float* vf = (const float*)&v;
#pragma unroll
            for (int t = 0; t < 4; ++t) {
                uint32_t h = f2tf32(vf[t]);
                sAh[r][q * 4 + t] = h;
                sAl[r][q * 4 + t] = f2tf32(vf[t] - __uint_as_float(h));
            }
        }
        // B tile: 16 k x 40 cols = 160 float4
        for (int i = tid; i < 160; i += 256) {
            int k = i / 10, q = i - (i / 10) * 10;
            float4 v = *((const float4*)(W2 + (size_t)(kc * 16 + k) * 40 + q * 4));
            const float* vf = (const float*)&v;
#pragma unroll
            for (int t = 0; t < 4; ++t) {
                uint32_t h = f2tf32(vf[t]);
                sBh[k][q * 4 + t] = h;
                sBl[k][q * 4 + t] = f2tf32(vf[t] - __uint_as_float(h));
            }
        }
        __syncthreads();
#pragma unroll
        for (int ks = 0; ks < 2; ++ks) {
            int k0 = ks * 8;
            uint32_t ah0 = sAh[wrow + g][k0 + tig];
            uint32_t ah1 = sAh[wrow + g + 8][k0 + tig];
            uint32_t ah2 = sAh[wrow + g][k0 + tig + 4];
            uint32_t ah3 = sAh[wrow + g + 8][k0 + tig + 4];
            uint32_t al0 = sAl[wrow + g][k0 + tig];
            uint32_t al1 = sAl[wrow + g + 8][k0 + tig];
            uint32_t al2 = sAl[wrow + g][k0 + tig + 4];
            uint32_t al3 = sAl[wrow + g + 8][k0 + tig + 4];
#pragma unroll
            for (int j = 0; j < 5; ++j) {
                int n0 = j * 8;
                uint32_t bh0 = sBh[k0 + tig][n0 + g];
                uint32_t bh1 = sBh[k0 + tig + 4][n0 + g];
                uint32_t bl0 = sBl[k0 + tig][n0 + g];
                uint32_t bl1 = sBl[k0 + tig + 4][n0 + g];
                mma_tf32(acc[j], ah0, ah1, ah2, ah3, bh0, bh1);
                mma_tf32(acc[j], ah0, ah1, ah2, ah3, bl0, bl1);
                mma_tf32(acc[j], al0, al1, al2, al3, bh0, bh1);
            }
        }
    }
    int row0 = rowBase + wrow + g, row1 = row0 + 8;
    float ps0 = 0.f, pd0 = 0.f, ps1 = 0.f, pd1 = 0.f;
#pragma unroll
    for (int j = 0; j < 5; ++j) {
        int col = j * 8 + tig * 2;
        float a0 = att_s[col], a1 = att_s[col + 1];
        float d0 = att_d[col], d1 = att_d[col + 1];
        ps0 += acc[j][0] * a0 + acc[j][1] * a1;
        pd0 += acc[j][0] * d0 + acc[j][1] * d1;
        ps1 += acc[j][2] * a0 + acc[j][3] * a1;
        pd1 += acc[j][2] * d0 + acc[j][3] * d1;
        if (row0 < N)
            *(float2*)(g_xw2 + (size_t)row0 * F2 + col) = make_float2(acc[j][0], acc[j][1]);
        if (row1 < N)
            *(float2*)(g_xw2 + (size_t)row1 * F2 + col) = make_float2(acc[j][2], acc[j][3]);
    }
#pragma unroll
    for (int o = 1; o < 4; o <<= 1) {
        ps0 += __shfl_xor_sync(0xffffffffu, ps0, o);
        pd0 += __shfl_xor_sync(0xffffffffu, pd0, o);
        ps1 += __shfl_xor_sync(0xffffffffu, ps1, o);
        pd1 += __shfl_xor_sync(0xffffffffu, pd1, o);
    }
    if (tig == 0) {
        if (row0 < N) { g_asrc2[row0] = ps0; g_adst2[row0] = pd0; }
        if (row1 < N) { g_asrc2[row1] = ps1; g_adst2[row1] = pd1; }
    }
}

// ---------------- layer2 CSR aggregate: warp per dst, 3 edge-groups ----------
__global__ void agg2_kernel(const float* __restrict__ b2,
                            float* __restrict__ out, int N) {
    int dst = blockIdx.x * 8 + (threadIdx.x >> 5);
    int lane = threadIdx.x & 31;
    if (dst >= N) return;
    int grp = lane / 10, gl = lane - grp * 10;   // grp 3 = lanes 30,31 idle
    float adst = g_adst2[dst];
    float4 acc = make_float4(0.f, 0.f, 0.f, 0.f);
    float den = 0.f;
    if (grp == 0) {      // self-loop in group 0
        float ex = __expf(leaky(g_asrc2[dst] + adst));
        float4 v = ((const float4*)(g_xw2 + (size_t)dst * F2))[gl];
        acc.x = v.x * ex; acc.y = v.y * ex; acc.z = v.z * ex; acc.w = v.w * ex;
        den = ex;
    }
    int start = g_off[dst], end = g_off[dst + 1];
    if (grp < 3) {
        for (int i = start + grp; i < end; i += 3) {
            int src = g_srt[i];
            float ex = __expf(leaky(g_asrc2[src] + adst));
            float4 v = ((const float4*)(g_xw2 + (size_t)src * F2))[gl];
            acc.x += v.x * ex; acc.y += v.y * ex;
            acc.z += v.z * ex; acc.w += v.w * ex;
            den += ex;
        }
    }
    float4 a1, a2;
    a1.x = __shfl_sync(0xffffffffu, acc.x, lane + 10);
    a1.y = __shfl_sync(0xffffffffu, acc.y, lane + 10);
    a1.z = __shfl_sync(0xffffffffu, acc.z, lane + 10);
    a1.w = __shfl_sync(0xffffffffu, acc.w, lane + 10);
    a2.x = __shfl_sync(0xffffffffu, acc.x, lane + 20);
    a2.y = __shfl_sync(0xffffffffu, acc.y, lane + 20);
    a2.z = __shfl_sync(0xffffffffu, acc.z, lane + 20);
    a2.w = __shfl_sync(0xffffffffu, acc.w, lane + 20);
    float d1 = __shfl_sync(0xffffffffu, den, lane + 10);
    float d2 = __shfl_sync(0xffffffffu, den, lane + 20);
    if (grp == 0) {
        acc.x += a1.x + a2.x; acc.y += a1.y + a2.y;
        acc.z += a1.z + a2.z; acc.w += a1.w + a2.w;
        float inv = 1.f / (den + d1 + d2);
        float4 b = ((const float4*)b2)[gl];
        float4 o;
        o.x = acc.x * inv + b.x;
        o.y = acc.y * inv + b.y;
        o.z = acc.z * inv + b.z;
        o.w = acc.w * inv + b.w;
        ((float4*)(out + (size_t)dst * F2))[gl] = o;
    }
}

// ============================================================================
extern "C" void kernel_launch(void* const* d_in, const int* in_sizes, int n_in,
                              void* d_out, int out_size) {
    const float* x   = (const float*)d_in[0];
    const int*   ei  = (const int*)d_in[1];   // int32 (JAX default-config downcast)
    const float* W1  = (const float*)d_in[2];
    const float* as1 = (const float*)d_in[3];
    const float* ad1 = (const float*)d_in[4];
    const float* b1  = (const float*)d_in[5];
    const float* W2  = (const float*)d_in[6];
    const float* as2 = (const float*)d_in[7];
    const float* ad2 = (const float*)d_in[8];
    const float* b2  = (const float*)d_in[9];
    float*       out = (float*)d_out;

    int N  = in_sizes[0] / DIM1;   // 100000
    int E  = in_sizes[1] / 2;      // 1600000

    // CSR build (shared by both layers)
    zero_cnt_kernel<<<(N + 255) / 256, 256>>>(N);
    hist_kernel    <<<(E + 255) / 256, 256>>>(ei, E);
    scan_kernel    <<<1, 1024>>>(N);
    scatter_kernel <<<(E + 255) / 256, 256>>>(ei, E);

    // layer 1
    gemm1_kernel<<<(N + 127) / 128, 256>>>(x, W1, as1, ad1, N);
    agg1_kernel <<<(N + 7) / 8, 256>>>(b1, N);

    // layer 2
    gemm2_kernel<<<(N + 127) / 128, 256>>>(W2, as2, ad2, N);
    agg2_kernel <<<(N + 7) / 8, 256>>>(b2, out, N);
}

// round 12
// speedup vs baseline: 2.3605x; 1.0689x over previous
#include <cuda_runtime.h>
#include <cuda_fp16.h>
#include <cstdint>

#define NN    100000
#define EMAX  1700000
#define DIM1  128
#define H1    4
#define F2    40

// ---------------- scratch (device globals: allocation-free) ----------------
__device__ __half g_xw1h[(size_t)NN * DIM1]; // layer1 x@W1 (fp16)  [N,128]
__device__ float g_h  [(size_t)NN * DIM1];   // layer1 activated    [N,128]
__device__ float g_asrc1[NN * H1];
__device__ float g_adst1[NN * H1];
__device__ float g_xw2[(size_t)NN * F2];     // layer2 h@W2         [N,40]
__device__ float g_asrc2[NN];
__device__ float g_adst2[NN];
__device__ int   g_cnt [NN];                 // per-dst degree
__device__ int   g_fill[NN];                 // scatter cursors (init by scan)
__device__ int   g_off [NN + 1];             // CSR offsets
__device__ int   g_srt [EMAX];               // src indices sorted by dst

__device__ __forceinline__ float leaky(float v) { return v > 0.f ? v : 0.2f * v; }

__device__ __forceinline__ uint32_t f2tf32(float f) {
    uint32_t r;
    asm("cvt.rna.tf32.f32 %0, %1;" : "=r"(r) : "f"(f));
    return r;
}
__device__ __forceinline__ void mma_tf32(float* d, uint32_t a0, uint32_t a1,
                                         uint32_t a2, uint32_t a3,
                                         uint32_t b0, uint32_t b1) {
    asm volatile(
        "mma.sync.aligned.m16n8k8.row.col.f32.tf32.tf32.f32 "
        "{%0,%1,%2,%3}, {%4,%5,%6,%7}, {%8,%9}, {%0,%1,%2,%3};"
        : "+f"(d[0]), "+f"(d[1]), "+f"(d[2]), "+f"(d[3])
        : "r"(a0), "r"(a1), "r"(a2), "r"(a3), "r"(b0), "r"(b1));
}

// ---------------- CSR build ---------------------------------------------------
__global__ void zero_cnt_kernel(int N) {
    int i = blockIdx.x * blockDim.x + threadIdx.x;
    if (i < N) g_cnt[i] = 0;
}

__global__ void hist_kernel(const int* __restrict__ ei, int E) {
    int e = blockIdx.x * blockDim.x + threadIdx.x;
    if (e < E) atomicAdd(&g_cnt[__ldg(ei + E + e)], 1);
}

// single-block exclusive scan over g_cnt -> g_off; also seeds g_fill cursors
__global__ void scan_kernel(int NC) {
    __shared__ int wsum[32];
    int tid = threadIdx.x, lane = tid & 31, wid = tid >> 5;
    int carry = 0;
    for (int base = 0; base < NC; base += 1024) {
        int i = base + tid;
        int v = (i < NC) ? g_cnt[i] : 0;
        int s = v;
#pragma unroll
        for (int o = 1; o < 32; o <<= 1) {
            int t = __shfl_up_sync(0xffffffffu, s, o);
            if (lane >= o) s += t;
        }
        if (lane == 31) wsum[wid] = s;
        __syncthreads();
        if (wid == 0) {
            int ws = wsum[lane];
#pragma unroll
            for (int o = 1; o < 32; o <<= 1) {
                int t = __shfl_up_sync(0xffffffffu, ws, o);
                if (lane >= o) ws += t;
            }
            wsum[lane] = ws;
        }
        __syncthreads();
        int wexcl = (wid > 0) ? wsum[wid - 1] : 0;
        if (i < NC) {
            int off = carry + wexcl + s - v;
            g_off[i] = off;
            g_fill[i] = off;
        }
        int total = wsum[31];
        __syncthreads();
        carry += total;
    }
    if (tid == 0) g_off[NC] = carry;
}

__global__ void scatter_kernel(const int* __restrict__ ei, int E) {
    int e = blockIdx.x * blockDim.x + threadIdx.x;
    if (e < E) {
        int src = __ldg(ei + e), dst = __ldg(ei + E + e);
        int pos = atomicAdd(&g_fill[dst], 1);
        g_srt[pos] = src;
    }
}

// ---------------- GEMM1 via tensor cores (3xTF32) + fused attention dots ----
__global__ __launch_bounds__(256) void gemm1_kernel(
    const float* __restrict__ x, const float* __restrict__ W,
    const float* __restrict__ att_s, const float* __restrict__ att_d, int N) {
    __shared__ uint32_t sAh[128][20], sAl[128][20];
    __shared__ uint32_t sBh[16][136], sBl[16][136];   // stride 136: banks 8*tig+g
    int rowBase = blockIdx.x * 128;
    int tid = threadIdx.x, warp = tid >> 5, lane = tid & 31;
    int g = lane >> 2, tig = lane & 3;
    int wrow = warp * 16;

    float acc[16][4];
#pragma unroll
    for (int j = 0; j < 16; ++j)
#pragma unroll
        for (int q = 0; q < 4; ++q) acc[j][q] = 0.f;

    for (int kc = 0; kc < 8; ++kc) {
        __syncthreads();
        for (int i = tid; i < 512; i += 256) {
            int r = i >> 2, q = i & 3;
            int row = rowBase + r;
            float4 v = (row < N)
                ? *((const float4*)(x + (size_t)row * 128 + kc * 16 + q * 4))
                : make_float4(0.f, 0.f, 0.f, 0.f);
            const float* vf = (const float*)&v;
#pragma unroll
            for (int t = 0; t < 4; ++t) {
                uint32_t h = f2tf32(vf[t]);
                sAh[r][q * 4 + t] = h;
                sAl[r][q * 4 + t] = f2tf32(vf[t] - __uint_as_float(h));
            }
        }
        for (int i = tid; i < 512; i += 256) {
            int k = i >> 5, q = i & 31;
            float4 v = *((const float4*)(W + (size_t)(kc * 16 + k) * 128 + q * 4));
            const float* vf = (const float*)&v;
#pragma unroll
            for (int t = 0; t < 4; ++t) {
                uint32_t h = f2tf32(vf[t]);
                sBh[k][q * 4 + t] = h;
                sBl[k][q * 4 + t] = f2tf32(vf[t] - __uint_as_float(h));
            }
        }
        __syncthreads();
#pragma unroll
        for (int ks = 0; ks < 2; ++ks) {
            int k0 = ks * 8;
            uint32_t ah0 = sAh[wrow + g][k0 + tig];
            uint32_t ah1 = sAh[wrow + g + 8][k0 + tig];
            uint32_t ah2 = sAh[wrow + g][k0 + tig + 4];
            uint32_t ah3 = sAh[wrow + g + 8][k0 + tig + 4];
            uint32_t al0 = sAl[wrow + g][k0 + tig];
            uint32_t al1 = sAl[wrow + g + 8][k0 + tig];
            uint32_t al2 = sAl[wrow + g][k0 + tig + 4];
            uint32_t al3 = sAl[wrow + g + 8][k0 + tig + 4];
#pragma unroll
            for (int j = 0; j < 16; ++j) {
                int n0 = j * 8;
                uint32_t bh0 = sBh[k0 + tig][n0 + g];
                uint32_t bh1 = sBh[k0 + tig + 4][n0 + g];
                uint32_t bl0 = sBl[k0 + tig][n0 + g];
                uint32_t bl1 = sBl[k0 + tig + 4][n0 + g];
                mma_tf32(acc[j], ah0, ah1, ah2, ah3, bh0, bh1);
                mma_tf32(acc[j], ah0, ah1, ah2, ah3, bl0, bl1);
                mma_tf32(acc[j], al0, al1, al2, al3, bh0, bh1);
            }
        }
    }
    int row0 = rowBase + wrow + g, row1 = row0 + 8;
    float ps0[4] = {0,0,0,0}, pd0[4] = {0,0,0,0};
    float ps1[4] = {0,0,0,0}, pd1[4] = {0,0,0,0};
#pragma unroll
    for (int j = 0; j < 16; ++j) {
        int col = j * 8 + tig * 2;
        int head = j >> 2;
        float a0 = att_s[col], a1 = att_s[col + 1];
        float d0 = att_d[col], d1 = att_d[col + 1];
        ps0[head] += acc[j][0] * a0 + acc[j][1] * a1;
        pd0[head] += acc[j][0] * d0 + acc[j][1] * d1;
        ps1[head] += acc[j][2] * a0 + acc[j][3] * a1;
        pd1[head] += acc[j][2] * d0 + acc[j][3] * d1;
        if (row0 < N)
            *(__half2*)(g_xw1h + (size_t)row0 * 128 + col) =
                __floats2half2_rn(acc[j][0], acc[j][1]);
        if (row1 < N)
            *(__half2*)(g_xw1h + (size_t)row1 * 128 + col) =
                __floats2half2_rn(acc[j][2], acc[j][3]);
    }
#pragma unroll
    for (int h = 0; h < 4; ++h) {
#pragma unroll
        for (int o = 1; o < 4; o <<= 1) {
            ps0[h] += __shfl_xor_sync(0xffffffffu, ps0[h], o);
            pd0[h] += __shfl_xor_sync(0xffffffffu, pd0[h], o);
            ps1[h] += __shfl_xor_sync(0xffffffffu, ps1[h], o);
            pd1[h] += __shfl_xor_sync(0xffffffffu, pd1[h], o);
        }
    }
    if (tig == 0) {
        if (row0 < N) {
            *(float4*)(g_asrc1 + row0 * 4) = make_float4(ps0[0], ps0[1], ps0[2], ps0[3]);
            *(float4*)(g_adst1 + row0 * 4) = make_float4(pd0[0], pd0[1], pd0[2], pd0[3]);
        }
        if (row1 < N) {
            *(float4*)(g_asrc1 + row1 * 4) = make_float4(ps1[0], ps1[1], ps1[2], ps1[3]);
            *(float4*)(g_adst1 + row1 * 4) = make_float4(pd1[0], pd1[1], pd1[2], pd1[3]);
        }
    }
}

// ---------------- layer1 CSR aggregate: warp per dst, fp16 gather, unroll-2 --
__global__ void agg1_kernel(const float* __restrict__ b1, int N) {
    int dst = blockIdx.x * 8 + (threadIdx.x >> 5);
    int lane = threadIdx.x & 31;
    if (dst >= N) return;
    int head = lane >> 3;
    float adst = g_adst1[dst * 4 + head];
    float ex = __expf(leaky(g_asrc1[dst * 4 + head] + adst));   // self-loop
    uint2 ps = *(const uint2*)(g_xw1h + (size_t)dst * 128 + lane * 4);
    float2 s01 = __half22float2(*(__half2*)&ps.x);
    float2 s23 = __half22float2(*(__half2*)&ps.y);
    float4 acc = make_float4(s01.x * ex, s01.y * ex, s23.x * ex, s23.y * ex);
    float den = ex;
    float4 acc2 = make_float4(0.f, 0.f, 0.f, 0.f);
    float den2 = 0.f;
    int start = g_off[dst], end = g_off[dst + 1];
    int i = start;
    for (; i + 1 < end; i += 2) {
        int s0 = g_srt[i], s1 = g_srt[i + 1];
        float e0 = __expf(leaky(g_asrc1[s0 * 4 + head] + adst));
        float e1 = __expf(leaky(g_asrc1[s1 * 4 + head] + adst));
        uint2 p0 = *(const uint2*)(g_xw1h + (size_t)s0 * 128 + lane * 4);
        uint2 p1 = *(const uint2*)(g_xw1h + (size_t)s1 * 128 + lane * 4);
        float2 a01 = __half22float2(*(__half2*)&p0.x);
        float2 a23 = __half22float2(*(__half2*)&p0.y);
        float2 b01 = __half22float2(*(__half2*)&p1.x);
        float2 b23 = __half22float2(*(__half2*)&p1.y);
        acc.x  += a01.x * e0; acc.y  += a01.y * e0; acc.z  += a23.x * e0; acc.w  += a23.y * e0;
        acc2.x += b01.x * e1; acc2.y += b01.y * e1; acc2.z += b23.x * e1; acc2.w += b23.y * e1;
        den += e0; den2 += e1;
    }
    if (i < end) {
        int s0 = g_srt[i];
        float e0 = __expf(leaky(g_asrc1[s0 * 4 + head] + adst));
        uint2 p0 = *(const uint2*)(g_xw1h + (size_t)s0 * 128 + lane * 4);
        float2 a01 = __half22float2(*(__half2*)&p0.x);
        float2 a23 = __half22float2(*(__half2*)&p0.y);
        acc.x += a01.x * e0; acc.y += a01.y * e0; acc.z += a23.x * e0; acc.w += a23.y * e0;
        den += e0;
    }
    acc.x += acc2.x; acc.y += acc2.y; acc.z += acc2.z; acc.w += acc2.w;
    den += den2;
    float inv = 1.f / den;
    float4 b = ((const float4*)b1)[lane];
    float4 o;
    o.x = fmaxf(acc.x * inv + b.x, 0.f);
    o.y = fmaxf(acc.y * inv + b.y, 0.f);
    o.z = fmaxf(acc.z * inv + b.z, 0.f);
    o.w = fmaxf(acc.w * inv + b.w, 0.f);
    ((float4*)(g_h + (size_t)dst * 128))[lane] = o;
}

// ---------------- GEMM2 via tensor cores (3xTF32) + att2 dots ----------------
__global__ __launch_bounds__(256) void gemm2_kernel(
    const float* __restrict__ W2,
    const float* __restrict__ att_s, const float* __restrict__ att_d, int N) {
    __shared__ uint32_t sAh[128][20], sAl[128][20];
    __shared__ uint32_t sBh[16][40], sBl[16][40];   // stride 40: banks 8*tig+g
    int rowBase = blockIdx.x * 128;
    int tid = threadIdx.x, warp = tid >> 5, lane = tid & 31;
    int g = lane >> 2, tig = lane & 3;
    int wrow = warp * 16;

    float acc[5][4];
#pragma unroll
    for (int j = 0; j < 5; ++j)
#pragma unroll
        for (int q = 0; q < 4; ++q) acc[j][q] = 0.f;

    for (int kc = 0; kc < 8; ++kc) {
        __syncthreads();
        for (int i = tid; i < 512; i += 256) {
            int r = i >> 2, q = i & 3;
            int row = rowBase + r;
            float4 v = (row < N)
                ? *((const float4*)(g_h + (size_t)row * 128 + kc * 16 + q * 4))
                : make_float4(0.f, 0.f, 0.f, 0.f);
            const float* vf = (const float*)&v;
#pragma unroll
            for (int t = 0; t < 4; ++t) {
                uint32_t h = f2tf32(vf[t]);
                sAh[r][q * 4 + t] = h;
                sAl[r][q * 4 + t] = f2tf32(vf[t] - __uint_as_float(h));
            }
        }
        for (int i = tid; i < 160; i += 256) {
            int k = i / 10, q = i - (i / 10) * 10;
            float4 v = *((const float4*)(W2 + (size_t)(kc * 16 + k) * 40 + q * 4));
            const float* vf = (const float*)&v;
#pragma unroll
            for (int t = 0; t < 4; ++t) {
                uint32_t h = f2tf32(vf[t]);
                sBh[k][q * 4 + t] = h;
                sBl[k][q * 4 + t] = f2tf32(vf[t] - __uint_as_float(h));
            }
        }
        __syncthreads();
#pragma unroll
        for (int ks = 0; ks < 2; ++ks) {
            int k0 = ks * 8;
            uint32_t ah0 = sAh[wrow + g][k0 + tig];
            uint32_t ah1 = sAh[wrow + g + 8][k0 + tig];
            uint32_t ah2 = sAh[wrow + g][k0 + tig + 4];
            uint32_t ah3 = sAh[wrow + g + 8][k0 + tig + 4];
            uint32_t al0 = sAl[wrow + g][k0 + tig];
            uint32_t al1 = sAl[wrow + g + 8][k0 + tig];
            uint32_t al2 = sAl[wrow + g][k0 + tig + 4];
            uint32_t al3 = sAl[wrow + g + 8][k0 + tig + 4];
#pragma unroll
            for (int j = 0; j < 5; ++j) {
                int n0 = j * 8;
                uint32_t bh0 = sBh[k0 + tig][n0 + g];
                uint32_t bh1 = sBh[k0 + tig + 4][n0 + g];
                uint32_t bl0 = sBl[k0 + tig][n0 + g];
                uint32_t bl1 = sBl[k0 + tig + 4][n0 + g];
                mma_tf32(acc[j], ah0, ah1, ah2, ah3, bh0, bh1);
                mma_tf32(acc[j], ah0, ah1, ah2, ah3, bl0, bl1);
                mma_tf32(acc[j], al0, al1, al2, al3, bh0, bh1);
            }
        }
    }
    int row0 = rowBase + wrow + g, row1 = row0 + 8;
    float ps0 = 0.f, pd0 = 0.f, ps1 = 0.f, pd1 = 0.f;
#pragma unroll
    for (int j = 0; j < 5; ++j) {
        int col = j * 8 + tig * 2;
        float a0 = att_s[col], a1 = att_s[col + 1];
        float d0 = att_d[col], d1 = att_d[col + 1];
        ps0 += acc[j][0] * a0 + acc[j][1] * a1;
        pd0 += acc[j][0] * d0 + acc[j][1] * d1;
        ps1 += acc[j][2] * a0 + acc[j][3] * a1;
        pd1 += acc[j][2] * d0 + acc[j][3] * d1;
        if (row0 < N)
            *(float2*)(g_xw2 + (size_t)row0 * F2 + col) = make_float2(acc[j][0], acc[j][1]);
        if (row1 < N)
            *(float2*)(g_xw2 + (size_t)row1 * F2 + col) = make_float2(acc[j][2], acc[j][3]);
    }
#pragma unroll
    for (int o = 1; o < 4; o <<= 1) {
        ps0 += __shfl_xor_sync(0xffffffffu, ps0, o);
        pd0 += __shfl_xor_sync(0xffffffffu, pd0, o);
        ps1 += __shfl_xor_sync(0xffffffffu, ps1, o);
        pd1 += __shfl_xor_sync(0xffffffffu, pd1, o);
    }
    if (tig == 0) {
        if (row0 < N) { g_asrc2[row0] = ps0; g_adst2[row0] = pd0; }
        if (row1 < N) { g_asrc2[row1] = ps1; g_adst2[row1] = pd1; }
    }
}

// ---------------- layer2 CSR aggregate: warp per dst, 3 edge-groups ----------
__global__ void agg2_kernel(const float* __restrict__ b2,
                            float* __restrict__ out, int N) {
    int dst = blockIdx.x * 8 + (threadIdx.x >> 5);
    int lane = threadIdx.x & 31;
    if (dst >= N) return;
    int grp = lane / 10, gl = lane - grp * 10;   // grp 3 = lanes 30,31 idle
    float adst = g_adst2[dst];
    float4 acc = make_float4(0.f, 0.f, 0.f, 0.f);
    float den = 0.f;
    if (grp == 0) {      // self-loop in group 0
        float ex = __expf(leaky(g_asrc2[dst] + adst));
        float4 v = ((const float4*)(g_xw2 + (size_t)dst * F2))[gl];
        acc.x = v.x * ex; acc.y = v.y * ex; acc.z = v.z * ex; acc.w = v.w * ex;
        den = ex;
    }
    int start = g_off[dst], end = g_off[dst + 1];
    if (grp < 3) {
        for (int i = start + grp; i < end; i += 3) {
            int src = g_srt[i];
            float ex = __expf(leaky(g_asrc2[src] + adst));
            float4 v = ((const float4*)(g_xw2 + (size_t)src * F2))[gl];
            acc.x += v.x * ex; acc.y += v.y * ex;
            acc.z += v.z * ex; acc.w += v.w * ex;
            den += ex;
        }
    }
    float4 a1, a2;
    a1.x = __shfl_sync(0xffffffffu, acc.x, lane + 10);
    a1.y = __shfl_sync(0xffffffffu, acc.y, lane + 10);
    a1.z = __shfl_sync(0xffffffffu, acc.z, lane + 10);
    a1.w = __shfl_sync(0xffffffffu, acc.w, lane + 10);
    a2.x = __shfl_sync(0xffffffffu, acc.x, lane + 20);
    a2.y = __shfl_sync(0xffffffffu, acc.y, lane + 20);
    a2.z = __shfl_sync(0xffffffffu, acc.z, lane + 20);
    a2.w = __shfl_sync(0xffffffffu, acc.w, lane + 20);
    float d1 = __shfl_sync(0xffffffffu, den, lane + 10);
    float d2 = __shfl_sync(0xffffffffu, den, lane + 20);
    if (grp == 0) {
        acc.x += a1.x + a2.x; acc.y += a1.y + a2.y;
        acc.z += a1.z + a2.z; acc.w += a1.w + a2.w;
        float inv = 1.f / (den + d1 + d2);
        float4 b = ((const float4*)b2)[gl];
        float4 o;
        o.x = acc.x * inv + b.x;
        o.y = acc.y * inv + b.y;
        o.z = acc.z * inv + b.z;
        o.w = acc.w * inv + b.w;
        ((float4*)(out + (size_t)dst * F2))[gl] = o;
    }
}

// ============================================================================
extern "C" void kernel_launch(void* const* d_in, const int* in_sizes, int n_in,
                              void* d_out, int out_size) {
    const float* x   = (const float*)d_in[0];
    const int*   ei  = (const int*)d_in[1];   // int32 (JAX default-config downcast)
    const float* W1  = (const float*)d_in[2];
    const float* as1 = (const float*)d_in[3];
    const float* ad1 = (const float*)d_in[4];
    const float* b1  = (const float*)d_in[5];
    const float* W2  = (const float*)d_in[6];
    const float* as2 = (const float*)d_in[7];
    const float* ad2 = (const float*)d_in[8];
    const float* b2  = (const float*)d_in[9];
    float*       out = (float*)d_out;

    int N  = in_sizes[0] / DIM1;   // 100000
    int E  = in_sizes[1] / 2;      // 1600000

    // fork-join stream setup (handles created once; graph capture turns
    // record/wait into edges)
    static cudaStream_t s2 = nullptr;
    static cudaEvent_t evFork = nullptr, evJoin = nullptr;
    if (!s2) {
        cudaStreamCreateWithFlags(&s2, cudaStreamNonBlocking);
        cudaEventCreateWithFlags(&evFork, cudaEventDisableTiming);
        cudaEventCreateWithFlags(&evJoin, cudaEventDisableTiming);
    }

    // fork: CSR build on s2, gemm1 on main stream (independent work)
    cudaEventRecord(evFork, 0);
    cudaStreamWaitEvent(s2, evFork, 0);

    zero_cnt_kernel<<<(N + 255) / 256, 256, 0, s2>>>(N);
    hist_kernel    <<<(E + 255) / 256, 256, 0, s2>>>(ei, E);
    scan_kernel    <<<1, 1024, 0, s2>>>(N);
    scatter_kernel <<<(E + 255) / 256, 256, 0, s2>>>(ei, E);
    cudaEventRecord(evJoin, s2);

    gemm1_kernel<<<(N + 127) / 128, 256>>>(x, W1, as1, ad1, N);

    // join: agg1 needs both gemm1 (main) and CSR (s2)
    cudaStreamWaitEvent(0, evJoin, 0);

    agg1_kernel <<<(N + 7) / 8, 256>>>(b1, N);
    gemm2_kernel<<<(N + 127) / 128, 256>>>(W2, as2, ad2, N);
    agg2_kernel <<<(N + 7) / 8, 256>>>(b2, out, N);
}

// round 13
// speedup vs baseline: 2.4348x; 1.0315x over previous
#include <cuda_runtime.h>
#include <cuda_fp16.h>
#include <cstdint>

#define NN    100000
#define EMAX  1700000
#define DIM1  128
#define H1    4
#define F2    40

// ---------------- scratch (device globals: allocation-free) ----------------
__device__ __half g_xw1h[(size_t)NN * DIM1]; // layer1 x@W1 (fp16)  [N,128]
__device__ float g_h  [(size_t)NN * DIM1];   // layer1 activated    [N,128]
__device__ float g_asrc1[NN * H1];
__device__ float g_adst1[NN * H1];
__device__ __half g_xw2h[(size_t)NN * F2];   // layer2 h@W2 (fp16)  [N,40]
__device__ float g_asrc2[NN];
__device__ float g_adst2[NN];
__device__ int   g_cnt [NN];                 // per-dst degree
__device__ int   g_fill[NN];                 // scatter cursors (init by scan)
__device__ int   g_off [NN + 1];             // CSR offsets
__device__ int   g_srt [EMAX];               // src indices sorted by dst

__device__ __forceinline__ float leaky(float v) { return v > 0.f ? v : 0.2f * v; }

__device__ __forceinline__ uint32_t f2tf32(float f) {
    uint32_t r;
    asm("cvt.rna.tf32.f32 %0, %1;" : "=r"(r) : "f"(f));
    return r;
}
__device__ __forceinline__ void mma_tf32(float* d, uint32_t a0, uint32_t a1,
                                         uint32_t a2, uint32_t a3,
                                         uint32_t b0, uint32_t b1) {
    asm volatile(
        "mma.sync.aligned.m16n8k8.row.col.f32.tf32.tf32.f32 "
        "{%0,%1,%2,%3}, {%4,%5,%6,%7}, {%8,%9}, {%0,%1,%2,%3};"
        : "+f"(d[0]), "+f"(d[1]), "+f"(d[2]), "+f"(d[3])
        : "r"(a0), "r"(a1), "r"(a2), "r"(a3), "r"(b0), "r"(b1));
}

// ---------------- CSR build ---------------------------------------------------
__global__ void zero_cnt_kernel(int N) {
    int i = blockIdx.x * blockDim.x + threadIdx.x;
    if (i < N) g_cnt[i] = 0;
}

__global__ void hist_kernel(const int* __restrict__ ei, int E) {
    int e = blockIdx.x * blockDim.x + threadIdx.x;
    if (e < E) atomicAdd(&g_cnt[__ldg(ei + E + e)], 1);
}

// single-block exclusive scan over g_cnt -> g_off; also seeds g_fill cursors
__global__ void scan_kernel(int NC) {
    __shared__ int wsum[32];
    int tid = threadIdx.x, lane = tid & 31, wid = tid >> 5;
    int carry = 0;
    for (int base = 0; base < NC; base += 1024) {
        int i = base + tid;
        int v = (i < NC) ? g_cnt[i] : 0;
        int s = v;
#pragma unroll
        for (int o = 1; o < 32; o <<= 1) {
            int t = __shfl_up_sync(0xffffffffu, s, o);
            if (lane >= o) s += t;
        }
        if (lane == 31) wsum[wid] = s;
        __syncthreads();
        if (wid == 0) {
            int ws = wsum[lane];
#pragma unroll
            for (int o = 1; o < 32; o <<= 1) {
                int t = __shfl_up_sync(0xffffffffu, ws, o);
                if (lane >= o) ws += t;
            }
            wsum[lane] = ws;
        }
        __syncthreads();
        int wexcl = (wid > 0) ? wsum[wid - 1] : 0;
        if (i < NC) {
            int off = carry + wexcl + s - v;
            g_off[i] = off;
            g_fill[i] = off;
        }
        int total = wsum[31];
        __syncthreads();
        carry += total;
    }
    if (tid == 0) g_off[NC] = carry;
}

__global__ void scatter_kernel(const int* __restrict__ ei, int E) {
    int e = blockIdx.x * blockDim.x + threadIdx.x;
    if (e < E) {
        int src = __ldg(ei + e), dst = __ldg(ei + E + e);
        int pos = atomicAdd(&g_fill[dst], 1);
        g_srt[pos] = src;
    }
}

// ---------------- GEMM1 via tensor cores (3xTF32) + fused attention dots ----
__global__ __launch_bounds__(256) void gemm1_kernel(
    const float* __restrict__ x, const float* __restrict__ W,
    const float* __restrict__ att_s, const float* __restrict__ att_d, int N) {
    __shared__ uint32_t sAh[128][20], sAl[128][20];
    __shared__ uint32_t sBh[16][136], sBl[16][136];   // stride 136: banks 8*tig+g
    int rowBase = blockIdx.x * 128;
    int tid = threadIdx.x, warp = tid >> 5, lane = tid & 31;
    int g = lane >> 2, tig = lane & 3;
    int wrow = warp * 16;

    float acc[16][4];
#pragma unroll
    for (int j = 0; j < 16; ++j)
#pragma unroll
        for (int q = 0; q < 4; ++q) acc[j][q] = 0.f;

    for (int kc = 0; kc < 8; ++kc) {
        __syncthreads();
        for (int i = tid; i < 512; i += 256) {
            int r = i >> 2, q = i & 3;
            int row = rowBase + r;
            float4 v = (row < N)
                ? *((const float4*)(x + (size_t)row * 128 + kc * 16 + q * 4))
                : make_float4(0.f, 0.f, 0.f, 0.f);
            const float* vf = (const float*)&v;
#pragma unroll
            for (int t = 0; t < 4; ++t) {
                uint32_t h = f2tf32(vf[t]);
                sAh[r][q * 4 + t] = h;
                sAl[r][q * 4 + t] = f2tf32(vf[t] - __uint_as_float(h));
            }
        }
        for (int i = tid; i < 512; i += 256) {
            int k = i >> 5, q = i & 31;
            float4 v = *((const float4*)(W + (size_t)(kc * 16 + k) * 128 + q * 4));
            const float* vf = (const float*)&v;
#pragma unroll
            for (int t = 0; t < 4; ++t) {
                uint32_t h = f2tf32(vf[t]);
                sBh[k][q * 4 + t] = h;
                sBl[k][q * 4 + t] = f2tf32(vf[t] - __uint_as_float(h));
            }
        }
        __syncthreads();
#pragma unroll
        for (int ks = 0; ks < 2; ++ks) {
            int k0 = ks * 8;
            uint32_t ah0 = sAh[wrow + g][k0 + tig];
            uint32_t ah1 = sAh[wrow + g + 8][k0 + tig];
            uint32_t ah2 = sAh[wrow + g][k0 + tig + 4];
            uint32_t ah3 = sAh[wrow + g + 8][k0 + tig + 4];
            uint32_t al0 = sAl[wrow + g][k0 + tig];
            uint32_t al1 = sAl[wrow + g + 8][k0 + tig];
            uint32_t al2 = sAl[wrow + g][k0 + tig + 4];
            uint32_t al3 = sAl[wrow + g + 8][k0 + tig + 4];
#pragma unroll
            for (int j = 0; j < 16; ++j) {
                int n0 = j * 8;
                uint32_t bh0 = sBh[k0 + tig][n0 + g];
                uint32_t bh1 = sBh[k0 + tig + 4][n0 + g];
                uint32_t bl0 = sBl[k0 + tig][n0 + g];
                uint32_t bl1 = sBl[k0 + tig + 4][n0 + g];
                mma_tf32(acc[j], ah0, ah1, ah2, ah3, bh0, bh1);
                mma_tf32(acc[j], ah0, ah1, ah2, ah3, bl0, bl1);
                mma_tf32(acc[j], al0, al1, al2, al3, bh0, bh1);
            }
        }
    }
    int row0 = rowBase + wrow + g, row1 = row0 + 8;
    float ps0[4] = {0,0,0,0}, pd0[4] = {0,0,0,0};
    float ps1[4] = {0,0,0,0}, pd1[4] = {0,0,0,0};
#pragma unroll
    for (int j = 0; j < 16; ++j) {
        int col = j * 8 + tig * 2;
        int head = j >> 2;
        float a0 = att_s[col], a1 = att_s[col + 1];
        float d0 = att_d[col], d1 = att_d[col + 1];
        ps0[head] += acc[j][0] * a0 + acc[j][1] * a1;
        pd0[head] += acc[j][0] * d0 + acc[j][1] * d1;
        ps1[head] += acc[j][2] * a0 + acc[j][3] * a1;
        pd1[head] += acc[j][2] * d0 + acc[j][3] * d1;
        if (row0 < N)
            *(__half2*)(g_xw1h + (size_t)row0 * 128 + col) =
                __floats2half2_rn(acc[j][0], acc[j][1]);
        if (row1 < N)
            *(__half2*)(g_xw1h + (size_t)row1 * 128 + col) =
                __floats2half2_rn(acc[j][2], acc[j][3]);
    }
#pragma unroll
    for (int h = 0; h < 4; ++h) {
#pragma unroll
        for (int o = 1; o < 4; o <<= 1) {
            ps0[h] += __shfl_xor_sync(0xffffffffu, ps0[h], o);
            pd0[h] += __shfl_xor_sync(0xffffffffu, pd0[h], o);
            ps1[h] += __shfl_xor_sync(0xffffffffu, ps1[h], o);
            pd1[h] += __shfl_xor_sync(0xffffffffu, pd1[h], o);
        }
    }
    if (tig == 0) {
        if (row0 < N) {
            *(float4*)(g_asrc1 + row0 * 4) = make_float4(ps0[0], ps0[1], ps0[2], ps0[3]);
            *(float4*)(g_adst1 + row0 * 4) = make_float4(pd0[0], pd0[1], pd0[2], pd0[3]);
        }
        if (row1 < N) {
            *(float4*)(g_asrc1 + row1 * 4) = make_float4(ps1[0], ps1[1], ps1[2], ps1[3]);
            *(float4*)(g_adst1 + row1 * 4) = make_float4(pd1[0], pd1[1], pd1[2], pd1[3]);
        }
    }
}

// ---------------- layer1 CSR aggregate: warp per dst, fp16 gather, unroll-4 --
__global__ void agg1_kernel(const float* __restrict__ b1, int N) {
    int dst = blockIdx.x * 8 + (threadIdx.x >> 5);
    int lane = threadIdx.x & 31;
    if (dst >= N) return;
    int head = lane >> 3;
    float adst = g_adst1[dst * 4 + head];
    float ex = __expf(leaky(g_asrc1[dst * 4 + head] + adst));   // self-loop
    uint2 ps = *(const uint2*)(g_xw1h + (size_t)dst * 128 + lane * 4);
    float2 s01 = __half22float2(*(__half2*)&ps.x);
    float2 s23 = __half22float2(*(__half2*)&ps.y);
    float4 accA = make_float4(s01.x * ex, s01.y * ex, s23.x * ex, s23.y * ex);
    float4 accB = make_float4(0.f, 0.f, 0.f, 0.f);
    float4 accC = make_float4(0.f, 0.f, 0.f, 0.f);
    float4 accD = make_float4(0.f, 0.f, 0.f, 0.f);
    float denA = ex, denB = 0.f, denC = 0.f, denD = 0.f;
    int start = g_off[dst], end = g_off[dst + 1];
    int i = start;
    for (; i + 3 < end; i += 4) {
        int s0 = g_srt[i],     s1 = g_srt[i + 1];
        int s2 = g_srt[i + 2], s3 = g_srt[i + 3];
        float e0 = __expf(leaky(g_asrc1[s0 * 4 + head] + adst));
        float e1 = __expf(leaky(g_asrc1[s1 * 4 + head] + adst));
        float e2 = __expf(leaky(g_asrc1[s2 * 4 + head] + adst));
        float e3 = __expf(leaky(g_asrc1[s3 * 4 + head] + adst));
        uint2 p0 = *(const uint2*)(g_xw1h + (size_t)s0 * 128 + lane * 4);
        uint2 p1 = *(const uint2*)(g_xw1h + (size_t)s1 * 128 + lane * 4);
        uint2 p2 = *(const uint2*)(g_xw1h + (size_t)s2 * 128 + lane * 4);
        uint2 p3 = *(const uint2*)(g_xw1h + (size_t)s3 * 128 + lane * 4);
        float2 a01 = __half22float2(*(__half2*)&p0.x), a23 = __half22float2(*(__half2*)&p0.y);
        float2 b01 = __half22float2(*(__half2*)&p1.x), b23 = __half22float2(*(__half2*)&p1.y);
        float2 c01 = __half22float2(*(__half2*)&p2.x), c23 = __half22float2(*(__half2*)&p2.y);
        float2 d01 = __half22float2(*(__half2*)&p3.x), d23 = __half22float2(*(__half2*)&p3.y);
        accA.x += a01.x * e0; accA.y += a01.y * e0; accA.z += a23.x * e0; accA.w += a23.y * e0;
        accB.x += b01.x * e1; accB.y += b01.y * e1; accB.z += b23.x * e1; accB.w += b23.y * e1;
        accC.x += c01.x * e2; accC.y += c01.y * e2; accC.z += c23.x * e2; accC.w += c23.y * e2;
        accD.x += d01.x * e3; accD.y += d01.y * e3; accD.z += d23.x * e3; accD.w += d23.y * e3;
        denA += e0; denB += e1; denC += e2; denD += e3;
    }
    for (; i < end; ++i) {
        int s0 = g_srt[i];
        float e0 = __expf(leaky(g_asrc1[s0 * 4 + head] + adst));
        uint2 p0 = *(const uint2*)(g_xw1h + (size_t)s0 * 128 + lane * 4);
        float2 a01 = __half22float2(*(__half2*)&p0.x), a23 = __half22float2(*(__half2*)&p0.y);
        accA.x += a01.x * e0; accA.y += a01.y * e0; accA.z += a23.x * e0; accA.w += a23.y * e0;
        denA += e0;
    }
    accA.x += accB.x + accC.x + accD.x;
    accA.y += accB.y + accC.y + accD.y;
    accA.z += accB.z + accC.z + accD.z;
    accA.w += accB.w + accC.w + accD.w;
    float inv = 1.f / (denA + denB + denC + denD);
    float4 b = ((const float4*)b1)[lane];
    float4 o;
    o.x = fmaxf(accA.x * inv + b.x, 0.f);
    o.y = fmaxf(accA.y * inv + b.y, 0.f);
    o.z = fmaxf(accA.z * inv + b.z, 0.f);
    o.w = fmaxf(accA.w * inv + b.w, 0.f);
    ((float4*)(g_h + (size_t)dst * 128))[lane] = o;
}

// ---------------- GEMM2 via tensor cores (3xTF32) + att2 dots ----------------
__global__ __launch_bounds__(256) void gemm2_kernel(
    const float* __restrict__ W2,
    const float* __restrict__ att_s, const float* __restrict__ att_d, int N) {
    __shared__ uint32_t sAh[128][20], sAl[128][20];
    __shared__ uint32_t sBh[16][40], sBl[16][40];   // stride 40: banks 8*tig+g
    int rowBase = blockIdx.x * 128;
    int tid = threadIdx.x, warp = tid >> 5, lane = tid & 31;
    int g = lane >> 2, tig = lane & 3;
    int wrow = warp * 16;

    float acc[5][4];
#pragma unroll
    for (int j = 0; j < 5; ++j)
#pragma unroll
        for (int q = 0; q < 4; ++q) acc[j][q] = 0.f;

    for (int kc = 0; kc < 8; ++kc) {
        __syncthreads();
        for (int i = tid; i < 512; i += 256) {
            int r = i >> 2, q = i & 3;
            int row = rowBase + r;
            float4 v = (row < N)
                ? *((const float4*)(g_h + (size_t)row * 128 + kc * 16 + q * 4))
                : make_float4(0.f, 0.f, 0.f, 0.f);
            const float* vf = (const float*)&v;
#pragma unroll
            for (int t = 0; t < 4; ++t) {
                uint32_t h = f2tf32(vf[t]);
                sAh[r][q * 4 + t] = h;
                sAl[r][q * 4 + t] = f2tf32(vf[t] - __uint_as_float(h));
            }
        }
        for (int i = tid; i < 160; i += 256) {
            int k = i / 10, q = i - (i / 10) * 10;
            float4 v = *((const float4*)(W2 + (size_t)(kc * 16 + k) * 40 + q * 4));
            const float* vf = (const float*)&v;
#pragma unroll
            for (int t = 0; t < 4; ++t) {
                uint32_t h = f2tf32(vf[t]);
                sBh[k][q * 4 + t] = h;
                sBl[k][q * 4 + t] = f2tf32(vf[t] - __uint_as_float(h));
            }
        }
        __syncthreads();
#pragma unroll
        for (int ks = 0; ks < 2; ++ks) {
            int k0 = ks * 8;
            uint32_t ah0 = sAh[wrow + g][k0 + tig];
            uint32_t ah1 = sAh[wrow + g + 8][k0 + tig];
            uint32_t ah2 = sAh[wrow + g][k0 + tig + 4];
            uint32_t ah3 = sAh[wrow + g + 8][k0 + tig + 4];
            uint32_t al0 = sAl[wrow + g][k0 + tig];
            uint32_t al1 = sAl[wrow + g + 8][k0 + tig];
            uint32_t al2 = sAl[wrow + g][k0 + tig + 4];
            uint32_t al3 = sAl[wrow + g + 8][k0 + tig + 4];
#pragma unroll
            for (int j = 0; j < 5; ++j) {
                int n0 = j * 8;
                uint32_t bh0 = sBh[k0 + tig][n0 + g];
                uint32_t bh1 = sBh[k0 + tig + 4][n0 + g];
                uint32_t bl0 = sBl[k0 + tig][n0 + g];
                uint32_t bl1 = sBl[k0 + tig + 4][n0 + g];
                mma_tf32(acc[j], ah0, ah1, ah2, ah3, bh0, bh1);
                mma_tf32(acc[j], ah0, ah1, ah2, ah3, bl0, bl1);
                mma_tf32(acc[j], al0, al1, al2, al3, bh0, bh1);
            }
        }
    }
    int row0 = rowBase + wrow + g, row1 = row0 + 8;
    float ps0 = 0.f, pd0 = 0.f, ps1 = 0.f, pd1 = 0.f;
#pragma unroll
    for (int j = 0; j < 5; ++j) {
        int col = j * 8 + tig * 2;
        float a0 = att_s[col], a1 = att_s[col + 1];
        float d0 = att_d[col], d1 = att_d[col + 1];
        ps0 += acc[j][0] * a0 + acc[j][1] * a1;
        pd0 += acc[j][0] * d0 + acc[j][1] * d1;
        ps1 += acc[j][2] * a0 + acc[j][3] * a1;
        pd1 += acc[j][2] * d0 + acc[j][3] * d1;
        if (row0 < N)
            *(__half2*)(g_xw2h + (size_t)row0 * F2 + col) =
                __floats2half2_rn(acc[j][0], acc[j][1]);
        if (row1 < N)
            *(__half2*)(g_xw2h + (size_t)row1 * F2 + col) =
                __floats2half2_rn(acc[j][2], acc[j][3]);
    }
#pragma unroll
    for (int o = 1; o < 4; o <<= 1) {
        ps0 += __shfl_xor_sync(0xffffffffu, ps0, o);
        pd0 += __shfl_xor_sync(0xffffffffu, pd0, o);
        ps1 += __shfl_xor_sync(0xffffffffu, ps1, o);
        pd1 += __shfl_xor_sync(0xffffffffu, pd1, o);
    }
    if (tig == 0) {
        if (row0 < N) { g_asrc2[row0] = ps0; g_adst2[row0] = pd0; }
        if (row1 < N) { g_asrc2[row1] = ps1; g_adst2[row1] = pd1; }
    }
}

// ---------------- layer2 CSR aggregate: warp per dst, fp16, 3 edge-groups ----
__global__ void agg2_kernel(const float* __restrict__ b2,
                            float* __restrict__ out, int N) {
    int dst = blockIdx.x * 8 + (threadIdx.x >> 5);
    int lane = threadIdx.x & 31;
    if (dst >= N) return;
    int grp = lane / 10, gl = lane - grp * 10;   // grp 3 = lanes 30,31 idle
    float adst = g_adst2[dst];
    float4 acc = make_float4(0.f, 0.f, 0.f, 0.f);
    float den = 0.f;
    if (grp == 0) {      // self-loop in group 0
        float ex = __expf(leaky(g_asrc2[dst] + adst));
        uint2 p = *(const uint2*)(g_xw2h + (size_t)dst * F2 + gl * 4);
        float2 v01 = __half22float2(*(__half2*)&p.x);
        float2 v23 = __half22float2(*(__half2*)&p.y);
        acc.x = v01.x * ex; acc.y = v01.y * ex; acc.z = v23.x * ex; acc.w = v23.y * ex;
        den = ex;
    }
    int start = g_off[dst], end = g_off[dst + 1];
    if (grp < 3) {
        for (int i = start + grp; i < end; i += 3) {
            int src = g_srt[i];
            float ex = __expf(leaky(g_asrc2[src] + adst));
            uint2 p = *(const uint2*)(g_xw2h + (size_t)src * F2 + gl * 4);
            float2 v01 = __half22float2(*(__half2*)&p.x);
            float2 v23 = __half22float2(*(__half2*)&p.y);
            acc.x += v01.x * ex; acc.y += v01.y * ex;
            acc.z += v23.x * ex; acc.w += v23.y * ex;
            den += ex;
        }
    }
    float4 a1, a2;
    a1.x = __shfl_sync(0xffffffffu, acc.x, lane + 10);
    a1.y = __shfl_sync(0xffffffffu, acc.y, lane + 10);
    a1.z = __shfl_sync(0xffffffffu, acc.z, lane + 10);
    a1.w = __shfl_sync(0xffffffffu, acc.w, lane + 10);
    a2.x = __shfl_sync(0xffffffffu, acc.x, lane + 20);
    a2.y = __shfl_sync(0xffffffffu, acc.y, lane + 20);
    a2.z = __shfl_sync(0xffffffffu, acc.z, lane + 20);
    a2.w = __shfl_sync(0xffffffffu, acc.w, lane + 20);
    float d1 = __shfl_sync(0xffffffffu, den, lane + 10);
    float d2 = __shfl_sync(0xffffffffu, den, lane + 20);
    if (grp == 0) {
        acc.x += a1.x + a2.x; acc.y += a1.y + a2.y;
        acc.z += a1.z + a2.z; acc.w += a1.w + a2.w;
        float inv = 1.f / (den + d1 + d2);
        float4 b = ((const float4*)b2)[gl];
        float4 o;
        o.x = acc.x * inv + b.x;
        o.y = acc.y * inv + b.y;
        o.z = acc.z * inv + b.z;
        o.w = acc.w * inv + b.w;
        ((float4*)(out + (size_t)dst * F2))[gl] = o;
    }
}

// ============================================================================
extern "C" void kernel_launch(void* const* d_in, const int* in_sizes, int n_in,
                              void* d_out, int out_size) {
    const float* x   = (const float*)d_in[0];
    const int*   ei  = (const int*)d_in[1];   // int32 (JAX default-config downcast)
    const float* W1  = (const float*)d_in[2];
    const float* as1 = (const float*)d_in[3];
    const float* ad1 = (const float*)d_in[4];
    const float* b1  = (const float*)d_in[5];
    const float* W2  = (const float*)d_in[6];
    const float* as2 = (const float*)d_in[7];
    const float* ad2 = (const float*)d_in[8];
    const float* b2  = (const float*)d_in[9];
    float*       out = (float*)d_out;

    int N  = in_sizes[0] / DIM1;   // 100000
    int E  = in_sizes[1] / 2;      // 1600000

    // fork-join stream setup (handles created once; graph capture turns
    // record/wait into edges)
    static cudaStream_t s2 = nullptr;
    static cudaEvent_t evFork = nullptr, evJoin = nullptr;
    if (!s2) {
        cudaStreamCreateWithFlags(&s2, cudaStreamNonBlocking);
        cudaEventCreateWithFlags(&evFork, cudaEventDisableTiming);
        cudaEventCreateWithFlags(&evJoin, cudaEventDisableTiming);
    }

    // fork: CSR build on s2, gemm1 on main stream (independent work)
    cudaEventRecord(evFork, 0);
    cudaStreamWaitEvent(s2, evFork, 0);

    zero_cnt_kernel<<<(N + 255) / 256, 256, 0, s2>>>(N);
    hist_kernel    <<<(E + 255) / 256, 256, 0, s2>>>(ei, E);
    scan_kernel    <<<1, 1024, 0, s2>>>(N);
    scatter_kernel <<<(E + 255) / 256, 256, 0, s2>>>(ei, E);
    cudaEventRecord(evJoin, s2);

    gemm1_kernel<<<(N + 127) / 128, 256>>>(x, W1, as1, ad1, N);

    // join: agg1 needs both gemm1 (main) and CSR (s2)
    cudaStreamWaitEvent(0, evJoin, 0);

    agg1_kernel <<<(N + 7) / 8, 256>>>(b1, N);
    gemm2_kernel<<<(N + 127) / 128, 256>>>(W2, as2, ad2, N);
    agg2_kernel <<<(N + 7) / 8, 256>>>(b2, out, N);
}

// round 14
// speedup vs baseline: 2.4786x; 1.0180x over previous
#include <cuda_runtime.h>
#include <cuda_fp16.h>
#include <cstdint>

#define NN    100000
#define EMAX  1700000
#define DIM1  128
#define H1    4
#define F2    40

// ---------------- scratch (device globals: allocation-free) ----------------
__device__ __half g_xw1h[(size_t)NN * DIM1]; // layer1 x@W1 (fp16)  [N,128]
__device__ float g_h  [(size_t)NN * DIM1];   // layer1 activated    [N,128]
__device__ float g_asrc1[NN * H1];
__device__ float g_adst1[NN * H1];
__device__ __half g_xw2h[(size_t)NN * F2];   // layer2 h@W2 (fp16)  [N,40]
__device__ float g_asrc2[NN];
__device__ float g_adst2[NN];
__device__ int   g_cnt [NN];                 // per-dst degree (zeroed at graph tail)
__device__ int   g_off [NN + 1];             // CSR offsets
__device__ int   g_rank[EMAX];               // within-bucket rank per edge
__device__ int   g_srt [EMAX];               // src indices sorted by dst

__device__ __forceinline__ float leaky(float v) { return v > 0.f ? v : 0.2f * v; }

__device__ __forceinline__ uint32_t f2tf32(float f) {
    uint32_t r;
    asm("cvt.rna.tf32.f32 %0, %1;" : "=r"(r) : "f"(f));
    return r;
}
__device__ __forceinline__ void mma_tf32(float* d, uint32_t a0, uint32_t a1,
                                         uint32_t a2, uint32_t a3,
                                         uint32_t b0, uint32_t b1) {
    asm volatile(
        "mma.sync.aligned.m16n8k8.row.col.f32.tf32.tf32.f32 "
        "{%0,%1,%2,%3}, {%4,%5,%6,%7}, {%8,%9}, {%0,%1,%2,%3};"
        : "+f"(d[0]), "+f"(d[1]), "+f"(d[2]), "+f"(d[3])
        : "r"(a0), "r"(a1), "r"(a2), "r"(a3), "r"(b0), "r"(b1));
}

// ---------------- CSR build ---------------------------------------------------
// hist: count + record each edge's within-bucket rank (atomic return value)
__global__ void hist_kernel(const int* __restrict__ ei, int E) {
    int e = blockIdx.x * blockDim.x + threadIdx.x;
    if (e < E) g_rank[e] = atomicAdd(&g_cnt[__ldg(ei + E + e)], 1);
}

// single-block exclusive scan over g_cnt -> g_off
__global__ void scan_kernel(int NC) {
    __shared__ int wsum[32];
    int tid = threadIdx.x, lane = tid & 31, wid = tid >> 5;
    int carry = 0;
    for (int base = 0; base < NC; base += 1024) {
        int i = base + tid;
        int v = (i < NC) ? g_cnt[i] : 0;
        int s = v;
#pragma unroll
        for (int o = 1; o < 32; o <<= 1) {
            int t = __shfl_up_sync(0xffffffffu, s, o);
            if (lane >= o) s += t;
        }
        if (lane == 31) wsum[wid] = s;
        __syncthreads();
        if (wid == 0) {
            int ws = wsum[lane];
#pragma unroll
            for (int o = 1; o < 32; o <<= 1) {
                int t = __shfl_up_sync(0xffffffffu, ws, o);
                if (lane >= o) ws += t;
            }
            wsum[lane] = ws;
        }
        __syncthreads();
        int wexcl = (wid > 0) ? wsum[wid - 1] : 0;
        if (i < NC) g_off[i] = carry + wexcl + s - v;
        int total = wsum[31];
        __syncthreads();
        carry += total;
    }
    if (tid == 0) g_off[NC] = carry;
}

// atomic-free scatter: position = off[dst] + rank[e]
__global__ void scatter_kernel(const int* __restrict__ ei, int E) {
    int e = blockIdx.x * blockDim.x + threadIdx.x;
    if (e < E) {
        int src = __ldg(ei + e), dst = __ldg(ei + E + e);
        g_srt[g_off[dst] + g_rank[e]] = src;
    }
}

// zero g_cnt for the NEXT graph replay (cnt is dead after scan; static init
// covers the very first launch). Runs off the critical path.
__global__ void zero_cnt_kernel(int N) {
    int i = blockIdx.x * blockDim.x + threadIdx.x;
    if (i < N) g_cnt[i] = 0;
}

// ---------------- GEMM1 via tensor cores (3xTF32) + fused attention dots ----
__global__ __launch_bounds__(256) void gemm1_kernel(
    const float* __restrict__ x, const float* __restrict__ W,
    const float* __restrict__ att_s, const float* __restrict__ att_d, int N) {
    __shared__ uint32_t sAh[128][20], sAl[128][20];
    __shared__ uint32_t sBh[16][136], sBl[16][136];   // stride 136: banks 8*tig+g
    int rowBase = blockIdx.x * 128;
    int tid = threadIdx.x, warp = tid >> 5, lane = tid & 31;
    int g = lane >> 2, tig = lane & 3;
    int wrow = warp * 16;

    float acc[16][4];
#pragma unroll
    for (int j = 0; j < 16; ++j)
#pragma unroll
        for (int q = 0; q < 4; ++q) acc[j][q] = 0.f;

    for (int kc = 0; kc < 8; ++kc) {
        __syncthreads();
        for (int i = tid; i < 512; i += 256) {
            int r = i >> 2, q = i & 3;
            int row = rowBase + r;
            float4 v = (row < N)
                ? *((const float4*)(x + (size_t)row * 128 + kc * 16 + q * 4))
                : make_float4(0.f, 0.f, 0.f, 0.f);
            const float* vf = (const float*)&v;
#pragma unroll
            for (int t = 0; t < 4; ++t) {
                uint32_t h = f2tf32(vf[t]);
                sAh[r][q * 4 + t] = h;
                sAl[r][q * 4 + t] = f2tf32(vf[t] - __uint_as_float(h));
            }
        }
        for (int i = tid; i < 512; i += 256) {
            int k = i >> 5, q = i & 31;
            float4 v = *((const float4*)(W + (size_t)(kc * 16 + k) * 128 + q * 4));
            const float* vf = (const float*)&v;
#pragma unroll
            for (int t = 0; t < 4; ++t) {
                uint32_t h = f2tf32(vf[t]);
                sBh[k][q * 4 + t] = h;
                sBl[k][q * 4 + t] = f2tf32(vf[t] - __uint_as_float(h));
            }
        }
        __syncthreads();
#pragma unroll
        for (int ks = 0; ks < 2; ++ks) {
            int k0 = ks * 8;
            uint32_t ah0 = sAh[wrow + g][k0 + tig];
            uint32_t ah1 = sAh[wrow + g + 8][k0 + tig];
            uint32_t ah2 = sAh[wrow + g][k0 + tig + 4];
            uint32_t ah3 = sAh[wrow + g + 8][k0 + tig + 4];
            uint32_t al0 = sAl[wrow + g][k0 + tig];
            uint32_t al1 = sAl[wrow + g + 8][k0 + tig];
            uint32_t al2 = sAl[wrow + g][k0 + tig + 4];
            uint32_t al3 = sAl[wrow + g + 8][k0 + tig + 4];
#pragma unroll
            for (int j = 0; j < 16; ++j) {
                int n0 = j * 8;
                uint32_t bh0 = sBh[k0 + tig][n0 + g];
                uint32_t bh1 = sBh[k0 + tig + 4][n0 + g];
                uint32_t bl0 = sBl[k0 + tig][n0 + g];
                uint32_t bl1 = sBl[k0 + tig + 4][n0 + g];
                mma_tf32(acc[j], ah0, ah1, ah2, ah3, bh0, bh1);
                mma_tf32(acc[j], ah0, ah1, ah2, ah3, bl0, bl1);
                mma_tf32(acc[j], al0, al1, al2, al3, bh0, bh1);
            }
        }
    }
    int row0 = rowBase + wrow + g, row1 = row0 + 8;
    float ps0[4] = {0,0,0,0}, pd0[4] = {0,0,0,0};
    float ps1[4] = {0,0,0,0}, pd1[4] = {0,0,0,0};
#pragma unroll
    for (int j = 0; j < 16; ++j) {
        int col = j * 8 + tig * 2;
        int head = j >> 2;
        float a0 = att_s[col], a1 = att_s[col + 1];
        float d0 = att_d[col], d1 = att_d[col + 1];
        ps0[head] += acc[j][0] * a0 + acc[j][1] * a1;
        pd0[head] += acc[j][0] * d0 + acc[j][1] * d1;
        ps1[head] += acc[j][2] * a0 + acc[j][3] * a1;
        pd1[head] += acc[j][2] * d0 + acc[j][3] * d1;
        if (row0 < N)
            *(__half2*)(g_xw1h + (size_t)row0 * 128 + col) =
                __floats2half2_rn(acc[j][0], acc[j][1]);
        if (row1 < N)
            *(__half2*)(g_xw1h + (size_t)row1 * 128 + col) =
                __floats2half2_rn(acc[j][2], acc[j][3]);
    }
#pragma unroll
    for (int h = 0; h < 4; ++h) {
#pragma unroll
        for (int o = 1; o < 4; o <<= 1) {
            ps0[h] += __shfl_xor_sync(0xffffffffu, ps0[h], o);
            pd0[h] += __shfl_xor_sync(0xffffffffu, pd0[h], o);
            ps1[h] += __shfl_xor_sync(0xffffffffu, ps1[h], o);
            pd1[h] += __shfl_xor_sync(0xffffffffu, pd1[h], o);
        }
    }
    if (tig == 0) {
        if (row0 < N) {
            *(float4*)(g_asrc1 + row0 * 4) = make_float4(ps0[0], ps0[1], ps0[2], ps0[3]);
            *(float4*)(g_adst1 + row0 * 4) = make_float4(pd0[0], pd0[1], pd0[2], pd0[3]);
        }
        if (row1 < N) {
            *(float4*)(g_asrc1 + row1 * 4) = make_float4(ps1[0], ps1[1], ps1[2], ps1[3]);
            *(float4*)(g_adst1 + row1 * 4) = make_float4(pd1[0], pd1[1], pd1[2], pd1[3]);
        }
    }
}

// ---------------- layer1 CSR aggregate: warp per dst, fp16 gather, unroll-4 --
// processes dst in [begin, end)
__global__ void agg1_kernel(const float* __restrict__ b1, int begin, int end) {
    int dst = begin + blockIdx.x * 8 + (threadIdx.x >> 5);
    int lane = threadIdx.x & 31;
    if (dst >= end) return;
    int head = lane >> 3;
    float adst = g_adst1[dst * 4 + head];
    float ex = __expf(leaky(g_asrc1[dst * 4 + head] + adst));   // self-loop
    uint2 ps = *(const uint2*)(g_xw1h + (size_t)dst * 128 + lane * 4);
    float2 s01 = __half22float2(*(__half2*)&ps.x);
    float2 s23 = __half22float2(*(__half2*)&ps.y);
    float4 accA = make_float4(s01.x * ex, s01.y * ex, s23.x * ex, s23.y * ex);
    float4 accB = make_float4(0.f, 0.f, 0.f, 0.f);
    float4 accC = make_float4(0.f, 0.f, 0.f, 0.f);
    float4 accD = make_float4(0.f, 0.f, 0.f, 0.f);
    float denA = ex, denB = 0.f, denC = 0.f, denD = 0.f;
    int start = g_off[dst], stop = g_off[dst + 1];
    int i = start;
    for (; i + 3 < stop; i += 4) {
        int s0 = g_srt[i],     s1 = g_srt[i + 1];
        int s2 = g_srt[i + 2], s3 = g_srt[i + 3];
        float e0 = __expf(leaky(g_asrc1[s0 * 4 + head] + adst));
        float e1 = __expf(leaky(g_asrc1[s1 * 4 + head] + adst));
        float e2 = __expf(leaky(g_asrc1[s2 * 4 + head] + adst));
        float e3 = __expf(leaky(g_asrc1[s3 * 4 + head] + adst));
        uint2 p0 = *(const uint2*)(g_xw1h + (size_t)s0 * 128 + lane * 4);
        uint2 p1 = *(const uint2*)(g_xw1h + (size_t)s1 * 128 + lane * 4);
        uint2 p2 = *(const uint2*)(g_xw1h + (size_t)s2 * 128 + lane * 4);
        uint2 p3 = *(const uint2*)(g_xw1h + (size_t)s3 * 128 + lane * 4);
        float2 a01 = __half22float2(*(__half2*)&p0.x), a23 = __half22float2(*(__half2*)&p0.y);
        float2 b01 = __half22float2(*(__half2*)&p1.x), b23 = __half22float2(*(__half2*)&p1.y);
        float2 c01 = __half22float2(*(__half2*)&p2.x), c23 = __half22float2(*(__half2*)&p2.y);
        float2 d01 = __half22float2(*(__half2*)&p3.x), d23 = __half22float2(*(__half2*)&p3.y);
        accA.x += a01.x * e0; accA.y += a01.y * e0; accA.z += a23.x * e0; accA.w += a23.y * e0;
        accB.x += b01.x * e1; accB.y += b01.y * e1; accB.z += b23.x * e1; accB.w += b23.y * e1;
        accC.x += c01.x * e2; accC.y += c01.y * e2; accC.z += c23.x * e2; accC.w += c23.y * e2;
        accD.x += d01.x * e3; accD.y += d01.y * e3; accD.z += d23.x * e3; accD.w += d23.y * e3;
        denA += e0; denB += e1; denC += e2; denD += e3;
    }
    for (; i < stop; ++i) {
        int s0 = g_srt[i];
        float e0 = __expf(leaky(g_asrc1[s0 * 4 + head] + adst));
        uint2 p0 = *(const uint2*)(g_xw1h + (size_t)s0 * 128 + lane * 4);
        float2 a01 = __half22float2(*(__half2*)&p0.x), a23 = __half22float2(*(__half2*)&p0.y);
        accA.x += a01.x * e0; accA.y += a01.y * e0; accA.z += a23.x * e0; accA.w += a23.y * e0;
        denA += e0;
    }
    accA.x += accB.x + accC.x + accD.x;
    accA.y += accB.y + accC.y + accD.y;
    accA.z += accB.z + accC.z + accD.z;
    accA.w += accB.w + accC.w + accD.w;
    float inv = 1.f / (denA + denB + denC + denD);
    float4 b = ((const float4*)b1)[lane];
    float4 o;
    o.x = fmaxf(accA.x * inv + b.x, 0.f);
    o.y = fmaxf(accA.y * inv + b.y, 0.f);
    o.z = fmaxf(accA.z * inv + b.z, 0.f);
    o.w = fmaxf(accA.w * inv + b.w, 0.f);
    ((float4*)(g_h + (size_t)dst * 128))[lane] = o;
}

// ---------------- GEMM2 via tensor cores (3xTF32) + att2 dots ----------------
// processes rows [begin, begin + 128*gridDim.x), clamped to N
__global__ __launch_bounds__(256) void gemm2_kernel(
    const float* __restrict__ W2,
    const float* __restrict__ att_s, const float* __restrict__ att_d,
    int begin, int N) {
    __shared__ uint32_t sAh[128][20], sAl[128][20];
    __shared__ uint32_t sBh[16][40], sBl[16][40];   // stride 40: banks 8*tig+g
    int rowBase = begin + blockIdx.x * 128;
    int tid = threadIdx.x, warp = tid >> 5, lane = tid & 31;
    int g = lane >> 2, tig = lane & 3;
    int wrow = warp * 16;

    float acc[5][4];
#pragma unroll
    for (int j = 0; j < 5; ++j)
#pragma unroll
        for (int q = 0; q < 4; ++q) acc[j][q] = 0.f;

    for (int kc = 0; kc < 8; ++kc) {
        __syncthreads();
        for (int i = tid; i < 512; i += 256) {
            int r = i >> 2, q = i & 3;
            int row = rowBase + r;
            float4 v = (row < N)
                ? *((const float4*)(g_h + (size_t)row * 128 + kc * 16 + q * 4))
                : make_float4(0.f, 0.f, 0.f, 0.f);
            const float* vf = (const float*)&v;
#pragma unroll
            for (int t = 0; t < 4; ++t) {
                uint32_t h = f2tf32(vf[t]);
                sAh[r][q * 4 + t] = h;
                sAl[r][q * 4 + t] = f2tf32(vf[t] - __uint_as_float(h));
            }
        }
        for (int i = tid; i < 160; i += 256) {
            int k = i / 10, q = i - (i / 10) * 10;
            float4 v = *((const float4*)(W2 + (size_t)(kc * 16 + k) * 40 + q * 4));
            const float* vf = (const float*)&v;
#pragma unroll
            for (int t = 0; t < 4; ++t) {
                uint32_t h = f2tf32(vf[t]);
                sBh[k][q * 4 + t] = h;
                sBl[k][q * 4 + t] = f2tf32(vf[t] - __uint_as_float(h));
            }
        }
        __syncthreads();
#pragma unroll
        for (int ks = 0; ks < 2; ++ks) {
            int k0 = ks * 8;
            uint32_t ah0 = sAh[wrow + g][k0 + tig];
            uint32_t ah1 = sAh[wrow + g + 8][k0 + tig];
            uint32_t ah2 = sAh[wrow + g][k0 + tig + 4];
            uint32_t ah3 = sAh[wrow + g + 8][k0 + tig + 4];
            uint32_t al0 = sAl[wrow + g][k0 + tig];
            uint32_t al1 = sAl[wrow + g + 8][k0 + tig];
            uint32_t al2 = sAl[wrow + g][k0 + tig + 4];
            uint32_t al3 = sAl[wrow + g + 8][k0 + tig + 4];
#pragma unroll
            for (int j = 0; j < 5; ++j) {
                int n0 = j * 8;
                uint32_t bh0 = sBh[k0 + tig][n0 + g];
                uint32_t bh1 = sBh[k0 + tig + 4][n0 + g];
                uint32_t bl0 = sBl[k0 + tig][n0 + g];
                uint32_t bl1 = sBl[k0 + tig + 4][n0 + g];
                mma_tf32(acc[j], ah0, ah1, ah2, ah3, bh0, bh1);
                mma_tf32(acc[j], ah0, ah1, ah2, ah3, bl0, bl1);
                mma_tf32(acc[j], al0, al1, al2, al3, bh0, bh1);
            }
        }
    }
    int row0 = rowBase + wrow + g, row1 = row0 + 8;
    float ps0 = 0.f, pd0 = 0.f, ps1 = 0.f, pd1 = 0.f;
#pragma unroll
    for (int j = 0; j < 5; ++j) {
        int col = j * 8 + tig * 2;
        float a0 = att_s[col], a1 = att_s[col + 1];
        float d0 = att_d[col], d1 = att_d[col + 1];
        ps0 += acc[j][0] * a0 + acc[j][1] * a1;
        pd0 += acc[j][0] * d0 + acc[j][1] * d1;
        ps1 += acc[j][2] * a0 + acc[j][3] * a1;
        pd1 += acc[j][2] * d0 + acc[j][3] * d1;
        if (row0 < N)
            *(__half2*)(g_xw2h + (size_t)row0 * F2 + col) =
                __floats2half2_rn(acc[j][0], acc[j][1]);
        if (row1 < N)
            *(__half2*)(g_xw2h + (size_t)row1 * F2 + col) =
                __floats2half2_rn(acc[j][2], acc[j][3]);
    }
#pragma unroll
    for (int o = 1; o < 4; o <<= 1) {
        ps0 += __shfl_xor_sync(0xffffffffu, ps0, o);
        pd0 += __shfl_xor_sync(0xffffffffu, pd0, o);
        ps1 += __shfl_xor_sync(0xffffffffu, ps1, o);
        pd1 += __shfl_xor_sync(0xffffffffu, pd1, o);
    }
    if (tig == 0) {
        if (row0 < N) { g_asrc2[row0] = ps0; g_adst2[row0] = pd0; }
        if (row1 < N) { g_asrc2[row1] = ps1; g_adst2[row1] = pd1; }
    }
}

// ---------------- layer2 CSR aggregate: warp per dst, fp16, 3 edge-groups ----
__global__ void agg2_kernel(const float* __restrict__ b2,
                            float* __restrict__ out, int N) {
    int dst = blockIdx.x * 8 + (threadIdx.x >> 5);
    int lane = threadIdx.x & 31;
    if (dst >= N) return;
    int grp = lane / 10, gl = lane - grp * 10;   // grp 3 = lanes 30,31 idle
    float adst = g_adst2[dst];
    float4 acc = make_float4(0.f, 0.f, 0.f, 0.f);
    float den = 0.f;
    if (grp == 0) {      // self-loop in group 0
        float ex = __expf(leaky(g_asrc2[dst] + adst));
        uint2 p = *(const uint2*)(g_xw2h + (size_t)dst * F2 + gl * 4);
        float2 v01 = __half22float2(*(__half2*)&p.x);
        float2 v23 = __half22float2(*(__half2*)&p.y);
        acc.x = v01.x * ex; acc.y = v01.y * ex; acc.z = v23.x * ex; acc.w = v23.y * ex;
        den = ex;
    }
    int start = g_off[dst], end = g_off[dst + 1];
    if (grp < 3) {
        for (int i = start + grp; i < end; i += 3) {
            int src = g_srt[i];
            float ex = __expf(leaky(g_asrc2[src] + adst));
            uint2 p = *(const uint2*)(g_xw2h + (size_t)src * F2 + gl * 4);
            float2 v01 = __half22float2(*(__half2*)&p.x);
            float2 v23 = __half22float2(*(__half2*)&p.y);
            acc.x += v01.x * ex; acc.y += v01.y * ex;
            acc.z += v23.x * ex; acc.w += v23.y * ex;
            den += ex;
        }
    }
    float4 a1, a2;
    a1.x = __shfl_sync(0xffffffffu, acc.x, lane + 10);
    a1.y = __shfl_sync(0xffffffffu, acc.y, lane + 10);
    a1.z = __shfl_sync(0xffffffffu, acc.z, lane + 10);
    a1.w = __shfl_sync(0xffffffffu, acc.w, lane + 10);
    a2.x = __shfl_sync(0xffffffffu, acc.x, lane + 20);
    a2.y = __shfl_sync(0xffffffffu, acc.y, lane + 20);
    a2.z = __shfl_sync(0xffffffffu, acc.z, lane + 20);
    a2.w = __shfl_sync(0xffffffffu, acc.w, lane + 20);
    float d1 = __shfl_sync(0xffffffffu, den, lane + 10);
    float d2 = __shfl_sync(0xffffffffu, den, lane + 20);
    if (grp == 0) {
        acc.x += a1.x + a2.x; acc.y += a1.y + a2.y;
        acc.z += a1.z + a2.z; acc.w += a1.w + a2.w;
        float inv = 1.f / (den + d1 + d2);
        float4 b = ((const float4*)b2)[gl];
        float4 o;
        o.x = acc.x * inv + b.x;
        o.y = acc.y * inv + b.y;
        o.z = acc.z * inv + b.z;
        o.w = acc.w * inv + b.w;
        ((float4*)(out + (size_t)dst * F2))[gl] = o;
    }
}

// ============================================================================
extern "C" void kernel_launch(void* const* d_in, const int* in_sizes, int n_in,
                              void* d_out, int out_size) {
    const float* x   = (const float*)d_in[0];
    const int*   ei  = (const int*)d_in[1];   // int32 (JAX default-config downcast)
    const float* W1  = (const float*)d_in[2];
    const float* as1 = (const float*)d_in[3];
    const float* ad1 = (const float*)d_in[4];
    const float* b1  = (const float*)d_in[5];
    const float* W2  = (const float*)d_in[6];
    const float* as2 = (const float*)d_in[7];
    const float* ad2 = (const float*)d_in[8];
    const float* b2  = (const float*)d_in[9];
    float*       out = (float*)d_out;

    int N  = in_sizes[0] / DIM1;   // 100000
    int E  = in_sizes[1] / 2;      // 1600000
    int NLO = ((N / 2 + 127) / 128) * 128;   // 50048: gemm2-tile-aligned split
    if (NLO > N) NLO = N;

    static cudaStream_t s2 = nullptr;
    static cudaEvent_t evFork = nullptr, evJoin = nullptr, evA = nullptr, evB = nullptr;
    if (!s2) {
        cudaStreamCreateWithFlags(&s2, cudaStreamNonBlocking);
        cudaEventCreateWithFlags(&evFork, cudaEventDisableTiming);
        cudaEventCreateWithFlags(&evJoin, cudaEventDisableTiming);
        cudaEventCreateWithFlags(&evA, cudaEventDisableTiming);
        cudaEventCreateWithFlags(&evB, cudaEventDisableTiming);
    }

    // fork: CSR build on s2, gemm1 on main (independent)
    cudaEventRecord(evFork, 0);
    cudaStreamWaitEvent(s2, evFork, 0);

    hist_kernel   <<<(E + 255) / 256, 256, 0, s2>>>(ei, E);
    scan_kernel   <<<1, 1024, 0, s2>>>(N);
    scatter_kernel<<<(E + 255) / 256, 256, 0, s2>>>(ei, E);
    cudaEventRecord(evJoin, s2);
    // zero cnt for next replay — off the critical path
    zero_cnt_kernel<<<(N + 255) / 256, 256, 0, s2>>>(N);

    gemm1_kernel<<<(N + 127) / 128, 256>>>(x, W1, as1, ad1, N);
    cudaStreamWaitEvent(0, evJoin, 0);      // agg1 needs gemm1 + CSR

    // pipeline: agg1_lo -> (gemm2_lo on s2 || agg1_hi on main) -> gemm2_hi
    agg1_kernel<<<(NLO + 7) / 8, 256>>>(b1, 0, NLO);
    cudaEventRecord(evA, 0);
    cudaStreamWaitEvent(s2, evA, 0);
    gemm2_kernel<<<NLO / 128, 256, 0, s2>>>(W2, as2, ad2, 0, N);
    cudaEventRecord(evB, s2);

    agg1_kernel<<<(N - NLO + 7) / 8, 256>>>(b1, NLO, N);
    gemm2_kernel<<<(N - NLO + 127) / 128, 256>>>(W2, as2, ad2, NLO, N);
    cudaStreamWaitEvent(0, evB, 0);         // agg2 needs both gemm2 halves

    agg2_kernel<<<(N + 7) / 8, 256>>>(b2, out, N);
}

// round 16
// speedup vs baseline: 2.5580x; 1.0320x over previous
#include <cuda_runtime.h>
#include <cuda_fp16.h>
#include <cstdint>

#define NN    100000
#define EMAX  1700000
#define DIM1  128
#define H1    4
#define F2    40

// ---------------- scratch (device globals: allocation-free) ----------------
__device__ __half g_xw1h[(size_t)NN * DIM1]; // layer1 x@W1 (fp16)  [N,128]
__device__ __half g_hh [(size_t)NN * DIM1];  // layer1 activated (fp16) [N,128]
__device__ float g_asrc1[NN * H1];
__device__ float g_adst1[NN * H1];
__device__ __half g_xw2h[(size_t)NN * F2];   // layer2 h@W2 (fp16)  [N,40]
__device__ float g_asrc2[NN];
__device__ float g_adst2[NN];
__device__ int   g_cnt [NN];                 // per-dst degree (zeroed at graph tail)
__device__ int   g_off [NN + 1];             // CSR offsets
__device__ int   g_rank[EMAX];               // within-bucket rank per edge
__device__ int   g_srt [EMAX];               // src indices sorted by dst

__device__ __forceinline__ float leaky(float v) { return v > 0.f ? v : 0.2f * v; }

__device__ __forceinline__ uint32_t f2tf32(float f) {
    uint32_t r;
    asm("cvt.rna.tf32.f32 %0, %1;" : "=r"(r) : "f"(f));
    return r;
}
__device__ __forceinline__ void mma_tf32(float* d, uint32_t a0, uint32_t a1,
                                         uint32_t a2, uint32_t a3,
                                         uint32_t b0, uint32_t b1) {
    asm volatile(
        "mma.sync.aligned.m16n8k8.row.col.f32.tf32.tf32.f32 "
        "{%0,%1,%2,%3}, {%4,%5,%6,%7}, {%8,%9}, {%0,%1,%2,%3};"
        : "+f"(d[0]), "+f"(d[1]), "+f"(d[2]), "+f"(d[3])
        : "r"(a0), "r"(a1), "r"(a2), "r"(a3), "r"(b0), "r"(b1));
}

// ---------------- CSR build ---------------------------------------------------
__global__ void hist_kernel(const int* __restrict__ ei, int E) {
    int e = blockIdx.x * blockDim.x + threadIdx.x;
    if (e < E) g_rank[e] = atomicAdd(&g_cnt[__ldg(ei + E + e)], 1);
}

// single-block exclusive scan over g_cnt -> g_off
__global__ void scan_kernel(int NC) {
    __shared__ int wsum[32];
    int tid = threadIdx.x, lane = tid & 31, wid = tid >> 5;
    int carry = 0;
    for (int base = 0; base < NC; base += 1024) {
        int i = base + tid;
        int v = (i < NC) ? g_cnt[i] : 0;
        int s = v;
#pragma unroll
        for (int o = 1; o < 32; o <<= 1) {
            int t = __shfl_up_sync(0xffffffffu, s, o);
            if (lane >= o) s += t;
        }
        if (lane == 31) wsum[wid] = s;
        __syncthreads();
        if (wid == 0) {
            int ws = wsum[lane];
#pragma unroll
            for (int o = 1; o < 32; o <<= 1) {
                int t = __shfl_up_sync(0xffffffffu, ws, o);
                if (lane >= o) ws += t;
            }
            wsum[lane] = ws;
        }
        __syncthreads();
        int wexcl = (wid > 0) ? wsum[wid - 1] : 0;
        if (i < NC) g_off[i] = carry + wexcl + s - v;
        int total = wsum[31];
        __syncthreads();
        carry += total;
    }
    if (tid == 0) g_off[NC] = carry;
}

// atomic-free scatter: position = off[dst] + rank[e]
__global__ void scatter_kernel(const int* __restrict__ ei, int E) {
    int e = blockIdx.x * blockDim.x + threadIdx.x;
    if (e < E) {
        int src = __ldg(ei + e), dst = __ldg(ei + E + e);
        g_srt[g_off[dst] + g_rank[e]] = src;
    }
}

// zero g_cnt for the NEXT graph replay (cnt dead after scan; static init
// covers first launch). Runs at graph tail on the MAIN stream.
__global__ void zero_cnt_kernel(int N) {
    int i = blockIdx.x * blockDim.x + threadIdx.x;
    if (i < N) g_cnt[i] = 0;
}

// ---------------- GEMM1 tensor cores (2-MMA TF32: A hi-only, B hi+lo) -------
__global__ __launch_bounds__(256) void gemm1_kernel(
    const float* __restrict__ x, const float* __restrict__ W,
    const float* __restrict__ att_s, const float* __restrict__ att_d, int N) {
    __shared__ uint32_t sAh[128][20];
    __shared__ uint32_t sBh[16][136], sBl[16][136];   // stride 136: banks 8*tig+g
    int rowBase = blockIdx.x * 128;
    int tid = threadIdx.x, warp = tid >> 5, lane = tid & 31;
    int g = lane >> 2, tig = lane & 3;
    int wrow = warp * 16;

    float acc[16][4];
#pragma unroll
    for (int j = 0; j < 16; ++j)
#pragma unroll
        for (int q = 0; q < 4; ++q) acc[j][q] = 0.f;

    for (int kc = 0; kc < 8; ++kc) {
        __syncthreads();
        for (int i = tid; i < 512; i += 256) {
            int r = i >> 2, q = i & 3;
            int row = rowBase + r;
            float4 v = (row < N)
                ? *((const float4*)(x + (size_t)row * 128 + kc * 16 + q * 4))
                : make_float4(0.f, 0.f, 0.f, 0.f);
            const float* vf = (const float*)&v;
#pragma unroll
            for (int t = 0; t < 4; ++t)
                sAh[r][q * 4 + t] = f2tf32(vf[t]);
        }
        for (int i = tid; i < 512; i += 256) {
            int k = i >> 5, q = i & 31;
            float4 v = *((const float4*)(W + (size_t)(kc * 16 + k) * 128 + q * 4));
            const float* vf = (const float*)&v;
#pragma unroll
            for (int t = 0; t < 4; ++t) {
                uint32_t h = f2tf32(vf[t]);
                sBh[k][q * 4 + t] = h;
                sBl[k][q * 4 + t] = f2tf32(vf[t] - __uint_as_float(h));
            }
        }
        __syncthreads();
#pragma unroll
        for (int ks = 0; ks < 2; ++ks) {
            int k0 = ks * 8;
            uint32_t ah0 = sAh[wrow + g][k0 + tig];
            uint32_t ah1 = sAh[wrow + g + 8][k0 + tig];
            uint32_t ah2 = sAh[wrow + g][k0 + tig + 4];
            uint32_t ah3 = sAh[wrow + g + 8][k0 + tig + 4];
#pragma unroll
            for (int j = 0; j < 16; ++j) {
                int n0 = j * 8;
                uint32_t bh0 = sBh[k0 + tig][n0 + g];
                uint32_t bh1 = sBh[k0 + tig + 4][n0 + g];
                uint32_t bl0 = sBl[k0 + tig][n0 + g];
                uint32_t bl1 = sBl[k0 + tig + 4][n0 + g];
                mma_tf32(acc[j], ah0, ah1, ah2, ah3, bh0, bh1);
                mma_tf32(acc[j], ah0, ah1, ah2, ah3, bl0, bl1);
            }
        }
    }
    int row0 = rowBase + wrow + g, row1 = row0 + 8;
    float ps0[4] = {0,0,0,0}, pd0[4] = {0,0,0,0};
    float ps1[4] = {0,0,0,0}, pd1[4] = {0,0,0,0};
#pragma unroll
    for (int j = 0; j < 16; ++j) {
        int col = j * 8 + tig * 2;
        int head = j >> 2;
        float a0 = att_s[col], a1 = att_s[col + 1];
        float d0 = att_d[col], d1 = att_d[col + 1];
        ps0[head] += acc[j][0] * a0 + acc[j][1] * a1;
        pd0[head] += acc[j][0] * d0 + acc[j][1] * d1;
        ps1[head] += acc[j][2] * a0 + acc[j][3] * a1;
        pd1[head] += acc[j][2] * d0 + acc[j][3] * d1;
        if (row0 < N)
            *(__half2*)(g_xw1h + (size_t)row0 * 128 + col) =
                __floats2half2_rn(acc[j][0], acc[j][1]);
        if (row1 < N)
            *(__half2*)(g_xw1h + (size_t)row1 * 128 + col) =
                __floats2half2_rn(acc[j][2], acc[j][3]);
    }
#pragma unroll
    for (int h = 0; h < 4; ++h) {
#pragma unroll
        for (int o = 1; o < 4; o <<= 1) {
            ps0[h] += __shfl_xor_sync(0xffffffffu, ps0[h], o);
            pd0[h] += __shfl_xor_sync(0xffffffffu, pd0[h], o);
            ps1[h] += __shfl_xor_sync(0xffffffffu, ps1[h], o);
            pd1[h] += __shfl_xor_sync(0xffffffffu, pd1[h], o);
        }
    }
    if (tig == 0) {
        if (row0 < N) {
            *(float4*)(g_asrc1 + row0 * 4) = make_float4(ps0[0], ps0[1], ps0[2], ps0[3]);
            *(float4*)(g_adst1 + row0 * 4) = make_float4(pd0[0], pd0[1], pd0[2], pd0[3]);
        }
        if (row1 < N) {
            *(float4*)(g_asrc1 + row1 * 4) = make_float4(ps1[0], ps1[1], ps1[2], ps1[3]);
            *(float4*)(g_adst1 + row1 * 4) = make_float4(pd1[0], pd1[1], pd1[2], pd1[3]);
        }
    }
}

// ---------------- layer1 CSR aggregate: warp per dst, fp16 gather, unroll-4 --
__global__ void agg1_kernel(const float* __restrict__ b1, int begin, int end) {
    int dst = begin + blockIdx.x * 8 + (threadIdx.x >> 5);
    int lane = threadIdx.x & 31;
    if (dst >= end) return;
    int head = lane >> 3;
    float adst = g_adst1[dst * 4 + head];
    float ex = __expf(leaky(g_asrc1[dst * 4 + head] + adst));   // self-loop
    uint2 ps = *(const uint2*)(g_xw1h + (size_t)dst * 128 + lane * 4);
    float2 s01 = __half22float2(*(__half2*)&ps.x);
    float2 s23 = __half22float2(*(__half2*)&ps.y);
    float4 accA = make_float4(s01.x * ex, s01.y * ex, s23.x * ex, s23.y * ex);
    float4 accB = make_float4(0.f, 0.f, 0.f, 0.f);
    float4 accC = make_float4(0.f, 0.f, 0.f, 0.f);
    float4 accD = make_float4(0.f, 0.f, 0.f, 0.f);
    float denA = ex, denB = 0.f, denC = 0.f, denD = 0.f;
    int start = g_off[dst], stop = g_off[dst + 1];
    int i = start;
    for (; i + 3 < stop; i += 4) {
        int s0 = g_srt[i],     s1 = g_srt[i + 1];
        int s2 = g_srt[i + 2], s3 = g_srt[i + 3];
        float e0 = __expf(leaky(g_asrc1[s0 * 4 + head] + adst));
        float e1 = __expf(leaky(g_asrc1[s1 * 4 + head] + adst));
        float e2 = __expf(leaky(g_asrc1[s2 * 4 + head] + adst));
        float e3 = __expf(leaky(g_asrc1[s3 * 4 + head] + adst));
        uint2 p0 = *(const uint2*)(g_xw1h + (size_t)s0 * 128 + lane * 4);
        uint2 p1 = *(const uint2*)(g_xw1h + (size_t)s1 * 128 + lane * 4);
        uint2 p2 = *(const uint2*)(g_xw1h + (size_t)s2 * 128 + lane * 4);
        uint2 p3 = *(const uint2*)(g_xw1h + (size_t)s3 * 128 + lane * 4);
        float2 a01 = __half22float2(*(__half2*)&p0.x), a23 = __half22float2(*(__half2*)&p0.y);
        float2 b01 = __half22float2(*(__half2*)&p1.x), b23 = __half22float2(*(__half2*)&p1.y);
        float2 c01 = __half22float2(*(__half2*)&p2.x), c23 = __half22float2(*(__half2*)&p2.y);
        float2 d01 = __half22float2(*(__half2*)&p3.x), d23 = __half22float2(*(__half2*)&p3.y);
        accA.x += a01.x * e0; accA.y += a01.y * e0; accA.z += a23.x * e0; accA.w += a23.y * e0;
        accB.x += b01.x * e1; accB.y += b01.y * e1; accB.z += b23.x * e1; accB.w += b23.y * e1;
        accC.x += c01.x * e2; accC.y += c01.y * e2; accC.z += c23.x * e2; accC.w += c23.y * e2;
        accD.x += d01.x * e3; accD.y += d01.y * e3; accD.z += d23.x * e3; accD.w += d23.y * e3;
        denA += e0; denB += e1; denC += e2; denD += e3;
    }
    for (; i < stop; ++i) {
        int s0 = g_srt[i];
        float e0 = __expf(leaky(g_asrc1[s0 * 4 + head] + adst));
        uint2 p0 = *(const uint2*)(g_xw1h + (size_t)s0 * 128 + lane * 4);
        float2 a01 = __half22float2(*(__half2*)&p0.x), a23 = __half22float2(*(__half2*)&p0.y);
        accA.x += a01.x * e0; accA.y += a01.y * e0; accA.z += a23.x * e0; accA.w += a23.y * e0;
        denA += e0;
    }
    accA.x += accB.x + accC.x + accD.x;
    accA.y += accB.y + accC.y + accD.y;
    accA.z += accB.z + accC.z + accD.z;
    accA.w += accB.w + accC.w + accD.w;
    float inv = 1.f / (denA + denB + denC + denD);
    float4 b = ((const float4*)b1)[lane];
    float ox = fmaxf(accA.x * inv + b.x, 0.f);
    float oy = fmaxf(accA.y * inv + b.y, 0.f);
    float oz = fmaxf(accA.z * inv + b.z, 0.f);
    float ow = fmaxf(accA.w * inv + b.w, 0.f);
    uint2 o;
    *(__half2*)&o.x = __floats2half2_rn(ox, oy);
    *(__half2*)&o.y = __floats2half2_rn(oz, ow);
    *(uint2*)(g_hh + (size_t)dst * 128 + lane * 4) = o;
}

// ---------------- GEMM2 tensor cores (2-MMA TF32, A from fp16 h) -------------
__global__ __launch_bounds__(256) void gemm2_kernel(
    const float* __restrict__ W2,
    const float* __restrict__ att_s, const float* __restrict__ att_d,
    int begin, int N) {
    __shared__ uint32_t sAh[128][20];
    __shared__ uint32_t sBh[16][40], sBl[16][40];   // stride 40: banks 8*tig+g
    int rowBase = begin + blockIdx.x * 128;
    int tid = threadIdx.x, warp = tid >> 5, lane = tid & 31;
    int g = lane >> 2, tig = lane & 3;
    int wrow = warp * 16;

    float acc[5][4];
#pragma unroll
    for (int j = 0; j < 5; ++j)
#pragma unroll
        for (int q = 0; q < 4; ++q) acc[j][q] = 0.f;

    for (int kc = 0; kc < 8; ++kc) {
        __syncthreads();
        // A tile from fp16 h: 128 rows x 16 halves; i handles 4 halves (8B)
        for (int i = tid; i < 512; i += 256) {
            int r = i >> 2, q = i & 3;
            int row = rowBase + r;
            float2 v01 = make_float2(0.f, 0.f), v23 = make_float2(0.f, 0.f);
            if (row < N) {
                uint2 p = *(const uint2*)(g_hh + (size_t)row * 128 + kc * 16 + q * 4);
                v01 = __half22float2(*(__half2*)&p.x);
                v23 = __half22float2(*(__half2*)&p.y);
            }
            sAh[r][q * 4 + 0] = f2tf32(v01.x);
            sAh[r][q * 4 + 1] = f2tf32(v01.y);
            sAh[r][q * 4 + 2] = f2tf32(v23.x);
            sAh[r][q * 4 + 3] = f2tf32(v23.y);
        }
        for (int i = tid; i < 160; i += 256) {
            int k = i / 10, q = i - (i / 10) * 10;
            float4 v = *((const float4*)(W2 + (size_t)(kc * 16 + k) * 40 + q * 4));
            const float* vf = (const float*)&v;
#pragma unroll
            for (int t = 0; t < 4; ++t) {
                uint32_t h = f2tf32(vf[t]);
                sBh[k][q * 4 + t] = h;
                sBl[k][q * 4 + t] = f2tf32(vf[t] - __uint_as_float(h));
            }
        }
        __syncthreads();
#pragma unroll
        for (int ks = 0; ks < 2; ++ks) {
            int k0 = ks * 8;
            uint32_t ah0 = sAh[wrow + g][k0 + tig];
            uint32_t ah1 = sAh[wrow + g + 8][k0 + tig];
            uint32_t ah2 = sAh[wrow + g][k0 + tig + 4];
            uint32_t ah3 = sAh[wrow + g + 8][k0 + tig + 4];
#pragma unroll
            for (int j = 0; j < 5; ++j) {
                int n0 = j * 8;
                uint32_t bh0 = sBh[k0 + tig][n0 + g];
                uint32_t bh1 = sBh[k0 + tig + 4][n0 + g];
                uint32_t bl0 = sBl[k0 + tig][n0 + g];
                uint32_t bl1 = sBl[k0 + tig + 4][n0 + g];
                mma_tf32(acc[j], ah0, ah1, ah2, ah3, bh0, bh1);
                mma_tf32(acc[j], ah0, ah1, ah2, ah3, bl0, bl1);
            }
        }
    }
    int row0 = rowBase + wrow + g, row1 = row0 + 8;
    float ps0 = 0.f, pd0 = 0.f, ps1 = 0.f, pd1 = 0.f;
#pragma unroll
    for (int j = 0; j < 5; ++j) {
        int col = j * 8 + tig * 2;
        float a0 = att_s[col], a1 = att_s[col + 1];
        float d0 = att_d[col], d1 = att_d[col + 1];
        ps0 += acc[j][0] * a0 + acc[j][1] * a1;
        pd0 += acc[j][0] * d0 + acc[j][1] * d1;
        ps1 += acc[j][2] * a0 + acc[j][3] * a1;
        pd1 += acc[j][2] * d0 + acc[j][3] * d1;
        if (row0 < N)
            *(__half2*)(g_xw2h + (size_t)row0 * F2 + col) =
                __floats2half2_rn(acc[j][0], acc[j][1]);
        if (row1 < N)
            *(__half2*)(g_xw2h + (size_t)row1 * F2 + col) =
                __floats2half2_rn(acc[j][2], acc[j][3]);
    }
#pragma unroll
    for (int o = 1; o < 4; o <<= 1) {
        ps0 += __shfl_xor_sync(0xffffffffu, ps0, o);
        pd0 += __shfl_xor_sync(0xffffffffu, pd0, o);
        ps1 += __shfl_xor_sync(0xffffffffu, ps1, o);
        pd1 += __shfl_xor_sync(0xffffffffu, pd1, o);
    }
    if (tig == 0) {
        if (row0 < N) { g_asrc2[row0] = ps0; g_adst2[row0] = pd0; }
        if (row1 < N) { g_asrc2[row1] = ps1; g_adst2[row1] = pd1; }
    }
}

// ---------------- layer2 CSR aggregate: warp per dst, fp16, 3 groups, unroll-2
__global__ void agg2_kernel(const float* __restrict__ b2,
                            float* __restrict__ out, int N) {
    int dst = blockIdx.x * 8 + (threadIdx.x >> 5);
    int lane = threadIdx.x & 31;
    if (dst >= N) return;
    int grp = lane / 10, gl = lane - grp * 10;   // grp 3 = lanes 30,31 idle
    float adst = g_adst2[dst];
    float4 accA = make_float4(0.f, 0.f, 0.f, 0.f);
    float4 accB = make_float4(0.f, 0.f, 0.f, 0.f);
    float denA = 0.f, denB = 0.f;
    if (grp == 0) {      // self-loop in group 0
        float ex = __expf(leaky(g_asrc2[dst] + adst));
        uint2 p = *(const uint2*)(g_xw2h + (size_t)dst * F2 + gl * 4);
        float2 v01 = __half22float2(*(__half2*)&p.x);
        float2 v23 = __half22float2(*(__half2*)&p.y);
        accA.x = v01.x * ex; accA.y = v01.y * ex; accA.z = v23.x * ex; accA.w = v23.y * ex;
        denA = ex;
    }
    int start = g_off[dst], end = g_off[dst + 1];
    if (grp < 3) {
        int i = start + grp;
        for (; i + 3 < end; i += 6) {        // two edges per iter, stride 3 each
            int s0 = g_srt[i], s1 = g_srt[i + 3];
            float e0 = __expf(leaky(g_asrc2[s0] + adst));
            float e1 = __expf(leaky(g_asrc2[s1] + adst));
            uint2 p0 = *(const uint2*)(g_xw2h + (size_t)s0 * F2 + gl * 4);
            uint2 p1 = *(const uint2*)(g_xw2h + (size_t)s1 * F2 + gl * 4);
            float2 a01 = __half22float2(*(__half2*)&p0.x), a23 = __half22float2(*(__half2*)&p0.y);
            float2 b01 = __half22float2(*(__half2*)&p1.x), b23 = __half22float2(*(__half2*)&p1.y);
            accA.x += a01.x * e0; accA.y += a01.y * e0; accA.z += a23.x * e0; accA.w += a23.y * e0;
            accB.x += b01.x * e1; accB.y += b01.y * e1; accB.z += b23.x * e1; accB.w += b23.y * e1;
            denA += e0; denB += e1;
        }
        if (i < end) {
            int s0 = g_srt[i];
            float e0 = __expf(leaky(g_asrc2[s0] + adst));
            uint2 p0 = *(const uint2*)(g_xw2h + (size_t)s0 * F2 + gl * 4);
            float2 a01 = __half22float2(*(__half2*)&p0.x), a23 = __half22float2(*(__half2*)&p0.y);
            accA.x += a01.x * e0; accA.y += a01.y * e0; accA.z += a23.x * e0; accA.w += a23.y * e0;
            denA += e0;
        }
    }
    accA.x += accB.x; accA.y += accB.y; accA.z += accB.z; accA.w += accB.w;
    float den = denA + denB;
    float4 a1, a2;
    a1.x = __shfl_sync(0xffffffffu, accA.x, lane + 10);
    a1.y = __shfl_sync(0xffffffffu, accA.y, lane + 10);
    a1.z = __shfl_sync(0xffffffffu, accA.z, lane + 10);
    a1.w = __shfl_sync(0xffffffffu, accA.w, lane + 10);
    a2.x = __shfl_sync(0xffffffffu, accA.x, lane + 20);
    a2.y = __shfl_sync(0xffffffffu, accA.y, lane + 20);
    a2.z = __shfl_sync(0xffffffffu, accA.z, lane + 20);
    a2.w = __shfl_sync(0xffffffffu, accA.w, lane + 20);
    float d1 = __shfl_sync(0xffffffffu, den, lane + 10);
    float d2 = __shfl_sync(0xffffffffu, den, lane + 20);
    if (grp == 0) {
        accA.x += a1.x + a2.x; accA.y += a1.y + a2.y;
        accA.z += a1.z + a2.z; accA.w += a1.w + a2.w;
        float inv = 1.f / (den + d1 + d2);
        float4 b = ((const float4*)b2)[gl];
        float4 o;
        o.x = accA.x * inv + b.x;
        o.y = accA.y * inv + b.y;
        o.z = accA.z * inv + b.z;
        o.w = accA.w * inv + b.w;
        ((float4*)(out + (size_t)dst * F2))[gl] = o;
    }
}

// ============================================================================
extern "C" void kernel_launch(void* const* d_in, const int* in_sizes, int n_in,
                              void* d_out, int out_size) {
    const float* x   = (const float*)d_in[0];
    const int*   ei  = (const int*)d_in[1];   // int32 (JAX default-config downcast)
    const float* W1  = (const float*)d_in[2];
    const float* as1 = (const float*)d_in[3];
    const float* ad1 = (const float*)d_in[4];
    const float* b1  = (const float*)d_in[5];
    const float* W2  = (const float*)d_in[6];
    const float* as2 = (const float*)d_in[7];
    const float* ad2 = (const float*)d_in[8];
    const float* b2  = (const float*)d_in[9];
    float*       out = (float*)d_out;

    int N  = in_sizes[0] / DIM1;   // 100000
    int E  = in_sizes[1] / 2;      // 1600000
    int NLO = ((N / 2 + 127) / 128) * 128;   // gemm2-tile-aligned split
    if (NLO > N) NLO = N;

    static cudaStream_t s2 = nullptr;
    static cudaEvent_t evFork = nullptr, evJoin = nullptr, evA = nullptr, evB = nullptr;
    if (!s2) {
        cudaStreamCreateWithFlags(&s2, cudaStreamNonBlocking);
        cudaEventCreateWithFlags(&evFork, cudaEventDisableTiming);
        cudaEventCreateWithFlags(&evJoin, cudaEventDisableTiming);
        cudaEventCreateWithFlags(&evA, cudaEventDisableTiming);
        cudaEventCreateWithFlags(&evB, cudaEventDisableTiming);
    }

    // fork: CSR build on s2, gemm1 on main (independent)
    cudaEventRecord(evFork, 0);
    cudaStreamWaitEvent(s2, evFork, 0);

    hist_kernel   <<<(E + 255) / 256, 256, 0, s2>>>(ei, E);   // launch 1
    scan_kernel   <<<1, 1024, 0, s2>>>(N);                    // launch 2
    scatter_kernel<<<(E + 255) / 256, 256, 0, s2>>>(ei, E);   // launch 3
    cudaEventRecord(evJoin, s2);

    gemm1_kernel<<<(N + 127) / 128, 256>>>(x, W1, as1, ad1, N);  // launch 4 (profiled)
    cudaStreamWaitEvent(0, evJoin, 0);      // agg1 needs gemm1 + CSR

    // pipeline: agg1_lo -> (gemm2_lo on s2 || agg1_hi on main) -> gemm2_hi
    agg1_kernel<<<(NLO + 7) / 8, 256>>>(b1, 0, NLO);
    cudaEventRecord(evA, 0);
    cudaStreamWaitEvent(s2, evA, 0);
    gemm2_kernel<<<NLO / 128, 256, 0, s2>>>(W2, as2, ad2, 0, N);
    cudaEventRecord(evB, s2);

    agg1_kernel<<<(N - NLO + 7) / 8, 256>>>(b1, NLO, N);
    gemm2_kernel<<<(N - NLO + 127) / 128, 256>>>(W2, as2, ad2, NLO, N);
    cudaStreamWaitEvent(0, evB, 0);         // agg2 needs both gemm2 halves (s2 rejoined)

    agg2_kernel<<<(N + 7) / 8, 256>>>(b2, out, N);

    // housekeeping for next replay — MAIN stream tail (keeps s2 fully joined)
    zero_cnt_kernel<<<(N + 255) / 256, 256>>>(N);
}

// round 17
// speedup vs baseline: 2.9246x; 1.1433x over previous
#include <cuda_runtime.h>
#include <cuda_fp16.h>
#include <cstdint>

#define NN    100000
#define EMAX  1700000
#define DIM1  128
#define H1    4
#define F2    40

// ---------------- scratch (device globals: allocation-free) ----------------
__device__ __half g_xw1h[(size_t)NN * DIM1]; // layer1 x@W1 (fp16)  [N,128]
__device__ __half g_hh [(size_t)NN * DIM1];  // layer1 activated (fp16) [N,128]
__device__ float g_asrc1[NN * H1];
__device__ float g_adst1[NN * H1];
__device__ __half g_xw2h[(size_t)NN * F2];   // layer2 h@W2 (fp16)  [N,40]
__device__ float g_asrc2[NN];
__device__ float g_adst2[NN];
__device__ __half g_W1t[128 * 128];          // W1^T fp16 [n][k]
__device__ __half g_W2t[40 * 128];           // W2^T fp16 [n][k]
__device__ int   g_cnt [NN];                 // per-dst degree (zeroed at graph tail)
__device__ int   g_off [NN + 1];             // CSR offsets
__device__ int   g_rank[EMAX];               // within-bucket rank per edge
__device__ int   g_srt [EMAX];               // src indices sorted by dst

__device__ __forceinline__ float leaky(float v) { return v > 0.f ? v : 0.2f * v; }

// fp16 m16n8k16 MMA, fp32 accumulate
__device__ __forceinline__ void mma_f16(float* d, uint32_t a0, uint32_t a1,
                                        uint32_t a2, uint32_t a3,
                                        uint32_t b0, uint32_t b1) {
    asm volatile(
        "mma.sync.aligned.m16n8k16.row.col.f32.f16.f16.f32 "
        "{%0,%1,%2,%3}, {%4,%5,%6,%7}, {%8,%9}, {%0,%1,%2,%3};"
        : "+f"(d[0]), "+f"(d[1]), "+f"(d[2]), "+f"(d[3])
        : "r"(a0), "r"(a1), "r"(a2), "r"(a3), "r"(b0), "r"(b1));
}

// ---------------- prep: W1,W2 -> transposed fp16 ----------------------------
__global__ void prep_kernel(const float* __restrict__ W1, const float* __restrict__ W2) {
    int i = blockIdx.x * blockDim.x + threadIdx.x;
    if (i < 16384) {                       // W1[k][n], k=i>>7, n=i&127
        int k = i >> 7, n = i & 127;
        g_W1t[n * 128 + k] = __float2half_rn(W1[i]);
    } else if (i < 16384 + 40 * 128) {     // W2[k][n], t=k*40+n
        int t = i - 16384;
        int k = t / 40, n = t - k * 40;
        g_W2t[n * 128 + k] = __float2half_rn(W2[t]);
    }
}

// ---------------- CSR build ---------------------------------------------------
__global__ void hist_kernel(const int* __restrict__ ei, int E) {
    int e = blockIdx.x * blockDim.x + threadIdx.x;
    if (e < E) g_rank[e] = atomicAdd(&g_cnt[__ldg(ei + E + e)], 1);
}

__global__ void scan_kernel(int NC) {
    __shared__ int wsum[32];
    int tid = threadIdx.x, lane = tid & 31, wid = tid >> 5;
    int carry = 0;
    for (int base = 0; base < NC; base += 1024) {
        int i = base + tid;
        int v = (i < NC) ? g_cnt[i] : 0;
        int s = v;
#pragma unroll
        for (int o = 1; o < 32; o <<= 1) {
            int t = __shfl_up_sync(0xffffffffu, s, o);
            if (lane >= o) s += t;
        }
        if (lane == 31) wsum[wid] = s;
        __syncthreads();
        if (wid == 0) {
            int ws = wsum[lane];
#pragma unroll
            for (int o = 1; o < 32; o <<= 1) {
                int t = __shfl_up_sync(0xffffffffu, ws, o);
                if (lane >= o) ws += t;
            }
            wsum[lane] = ws;
        }
        __syncthreads();
        int wexcl = (wid > 0) ? wsum[wid - 1] : 0;
        if (i < NC) g_off[i] = carry + wexcl + s - v;
        int total = wsum[31];
        __syncthreads();
        carry += total;
    }
    if (tid == 0) g_off[NC] = carry;
}

__global__ void scatter_kernel(const int* __restrict__ ei, int E) {
    int e = blockIdx.x * blockDim.x + threadIdx.x;
    if (e < E) {
        int src = __ldg(ei + e), dst = __ldg(ei + E + e);
        g_srt[g_off[dst] + g_rank[e]] = src;
    }
}

__global__ void zero_cnt_kernel(int N) {
    int i = blockIdx.x * blockDim.x + threadIdx.x;
    if (i < N) g_cnt[i] = 0;
}

// ---------------- GEMM1 fp16 m16n8k16 + fused attention dots -----------------
// Block 128 rows x 128 cols, 8 warps x 16 rows. smem strides 24 halves:
// fragment load bank = (12g + tig) mod 32 — conflict-free.
__global__ __launch_bounds__(256) void gemm1_kernel(
    const float* __restrict__ x,
    const float* __restrict__ att_s, const float* __restrict__ att_d, int N) {
    __shared__ __half sA[128][24];   // 6KB
    __shared__ __half sB[128][24];   // 6KB  ([n][k])
    int rowBase = blockIdx.x * 128;
    int tid = threadIdx.x, warp = tid >> 5, lane = tid & 31;
    int g = lane >> 2, tig = lane & 3;
    int wrow = warp * 16;

    float acc[16][4];
#pragma unroll
    for (int j = 0; j < 16; ++j)
#pragma unroll
        for (int q = 0; q < 4; ++q) acc[j][q] = 0.f;

    for (int kc = 0; kc < 8; ++kc) {
        __syncthreads();
        // A: x fp32 -> fp16, 128 rows x 16 k (512 float4 loads)
        for (int i = tid; i < 512; i += 256) {
            int r = i >> 2, q = i & 3;
            int row = rowBase + r;
            float4 v = (row < N)
                ? *((const float4*)(x + (size_t)row * 128 + kc * 16 + q * 4))
                : make_float4(0.f, 0.f, 0.f, 0.f);
            __half2 h01 = __floats2half2_rn(v.x, v.y);
            __half2 h23 = __floats2half2_rn(v.z, v.w);
            uint2 pk;
            pk.x = *(uint32_t*)&h01;
            pk.y = *(uint32_t*)&h23;
            *(uint2*)&sA[r][q * 4] = pk;          // 8B aligned (r*48 + q*8)
        }
        // B: copy pre-transposed fp16 W1t rows (128 n x 16 k = 256 uint4)
        {
            int i = tid;                           // exactly 256 work items
            int n = i >> 1, part = i & 1;
            uint4 v = *(const uint4*)(g_W1t + n * 128 + kc * 16 + part * 8);
            *(uint4*)&sB[n][part * 8] = v;        // 16B aligned (n*48 + part*16)
        }
        __syncthreads();
        uint32_t a0 = *(const uint32_t*)&sA[wrow + g][2 * tig];
        uint32_t a1 = *(const uint32_t*)&sA[wrow + g + 8][2 * tig];
        uint32_t a2 = *(const uint32_t*)&sA[wrow + g][2 * tig + 8];
        uint32_t a3 = *(const uint32_t*)&sA[wrow + g + 8][2 * tig + 8];
#pragma unroll
        for (int j = 0; j < 16; ++j) {
            uint32_t b0 = *(const uint32_t*)&sB[j * 8 + g][2 * tig];
            uint32_t b1 = *(const uint32_t*)&sB[j * 8 + g][2 * tig + 8];
            mma_f16(acc[j], a0, a1, a2, a3, b0, b1);
        }
    }
    int row0 = rowBase + wrow + g, row1 = row0 + 8;
    float ps0[4] = {0,0,0,0}, pd0[4] = {0,0,0,0};
    float ps1[4] = {0,0,0,0}, pd1[4] = {0,0,0,0};
#pragma unroll
    for (int j = 0; j < 16; ++j) {
        int col = j * 8 + tig * 2;
        int head = j >> 2;
        float a0 = att_s[col], a1 = att_s[col + 1];
        float d0 = att_d[col], d1 = att_d[col + 1];
        ps0[head] += acc[j][0] * a0 + acc[j][1] * a1;
        pd0[head] += acc[j][0] * d0 + acc[j][1] * d1;
        ps1[head] += acc[j][2] * a0 + acc[j][3] * a1;
        pd1[head] += acc[j][2] * d0 + acc[j][3] * d1;
        if (row0 < N)
            *(__half2*)(g_xw1h + (size_t)row0 * 128 + col) =
                __floats2half2_rn(acc[j][0], acc[j][1]);
        if (row1 < N)
            *(__half2*)(g_xw1h + (size_t)row1 * 128 + col) =
                __floats2half2_rn(acc[j][2], acc[j][3]);
    }
#pragma unroll
    for (int h = 0; h < 4; ++h) {
#pragma unroll
        for (int o = 1; o < 4; o <<= 1) {
            ps0[h] += __shfl_xor_sync(0xffffffffu, ps0[h], o);
            pd0[h] += __shfl_xor_sync(0xffffffffu, pd0[h], o);
            ps1[h] += __shfl_xor_sync(0xffffffffu, ps1[h], o);
            pd1[h] += __shfl_xor_sync(0xffffffffu, pd1[h], o);
        }
    }
    if (tig == 0) {
        if (row0 < N) {
            *(float4*)(g_asrc1 + row0 * 4) = make_float4(ps0[0], ps0[1], ps0[2], ps0[3]);
            *(float4*)(g_adst1 + row0 * 4) = make_float4(pd0[0], pd0[1], pd0[2], pd0[3]);
        }
        if (row1 < N) {
            *(float4*)(g_asrc1 + row1 * 4) = make_float4(ps1[0], ps1[1], ps1[2], ps1[3]);
            *(float4*)(g_adst1 + row1 * 4) = make_float4(pd1[0], pd1[1], pd1[2], pd1[3]);
        }
    }
}

// ---------------- layer1 CSR aggregate: warp per dst, fp16 gather, unroll-4 --
__global__ void agg1_kernel(const float* __restrict__ b1, int begin, int end) {
    int dst = begin + blockIdx.x * 8 + (threadIdx.x >> 5);
    int lane = threadIdx.x & 31;
    if (dst >= end) return;
    int head = lane >> 3;
    float adst = g_adst1[dst * 4 + head];
    float ex = __expf(leaky(g_asrc1[dst * 4 + head] + adst));   // self-loop
    uint2 ps = *(const uint2*)(g_xw1h + (size_t)dst * 128 + lane * 4);
    float2 s01 = __half22float2(*(__half2*)&ps.x);
    float2 s23 = __half22float2(*(__half2*)&ps.y);
    float4 accA = make_float4(s01.x * ex, s01.y * ex, s23.x * ex, s23.y * ex);
    float4 accB = make_float4(0.f, 0.f, 0.f, 0.f);
    float4 accC = make_float4(0.f, 0.f, 0.f, 0.f);
    float4 accD = make_float4(0.f, 0.f, 0.f, 0.f);
    float denA = ex, denB = 0.f, denC = 0.f, denD = 0.f;
    int start = g_off[dst], stop = g_off[dst + 1];
    int i = start;
    for (; i + 3 < stop; i += 4) {
        int s0 = g_srt[i],     s1 = g_srt[i + 1];
        int s2 = g_srt[i + 2], s3 = g_srt[i + 3];
        float e0 = __expf(leaky(g_asrc1[s0 * 4 + head] + adst));
        float e1 = __expf(leaky(g_asrc1[s1 * 4 + head] + adst));
        float e2 = __expf(leaky(g_asrc1[s2 * 4 + head] + adst));
        float e3 = __expf(leaky(g_asrc1[s3 * 4 + head] + adst));
        uint2 p0 = *(const uint2*)(g_xw1h + (size_t)s0 * 128 + lane * 4);
        uint2 p1 = *(const uint2*)(g_xw1h + (size_t)s1 * 128 + lane * 4);
        uint2 p2 = *(const uint2*)(g_xw1h + (size_t)s2 * 128 + lane * 4);
        uint2 p3 = *(const uint2*)(g_xw1h + (size_t)s3 * 128 + lane * 4);
        float2 a01 = __half22float2(*(__half2*)&p0.x), a23 = __half22float2(*(__half2*)&p0.y);
        float2 b01 = __half22float2(*(__half2*)&p1.x), b23 = __half22float2(*(__half2*)&p1.y);
        float2 c01 = __half22float2(*(__half2*)&p2.x), c23 = __half22float2(*(__half2*)&p2.y);
        float2 d01 = __half22float2(*(__half2*)&p3.x), d23 = __half22float2(*(__half2*)&p3.y);
        accA.x += a01.x * e0; accA.y += a01.y * e0; accA.z += a23.x * e0; accA.w += a23.y * e0;
        accB.x += b01.x * e1; accB.y += b01.y * e1; accB.z += b23.x * e1; accB.w += b23.y * e1;
        accC.x += c01.x * e2; accC.y += c01.y * e2; accC.z += c23.x * e2; accC.w += c23.y * e2;
        accD.x += d01.x * e3; accD.y += d01.y * e3; accD.z += d23.x * e3; accD.w += d23.y * e3;
        denA += e0; denB += e1; denC += e2; denD += e3;
    }
    for (; i < stop; ++i) {
        int s0 = g_srt[i];
        float e0 = __expf(leaky(g_asrc1[s0 * 4 + head] + adst));
        uint2 p0 = *(const uint2*)(g_xw1h + (size_t)s0 * 128 + lane * 4);
        float2 a01 = __half22float2(*(__half2*)&p0.x), a23 = __half22float2(*(__half2*)&p0.y);
        accA.x += a01.x * e0; accA.y += a01.y * e0; accA.z += a23.x * e0; accA.w += a23.y * e0;
        denA += e0;
    }
    accA.x += accB.x + accC.x + accD.x;
    accA.y += accB.y + accC.y + accD.y;
    accA.z += accB.z + accC.z + accD.z;
    accA.w += accB.w + accC.w + accD.w;
    float inv = 1.f / (denA + denB + denC + denD);
    float4 b = ((const float4*)b1)[lane];
    float ox = fmaxf(accA.x * inv + b.x, 0.f);
    float oy = fmaxf(accA.y * inv + b.y, 0.f);
    float oz = fmaxf(accA.z * inv + b.z, 0.f);
    float ow = fmaxf(accA.w * inv + b.w, 0.f);
    uint2 o;
    *(__half2*)&o.x = __floats2half2_rn(ox, oy);
    *(__half2*)&o.y = __floats2half2_rn(oz, ow);
    *(uint2*)(g_hh + (size_t)dst * 128 + lane * 4) = o;
}

// ---------------- GEMM2 fp16 m16n8k16 (A from fp16 h) + att2 dots ------------
__global__ __launch_bounds__(256) void gemm2_kernel(
    const float* __restrict__ att_s, const float* __restrict__ att_d,
    int begin, int N) {
    __shared__ __half sA[128][24];   // 6KB
    __shared__ __half sB[40][24];    // ~1.9KB  ([n][k])
    int rowBase = begin + blockIdx.x * 128;
    int tid = threadIdx.x, warp = tid >> 5, lane = tid & 31;
    int g = lane >> 2, tig = lane & 3;
    int wrow = warp * 16;

    float acc[5][4];
#pragma unroll
    for (int j = 0; j < 5; ++j)
#pragma unroll
        for (int q = 0; q < 4; ++q) acc[j][q] = 0.f;

    for (int kc = 0; kc < 8; ++kc) {
        __syncthreads();
        // A: copy fp16 h rows (128 rows x 16 k = 256 uint4)
        {
            int i = tid;
            int r = i >> 1, part = i & 1;
            int row = rowBase + r;
            uint4 v = make_uint4(0u, 0u, 0u, 0u);
            if (row < N)
                v = *(const uint4*)(g_hh + (size_t)row * 128 + kc * 16 + part * 8);
            *(uint4*)&sA[r][part * 8] = v;
        }
        // B: copy W2t rows (40 n x 16 k = 80 uint4)
        for (int i = tid; i < 80; i += 256) {
            int n = i >> 1, part = i & 1;
            uint4 v = *(const uint4*)(g_W2t + n * 128 + kc * 16 + part * 8);
            *(uint4*)&sB[n][part * 8] = v;
        }
        __syncthreads();
        uint32_t a0 = *(const uint32_t*)&sA[wrow + g][2 * tig];
        uint32_t a1 = *(const uint32_t*)&sA[wrow + g + 8][2 * tig];
        uint32_t a2 = *(const uint32_t*)&sA[wrow + g][2 * tig + 8];
        uint32_t a3 = *(const uint32_t*)&sA[wrow + g + 8][2 * tig + 8];
#pragma unroll
        for (int j = 0; j < 5; ++j) {
            uint32_t b0 = *(const uint32_t*)&sB[j * 8 + g][2 * tig];
            uint32_t b1 = *(const uint32_t*)&sB[j * 8 + g][2 * tig + 8];
            mma_f16(acc[j], a0, a1, a2, a3, b0, b1);
        }
    }
    int row0 = rowBase + wrow + g, row1 = row0 + 8;
    float ps0 = 0.f, pd0 = 0.f, ps1 = 0.f, pd1 = 0.f;
#pragma unroll
    for (int j = 0; j < 5; ++j) {
        int col = j * 8 + tig * 2;
        float a0 = att_s[col], a1 = att_s[col + 1];
        float d0 = att_d[col], d1 = att_d[col + 1];
        ps0 += acc[j][0] * a0 + acc[j][1] * a1;
        pd0 += acc[j][0] * d0 + acc[j][1] * d1;
        ps1 += acc[j][2] * a0 + acc[j][3] * a1;
        pd1 += acc[j][2] * d0 + acc[j][3] * d1;
        if (row0 < N)
            *(__half2*)(g_xw2h + (size_t)row0 * F2 + col) =
                __floats2half2_rn(acc[j][0], acc[j][1]);
        if (row1 < N)
            *(__half2*)(g_xw2h + (size_t)row1 * F2 + col) =
                __floats2half2_rn(acc[j][2], acc[j][3]);
    }
#pragma unroll
    for (int o = 1; o < 4; o <<= 1) {
        ps0 += __shfl_xor_sync(0xffffffffu, ps0, o);
        pd0 += __shfl_xor_sync(0xffffffffu, pd0, o);
        ps1 += __shfl_xor_sync(0xffffffffu, ps1, o);
        pd1 += __shfl_xor_sync(0xffffffffu, pd1, o);
    }
    if (tig == 0) {
        if (row0 < N) { g_asrc2[row0] = ps0; g_adst2[row0] = pd0; }
        if (row1 < N) { g_asrc2[row1] = ps1; g_adst2[row1] = pd1; }
    }
}

// ---------------- layer2 CSR aggregate: warp per dst, fp16, 3 groups, unroll-2
__global__ void agg2_kernel(const float* __restrict__ b2,
                            float* __restrict__ out, int N) {
    int dst = blockIdx.x * 8 + (threadIdx.x >> 5);
    int lane = threadIdx.x & 31;
    if (dst >= N) return;
    int grp = lane / 10, gl = lane - grp * 10;   // grp 3 = lanes 30,31 idle
    float adst = g_adst2[dst];
    float4 accA = make_float4(0.f, 0.f, 0.f, 0.f);
    float4 accB = make_float4(0.f, 0.f, 0.f, 0.f);
    float denA = 0.f, denB = 0.f;
    if (grp == 0) {      // self-loop in group 0
        float ex = __expf(leaky(g_asrc2[dst] + adst));
        uint2 p = *(const uint2*)(g_xw2h + (size_t)dst * F2 + gl * 4);
        float2 v01 = __half22float2(*(__half2*)&p.x);
        float2 v23 = __half22float2(*(__half2*)&p.y);
        accA.x = v01.x * ex; accA.y = v01.y * ex; accA.z = v23.x * ex; accA.w = v23.y * ex;
        denA = ex;
    }
    int start = g_off[dst], end = g_off[dst + 1];
    if (grp < 3) {
        int i = start + grp;
        for (; i + 3 < end; i += 6) {
            int s0 = g_srt[i], s1 = g_srt[i + 3];
            float e0 = __expf(leaky(g_asrc2[s0] + adst));
            float e1 = __expf(leaky(g_asrc2[s1] + adst));
            uint2 p0 = *(const uint2*)(g_xw2h + (size_t)s0 * F2 + gl * 4);
            uint2 p1 = *(const uint2*)(g_xw2h + (size_t)s1 * F2 + gl * 4);
            float2 a01 = __half22float2(*(__half2*)&p0.x), a23 = __half22float2(*(__half2*)&p0.y);
            float2 b01 = __half22float2(*(__half2*)&p1.x), b23 = __half22float2(*(__half2*)&p1.y);
            accA.x += a01.x * e0; accA.y += a01.y * e0; accA.z += a23.x * e0; accA.w += a23.y * e0;
            accB.x += b01.x * e1; accB.y += b01.y * e1; accB.z += b23.x * e1; accB.w += b23.y * e1;
            denA += e0; denB += e1;
        }
        if (i < end) {
            int s0 = g_srt[i];
            float e0 = __expf(leaky(g_asrc2[s0] + adst));
            uint2 p0 = *(const uint2*)(g_xw2h + (size_t)s0 * F2 + gl * 4);
            float2 a01 = __half22float2(*(__half2*)&p0.x), a23 = __half22float2(*(__half2*)&p0.y);
            accA.x += a01.x * e0; accA.y += a01.y * e0; accA.z += a23.x * e0; accA.w += a23.y * e0;
            denA += e0;
        }
    }
    accA.x += accB.x; accA.y += accB.y; accA.z += accB.z; accA.w += accB.w;
    float den = denA + denB;
    float4 a1, a2;
    a1.x = __shfl_sync(0xffffffffu, accA.x, lane + 10);
    a1.y = __shfl_sync(0xffffffffu, accA.y, lane + 10);
    a1.z = __shfl_sync(0xffffffffu, accA.z, lane + 10);
    a1.w = __shfl_sync(0xffffffffu, accA.w, lane + 10);
    a2.x = __shfl_sync(0xffffffffu, accA.x, lane + 20);
    a2.y = __shfl_sync(0xffffffffu, accA.y, lane + 20);
    a2.z = __shfl_sync(0xffffffffu, accA.z, lane + 20);
    a2.w = __shfl_sync(0xffffffffu, accA.w, lane + 20);
    float d1 = __shfl_sync(0xffffffffu, den, lane + 10);
    float d2 = __shfl_sync(0xffffffffu, den, lane + 20);
    if (grp == 0) {
        accA.x += a1.x + a2.x; accA.y += a1.y + a2.y;
        accA.z += a1.z + a2.z; accA.w += a1.w + a2.w;
        float inv = 1.f / (den + d1 + d2);
        float4 b = ((const float4*)b2)[gl];
        float4 o;
        o.x = accA.x * inv + b.x;
        o.y = accA.y * inv + b.y;
        o.z = accA.z * inv + b.z;
        o.w = accA.w * inv + b.w;
        ((float4*)(out + (size_t)dst * F2))[gl] = o;
    }
}

// ============================================================================
extern "C" void kernel_launch(void* const* d_in, const int* in_sizes, int n_in,
                              void* d_out, int out_size) {
    const float* x   = (const float*)d_in[0];
    const int*   ei  = (const int*)d_in[1];   // int32 (JAX default-config downcast)
    const float* W1  = (const float*)d_in[2];
    const float* as1 = (const float*)d_in[3];
    const float* ad1 = (const float*)d_in[4];
    const float* b1  = (const float*)d_in[5];
    const float* W2  = (const float*)d_in[6];
    const float* as2 = (const float*)d_in[7];
    const float* ad2 = (const float*)d_in[8];
    const float* b2  = (const float*)d_in[9];
    float*       out = (float*)d_out;

    int N  = in_sizes[0] / DIM1;   // 100000
    int E  = in_sizes[1] / 2;      // 1600000
    int NLO = ((N / 2 + 127) / 128) * 128;   // gemm2-tile-aligned split
    if (NLO > N) NLO = N;

    static cudaStream_t s2 = nullptr;
    static cudaEvent_t evFork = nullptr, evJoin = nullptr, evA = nullptr, evB = nullptr;
    if (!s2) {
        cudaStreamCreateWithFlags(&s2, cudaStreamNonBlocking);
        cudaEventCreateWithFlags(&evFork, cudaEventDisableTiming);
        cudaEventCreateWithFlags(&evJoin, cudaEventDisableTiming);
        cudaEventCreateWithFlags(&evA, cudaEventDisableTiming);
        cudaEventCreateWithFlags(&evB, cudaEventDisableTiming);
    }

    // fork: CSR build on s2, prep+gemm1 on main (independent)
    cudaEventRecord(evFork, 0);
    cudaStreamWaitEvent(s2, evFork, 0);

    hist_kernel   <<<(E + 255) / 256, 256, 0, s2>>>(ei, E);
    scan_kernel   <<<1, 1024, 0, s2>>>(N);
    scatter_kernel<<<(E + 255) / 256, 256, 0, s2>>>(ei, E);
    cudaEventRecord(evJoin, s2);

    prep_kernel <<<84, 256>>>(W1, W2);
    gemm1_kernel<<<(N + 127) / 128, 256>>>(x, as1, ad1, N);
    cudaStreamWaitEvent(0, evJoin, 0);      // agg1 needs gemm1 + CSR

    // pipeline: agg1_lo -> (gemm2_lo on s2 || agg1_hi on main) -> gemm2_hi
    agg1_kernel<<<(NLO + 7) / 8, 256>>>(b1, 0, NLO);
    cudaEventRecord(evA, 0);
    cudaStreamWaitEvent(s2, evA, 0);
    gemm2_kernel<<<NLO / 128, 256, 0, s2>>>(as2, ad2, 0, N);
    cudaEventRecord(evB, s2);

    agg1_kernel<<<(N - NLO + 7) / 8, 256>>>(b1, NLO, N);
    gemm2_kernel<<<(N - NLO + 127) / 128, 256>>>(as2, ad2, NLO, N);
    cudaStreamWaitEvent(0, evB, 0);         // agg2 needs both gemm2 halves (s2 rejoined)

    agg2_kernel<<<(N + 7) / 8, 256>>>(b2, out, N);

    // housekeeping for next replay — MAIN stream tail (keeps s2 fully joined)
    zero_cnt_kernel<<<(N + 255) / 256, 256>>>(N);
}